// round 9
// baseline (speedup 1.0000x reference)
#include <cuda_runtime.h>
#include <cuda_fp16.h>
#include <math.h>
#include <stdint.h>
#include <stddef.h>

#define DM 1024
#define NH 16
#define DEPTH 64
#define BATCH 2
#define SEQ 2048
#define BS_ROWS 4096
#define BH 32

// ---------------------------------------------------------------------------
// Scratch (__device__ globals; allocation-free rule). Zero-initialized.
// ---------------------------------------------------------------------------
__device__ __half g_Xhi[3][(size_t)BS_ROWS * DM];
__device__ __half g_Xlo[3][(size_t)BS_ROWS * DM];
__device__ __half g_QKVhi[3][(size_t)BS_ROWS * DM];
__device__ __half g_QKVlo[3][(size_t)BS_ROWS * DM];
__device__ __half g_Vthi[(size_t)BH * DEPTH * SEQ];   // [bh][d][compact s]
__device__ __half g_Vtlo[(size_t)BH * DEPTH * SEQ];
__device__ __half g_Cxhi[(size_t)BS_ROWS * DM];
__device__ __half g_Cxlo[(size_t)BS_ROWS * DM];
__device__ __half g_WThi[4][(size_t)DM * DM];
__device__ __half g_WTlo[4][(size_t)DM * DM];
__device__ __half g_Phi[(size_t)BH * SEQ * SEQ];      // exp(p) hi, compact cols
__device__ __half g_Plo[(size_t)BH * SEQ * SEQ];      // exp(p) lo residual
__device__ float  g_attn[(size_t)BH * SEQ * SEQ];     // fallback full attn
__device__ float  g_partial[(size_t)BH * SEQ * 16];
__device__ float  g_rowsum[(size_t)BH * SEQ];
__device__ int    g_fwd[BATCH * SEQ];                 // orig j -> compact slot or -1
__device__ int    g_cidx[BATCH * SEQ];                // compact slot -> orig j
__device__ int    g_cnt[BATCH];                       // unmasked count

// ---------------------------------------------------------------------------
// Helpers
// ---------------------------------------------------------------------------
__device__ __forceinline__ float residf(float x) {
    return x - __half2float(__float2half_rn(x));
}
__device__ __forceinline__ uint32_t smem_u32(const void* p) {
    return (uint32_t)__cvta_generic_to_shared(p);
}
// FMA/ALU-pipe exp (fp32, rel err ~1e-7): exp(x) = 2^(x*log2e).
// Magic-number round-to-nearest-int + degree-6 poly of 2^f on [-0.5, 0.5],
// scale folded into the exponent field. Runs on fma+alu pipes, leaving MUFU free.
__device__ __forceinline__ float exp_fma(float x) {
    float t = x * 1.44269504088896341f;
    float r = t + 12582912.0f;                      // 1.5 * 2^23
    int   n = __float_as_int(r) - 0x4B400000;
    float f = t - (r - 12582912.0f);                // f in [-0.5, 0.5]
    float p = 1.5403530393e-4f;
    p = fmaf(p, f, 1.3333558146e-3f);
    p = fmaf(p, f, 9.6181291076e-3f);
    p = fmaf(p, f, 5.5504108665e-2f);
    p = fmaf(p, f, 2.4022650696e-1f);
    p = fmaf(p, f, 6.9314718056e-1f);
    p = fmaf(p, f, 1.0f);
    return __int_as_float(__float_as_int(p) + (n << 23));
}
#define CP16(dst_u32, src_ptr) \
    asm volatile("cp.async.cg.shared.global [%0], [%1], 16;\n" :: "r"(dst_u32), "l"(src_ptr))
#define CP_COMMIT asm volatile("cp.async.commit_group;\n" ::: "memory")
#define CP_WAIT1  asm volatile("cp.async.wait_group 1;\n" ::: "memory")
#define CP_WAIT0  asm volatile("cp.async.wait_group 0;\n" ::: "memory")

__device__ __forceinline__ void mma16816(float4& d,
    uint32_t a0, uint32_t a1, uint32_t a2, uint32_t a3,
    uint32_t b0, uint32_t b1)
{
    asm volatile(
        "mma.sync.aligned.m16n8k16.row.col.f32.f16.f16.f32 "
        "{%0,%1,%2,%3},{%4,%5,%6,%7},{%8,%9},{%0,%1,%2,%3};\n"
        : "+f"(d.x), "+f"(d.y), "+f"(d.z), "+f"(d.w)
        : "r"(a0), "r"(a1), "r"(a2), "r"(a3), "r"(b0), "r"(b1));
}

__device__ __forceinline__ void ldsm4(uint32_t& r0, uint32_t& r1,
                                      uint32_t& r2, uint32_t& r3, uint32_t addr)
{
    asm volatile("ldmatrix.sync.aligned.m8n8.x4.shared.b16 {%0,%1,%2,%3}, [%4];\n"
                 : "=r"(r0), "=r"(r1), "=r"(r2), "=r"(r3) : "r"(addr));
}

__device__ __forceinline__ void lda_x4(uint32_t* f, uint32_t sbase, int lp_bytes,
                                       int rbase, int kb0, int lane)
{
    int seg = lane >> 3, rw = lane & 7;
    int row = rbase + rw + ((seg & 1) << 3);
    int col = kb0 + ((seg >> 1) << 3);
    ldsm4(f[0], f[1], f[2], f[3], sbase + row * lp_bytes + col * 2);
}
__device__ __forceinline__ void ldb_x4(uint32_t* f0, uint32_t* f1, uint32_t sbase,
                                       int lp_bytes, int cbase, int kb0, int lane)
{
    int seg = lane >> 3, rw = lane & 7;
    int row = cbase + rw + ((seg >> 1) << 3);
    int col = kb0 + ((seg & 1) << 3);
    ldsm4(f0[0], f0[1], f1[0], f1[1], sbase + row * lp_bytes + col * 2);
}

// ---------------------------------------------------------------------------
// Mask scan: per batch, prefix-compact unmasked columns. 1 block/batch.
// ---------------------------------------------------------------------------
__global__ __launch_bounds__(1024) void mask_scan_kernel(
    const int* __restrict__ mask, int* __restrict__ fwd,
    int* __restrict__ cidx, int* __restrict__ cnt)
{
    __shared__ int sa[1024], sb[1024];
    const int b = blockIdx.x, t = threadIdx.x;
    const int j0 = 2 * t, j1 = 2 * t + 1;
    const int m0 = (mask[b * SEQ + j0] == 0);
    const int m1 = (mask[b * SEQ + j1] == 0);
    sa[t] = m0 + m1;
    __syncthreads();
    int* src = sa; int* dst = sb;
    for (int off = 1; off < 1024; off <<= 1) {
        int v = src[t] + ((t >= off) ? src[t - off] : 0);
        dst[t] = v;
        __syncthreads();
        int* tmp = src; src = dst; dst = tmp;
    }
    const int incl = src[t];
    const int excl = incl - (m0 + m1);
    fwd[b * SEQ + j0] = m0 ? excl : -1;
    fwd[b * SEQ + j1] = m1 ? (excl + m0) : -1;
    if (m0) cidx[b * SEQ + excl] = j0;
    if (m1) cidx[b * SEQ + excl + m0] = j1;
    const int total = src[1023];
    if (t == 0) cnt[b] = total;
    __syncthreads();
    for (int s = t; s < SEQ; s += 1024)
        if (s >= total) cidx[b * SEQ + s] = 0;
}

// ---------------------------------------------------------------------------
// Elementwise split of q/k/v inputs
// ---------------------------------------------------------------------------
__global__ __launch_bounds__(256) void split_inputs_kernel(
    const float* __restrict__ q, const float* __restrict__ k,
    const float* __restrict__ v, __half* __restrict__ Xhi, __half* __restrict__ Xlo)
{
    const int z = blockIdx.y;
    const float* src = (z == 0) ? q : (z == 1) ? k : v;
    const size_t i = ((size_t)blockIdx.x * 256 + threadIdx.x) * 4;
    const size_t o = (size_t)z * BS_ROWS * DM + i;
    float4 x = *(const float4*)(src + i);
    *(__half2*)(Xhi + o)     = __floats2half2_rn(x.x, x.y);
    *(__half2*)(Xhi + o + 2) = __floats2half2_rn(x.z, x.w);
    *(__half2*)(Xlo + o)     = __floats2half2_rn(residf(x.x), residf(x.y));
    *(__half2*)(Xlo + o + 2) = __floats2half2_rn(residf(x.z), residf(x.w));
}

// ---------------------------------------------------------------------------
// Weight transpose+split
// ---------------------------------------------------------------------------
__global__ __launch_bounds__(256) void transpose_split_kernel(
    const float* __restrict__ Wq, const float* __restrict__ Wk,
    const float* __restrict__ Wv, const float* __restrict__ Wo,
    __half* __restrict__ ThiB, __half* __restrict__ TloB)
{
    const int z = blockIdx.z;
    const float* W = (z == 0) ? Wq : (z == 1) ? Wk : (z == 2) ? Wv : Wo;
    __half* Thi = ThiB + (size_t)z * DM * DM;
    __half* Tlo = TloB + (size_t)z * DM * DM;

    __shared__ float tile[32][33];
    const int k0 = blockIdx.y * 32, n0 = blockIdx.x * 32;
    const int tx = threadIdx.x & 31, ty = threadIdx.x >> 5;
#pragma unroll
    for (int i = 0; i < 4; i++) {
        int kk = ty + i * 8;
        tile[kk][tx] = W[(size_t)(k0 + kk) * DM + n0 + tx];
    }
    __syncthreads();
#pragma unroll
    for (int i = 0; i < 4; i++) {
        int nn = ty + i * 8;
        float x = tile[tx][nn];
        __half hi = __float2half_rn(x);
        Thi[(size_t)(n0 + nn) * DM + k0 + tx] = hi;
        Tlo[(size_t)(n0 + nn) * DM + k0 + tx] = __float2half_rn(x - __half2float(hi));
    }
}

// ---------------------------------------------------------------------------
// V transpose with compaction: V [4096][1024] -> Vt [bh][64][compact s]
// ---------------------------------------------------------------------------
__global__ __launch_bounds__(256) void transpose_v_kernel(
    const __half* __restrict__ Vhi, const __half* __restrict__ Vlo,
    const int* __restrict__ fwd,
    __half* __restrict__ Thi, __half* __restrict__ Tlo)
{
    __shared__ __half thi[32][33], tlo[32][33];
    const int n0 = blockIdx.x * 32;
    const int s0 = blockIdx.y * 32;
    const int tx = threadIdx.x & 31, ty = threadIdx.x >> 5;
#pragma unroll
    for (int i = 0; i < 4; i++) {
        int r = ty + i * 8;
        thi[r][tx] = Vhi[(size_t)(s0 + r) * DM + n0 + tx];
        tlo[r][tx] = Vlo[(size_t)(s0 + r) * DM + n0 + tx];
    }
    __syncthreads();
    const int b = s0 >> 11;
    const int slot = fwd[b * SEQ + (s0 & 2047) + tx];
    if (slot >= 0) {
#pragma unroll
        for (int i = 0; i < 4; i++) {
            int nn = ty + i * 8;
            int gn = n0 + nn;
            int h = gn >> 6, d = gn & 63;
            size_t orow = ((size_t)(b * NH + h) * DEPTH + d) * SEQ + slot;
            Thi[orow] = thi[tx][nn];
            Tlo[orow] = tlo[tx][nn];
        }
    }
}

// ---------------------------------------------------------------------------
// Double-buffered split-fp16 GEMM (projections). BM=BN=128, BK=32.
// ---------------------------------------------------------------------------
#define GSTAGE 40960
#define GEMM_SMEM (2 * GSTAGE)

__device__ __forceinline__ void gemm_load_stage(uint32_t smbase, int s,
    const __half* AhiG, const __half* AloG,
    const __half* BhiG, const __half* BloG,
    int m0, int n0, int k0, int tid)
{
    uint32_t sb = smbase + s * GSTAGE;
#pragma unroll
    for (int t = 0; t < 2; t++) {
        int id = tid * 2 + t;
        int r = id >> 2, q = id & 3;
        uint32_t off = r * 80 + q * 16;
        const size_t ga = (size_t)(m0 + r) * DM + k0 + q * 8;
        const size_t gb = (size_t)(n0 + r) * DM + k0 + q * 8;
        CP16(sb + off,         AhiG + ga);
        CP16(sb + 10240 + off, AloG + ga);
        CP16(sb + 20480 + off, BhiG + gb);
        CP16(sb + 30720 + off, BloG + gb);
    }
}

template<bool OUT_F32>
__device__ __forceinline__ void gemm_core(
    const __half* __restrict__ AhiG, const __half* __restrict__ AloG,
    const __half* __restrict__ BhiG, const __half* __restrict__ BloG,
    const float* __restrict__ bias,
    float* __restrict__ Cf, __half* __restrict__ Chi, __half* __restrict__ Clo)
{
    extern __shared__ char dsm[];
    const uint32_t smbase = smem_u32(dsm);

    const int tid = threadIdx.x;
    const int m0 = blockIdx.y * 128, n0 = blockIdx.x * 128;
    const int lane = tid & 31, wid = tid >> 5;
    const int wm = wid >> 2, wn = wid & 3;
    const int grp = lane >> 2, tig = lane & 3;

    float4 acc[4][4];
#pragma unroll
    for (int i = 0; i < 4; i++)
#pragma unroll
        for (int j = 0; j < 4; j++) acc[i][j] = make_float4(0.f, 0.f, 0.f, 0.f);

    gemm_load_stage(smbase, 0, AhiG, AloG, BhiG, BloG, m0, n0, 0, tid);
    CP_COMMIT;

    for (int kt = 0; kt < 32; kt++) {
        if (kt + 1 < 32) {
            gemm_load_stage(smbase, (kt + 1) & 1, AhiG, AloG, BhiG, BloG,
                            m0, n0, (kt + 1) * 32, tid);
            CP_COMMIT;
            CP_WAIT1;
        } else {
            CP_WAIT0;
        }
        __syncthreads();

        const uint32_t sb = smbase + (kt & 1) * GSTAGE;
        const uint32_t ah_b = sb, al_b = sb + 10240, bh_b = sb + 20480, bl_b = sb + 30720;
#pragma unroll
        for (int ks = 0; ks < 2; ks++) {
            const int kb0 = ks * 16;
            uint32_t ah[4][4], al[4][4];
#pragma unroll
            for (int mt = 0; mt < 4; mt++) {
                lda_x4(ah[mt], ah_b, 80, wm * 64 + mt * 16, kb0, lane);
                lda_x4(al[mt], al_b, 80, wm * 64 + mt * 16, kb0, lane);
            }
            uint32_t bhf[4][2], blf[4][2];
#pragma unroll
            for (int p = 0; p < 2; p++) {
                ldb_x4(bhf[2 * p], bhf[2 * p + 1], bh_b, 80, wn * 32 + p * 16, kb0, lane);
                ldb_x4(blf[2 * p], blf[2 * p + 1], bl_b, 80, wn * 32 + p * 16, kb0, lane);
            }
#pragma unroll
            for (int mt = 0; mt < 4; mt++)
#pragma unroll
                for (int nt = 0; nt < 4; nt++) {
                    mma16816(acc[mt][nt], ah[mt][0], ah[mt][1], ah[mt][2], ah[mt][3],
                             bhf[nt][0], bhf[nt][1]);
                    mma16816(acc[mt][nt], ah[mt][0], ah[mt][1], ah[mt][2], ah[mt][3],
                             blf[nt][0], blf[nt][1]);
                    mma16816(acc[mt][nt], al[mt][0], al[mt][1], al[mt][2], al[mt][3],
                             bhf[nt][0], bhf[nt][1]);
                }
        }
        __syncthreads();
    }

#pragma unroll
    for (int mt = 0; mt < 4; mt++) {
        int r = m0 + wm * 64 + mt * 16 + grp;
#pragma unroll
        for (int nt = 0; nt < 4; nt++) {
            int c = n0 + wn * 32 + nt * 8 + tig * 2;
            float bx = bias[c], by = bias[c + 1];
            float x0 = acc[mt][nt].x + bx, x1 = acc[mt][nt].y + by;
            float x2 = acc[mt][nt].z + bx, x3 = acc[mt][nt].w + by;
            if (OUT_F32) {
                *(float2*)&Cf[(size_t)r * DM + c]       = make_float2(x0, x1);
                *(float2*)&Cf[(size_t)(r + 8) * DM + c] = make_float2(x2, x3);
            } else {
                *(__half2*)&Chi[(size_t)r * DM + c]       = __floats2half2_rn(x0, x1);
                *(__half2*)&Chi[(size_t)(r + 8) * DM + c] = __floats2half2_rn(x2, x3);
                *(__half2*)&Clo[(size_t)r * DM + c]       = __floats2half2_rn(residf(x0), residf(x1));
                *(__half2*)&Clo[(size_t)(r + 8) * DM + c] = __floats2half2_rn(residf(x2), residf(x3));
            }
        }
    }
}

__global__ __launch_bounds__(256) void qkv_gemm_kernel(
    const __half* __restrict__ Xhi, const __half* __restrict__ Xlo,
    const __half* __restrict__ WThi, const __half* __restrict__ WTlo,
    const float* __restrict__ bq, const float* __restrict__ bk,
    const float* __restrict__ bv,
    __half* __restrict__ QKVhi, __half* __restrict__ QKVlo)
{
    const int z = blockIdx.z;
    const size_t asz = (size_t)BS_ROWS * DM, wsz = (size_t)DM * DM;
    const float* bias = (z == 0) ? bq : (z == 1) ? bk : bv;
    gemm_core<false>(Xhi + z * asz, Xlo + z * asz, WThi + z * wsz, WTlo + z * wsz,
                     bias, nullptr, QKVhi + z * asz, QKVlo + z * asz);
}

__global__ __launch_bounds__(256) void out_gemm_kernel(
    const __half* __restrict__ Cxhi, const __half* __restrict__ Cxlo,
    const __half* __restrict__ WThi, const __half* __restrict__ WTlo,
    const float* __restrict__ bo, float* __restrict__ out)
{
    const size_t wsz = (size_t)DM * DM;
    gemm_core<true>(Cxhi, Cxlo, WThi + 3 * wsz, WTlo + 3 * wsz, bo,
                    out, nullptr, nullptr);
}

// ---------------------------------------------------------------------------
// Logits over COMPACT columns: p = exp(0.125*QK) for unmasked cols only.
// Exp split across pipes: half MUFU (__expf), half FMA/ALU poly (exp_fma).
// ---------------------------------------------------------------------------
#define LP 72
#define LOGITS_SMEM (4 * 128 * LP * 2 + 128 * 4 * 4)

__global__ __launch_bounds__(256) void logits_kernel(
    const __half* __restrict__ Qhi, const __half* __restrict__ Qlo,
    const __half* __restrict__ Khi, const __half* __restrict__ Klo,
    const int* __restrict__ cidx, const int* __restrict__ cnt,
    __half* __restrict__ Phi, __half* __restrict__ Plo,
    float* __restrict__ partial)
{
    extern __shared__ __half sm[];
    __half (*Qh)[LP] = (__half(*)[LP])sm;
    __half (*Ql)[LP] = (__half(*)[LP])(sm + 128 * LP);
    __half (*Kh)[LP] = (__half(*)[LP])(sm + 2 * 128 * LP);
    __half (*Kl)[LP] = (__half(*)[LP])(sm + 3 * 128 * LP);
    float* sums = (float*)(sm + 4 * 128 * LP);

    const int tid = threadIdx.x;
    const int n0 = blockIdx.x * 128, m0 = blockIdx.y * 128;
    const int bh = blockIdx.z, b = bh >> 4, h = bh & 15;
    const int Mb = cnt[b];

    if (n0 >= Mb) {
        if (tid < 128)
            partial[((size_t)bh * SEQ + m0 + tid) * 16 + blockIdx.x] = 0.f;
        return;
    }

    const size_t hbase = (size_t)b * SEQ * DM + h * 64;
    const int* cb = cidx + b * SEQ;

#pragma unroll
    for (int t = 0; t < 16; t++) {
        int id = tid + 256 * t;
        int arr = id >> 10, rem = id & 1023;
        int r = rem >> 3, q = rem & 7;
        const __half* src = (arr == 0) ? Qhi : (arr == 1) ? Qlo : (arr == 2) ? Khi : Klo;
        __half (*dst)[LP] = (arr == 0) ? Qh : (arr == 1) ? Ql : (arr == 2) ? Kh : Kl;
        int rphys;
        if (arr < 2) rphys = m0 + r;
        else {
            int jr = n0 + r;
            rphys = (jr < Mb) ? cb[jr] : 0;
        }
        uint4 v = *(const uint4*)(src + hbase + (size_t)rphys * DM + q * 8);
        *(uint2*)&dst[r][q * 8]     = make_uint2(v.x, v.y);
        *(uint2*)&dst[r][q * 8 + 4] = make_uint2(v.z, v.w);
    }
    __syncthreads();

    const int lane = tid & 31, wid = tid >> 5;
    const int wm = wid >> 2, wn = wid & 3;
    const int grp = lane >> 2, tig = lane & 3;
    const uint32_t qh_b = smem_u32(Qh), ql_b = smem_u32(Ql);
    const uint32_t kh_b = smem_u32(Kh), kl_b = smem_u32(Kl);

    float4 acc[4][4];
#pragma unroll
    for (int i = 0; i < 4; i++)
#pragma unroll
        for (int j = 0; j < 4; j++) acc[i][j] = make_float4(0.f, 0.f, 0.f, 0.f);

#pragma unroll
    for (int ks = 0; ks < 4; ks++) {
        const int kb0 = ks * 16;
        uint32_t ah[4][4], al[4][4];
#pragma unroll
        for (int mt = 0; mt < 4; mt++) {
            lda_x4(ah[mt], qh_b, 144, wm * 64 + mt * 16, kb0, lane);
            lda_x4(al[mt], ql_b, 144, wm * 64 + mt * 16, kb0, lane);
        }
        uint32_t bhf[4][2], blf[4][2];
#pragma unroll
        for (int p = 0; p < 2; p++) {
            ldb_x4(bhf[2 * p], bhf[2 * p + 1], kh_b, 144, wn * 32 + p * 16, kb0, lane);
            ldb_x4(blf[2 * p], blf[2 * p + 1], kl_b, 144, wn * 32 + p * 16, kb0, lane);
        }
#pragma unroll
        for (int mt = 0; mt < 4; mt++)
#pragma unroll
            for (int nt = 0; nt < 4; nt++) {
                mma16816(acc[mt][nt], ah[mt][0], ah[mt][1], ah[mt][2], ah[mt][3],
                         bhf[nt][0], bhf[nt][1]);
                mma16816(acc[mt][nt], ah[mt][0], ah[mt][1], ah[mt][2], ah[mt][3],
                         blf[nt][0], blf[nt][1]);
                mma16816(acc[mt][nt], al[mt][0], al[mt][1], al[mt][2], al[mt][3],
                         bhf[nt][0], bhf[nt][1]);
            }
    }

    float rs0[4], rs1[4];
#pragma unroll
    for (int mt = 0; mt < 4; mt++) { rs0[mt] = 0.f; rs1[mt] = 0.f; }

#pragma unroll
    for (int mt = 0; mt < 4; mt++) {
        int r = m0 + wm * 64 + mt * 16 + grp;
        __half* oh0 = Phi + ((size_t)bh * SEQ + r) * SEQ;
        __half* ol0 = Plo + ((size_t)bh * SEQ + r) * SEQ;
        __half* oh1 = oh0 + (size_t)8 * SEQ;
        __half* ol1 = ol0 + (size_t)8 * SEQ;
#pragma unroll
        for (int nt = 0; nt < 4; nt++) {
            int j = n0 + wn * 32 + nt * 8 + tig * 2;
            bool v0 = (j < Mb), v1 = (j + 1 < Mb);
            float4 a = acc[mt][nt];
            // Split exp work across pipes: p0,p2 on MUFU; p1,p3 on FMA/ALU.
            float p0 = v0 ? __expf(a.x * 0.125f)   : 0.f;
            float p1 = v1 ? exp_fma(a.y * 0.125f)  : 0.f;
            float p2 = v0 ? __expf(a.z * 0.125f)   : 0.f;
            float p3 = v1 ? exp_fma(a.w * 0.125f)  : 0.f;
            *(__half2*)(oh0 + j) = __floats2half2_rn(p0, p1);
            *(__half2*)(ol0 + j) = __floats2half2_rn(residf(p0), residf(p1));
            *(__half2*)(oh1 + j) = __floats2half2_rn(p2, p3);
            *(__half2*)(ol1 + j) = __floats2half2_rn(residf(p2), residf(p3));
            rs0[mt] += p0 + p1;
            rs1[mt] += p2 + p3;
        }
    }
#pragma unroll
    for (int mt = 0; mt < 4; mt++) {
        float s0 = rs0[mt], s1 = rs1[mt];
        s0 += __shfl_xor_sync(0xffffffffu, s0, 1);
        s0 += __shfl_xor_sync(0xffffffffu, s0, 2);
        s1 += __shfl_xor_sync(0xffffffffu, s1, 1);
        s1 += __shfl_xor_sync(0xffffffffu, s1, 2);
        if (tig == 0) {
            int rl = wm * 64 + mt * 16 + grp;
            sums[(size_t)rl * 4 + wn] = s0;
            sums[(size_t)(rl + 8) * 4 + wn] = s1;
        }
    }
    __syncthreads();
    if (tid < 128) {
        float tot = (sums[tid * 4 + 0] + sums[tid * 4 + 1]) +
                    (sums[tid * 4 + 2] + sums[tid * 4 + 3]);
        partial[((size_t)bh * SEQ + m0 + tid) * 16 + blockIdx.x] = tot;
    }
}

__global__ __launch_bounds__(256) void reduce_sums_kernel(
    const float* __restrict__ partial, float* __restrict__ rowsum)
{
    int i = blockIdx.x * 256 + threadIdx.x;
    const float4* p = (const float4*)(partial + (size_t)i * 16);
    float4 a = p[0], b = p[1], c = p[2], d = p[3];
    rowsum[i] = ((a.x + a.y) + (a.z + a.w)) + ((b.x + b.y) + (b.z + b.w)) +
                ((c.x + c.y) + (c.z + c.w)) + ((d.x + d.y) + (d.z + d.w));
}

// ---------------------------------------------------------------------------
// AV over compact K-dim: ctx = (P @ Vc) / rowsum. BM=128, BN=64, BK=64.
// ---------------------------------------------------------------------------
#define AV_SMEM (2 * 128 * LP * 2 + 2 * 64 * LP * 2 + 128 * 4)

__global__ __launch_bounds__(256) void av_kernel(
    const __half* __restrict__ Phi, const __half* __restrict__ Plo,
    const __half* __restrict__ Vthi, const __half* __restrict__ Vtlo,
    const float* __restrict__ rowsum, const int* __restrict__ cnt,
    __half* __restrict__ Chi, __half* __restrict__ Clo)
{
    extern __shared__ char smraw[];
    __half (*Ah)[LP] = (__half(*)[LP])smraw;
    __half (*Al)[LP] = (__half(*)[LP])(smraw + 128 * LP * 2);
    __half (*Vh)[LP] = (__half(*)[LP])(smraw + 2 * 128 * LP * 2);
    __half (*Vl)[LP] = (__half(*)[LP])(smraw + 2 * 128 * LP * 2 + 64 * LP * 2);
    float* sinv = (float*)(smraw + 2 * 128 * LP * 2 + 2 * 64 * LP * 2);

    const int tid = threadIdx.x;
    const int m0 = blockIdx.x * 128;
    const int bh = blockIdx.y, b = bh >> 4, h = bh & 15;
    const int Mb = cnt[b];

    if (tid < 128) sinv[tid] = 1.0f / rowsum[(size_t)bh * SEQ + m0 + tid];
    __syncthreads();

    const int lane = tid & 31, wid = tid >> 5;
    const int wm = wid >> 2, wn = wid & 3;
    const int grp = lane >> 2, tig = lane & 3;
    const uint32_t ah_b = smem_u32(Ah), al_b = smem_u32(Al);
    const uint32_t vh_b = smem_u32(Vh), vl_b = smem_u32(Vl);

    float4 acc[4][2];
#pragma unroll
    for (int i = 0; i < 4; i++)
#pragma unroll
        for (int j = 0; j < 2; j++) acc[i][j] = make_float4(0.f, 0.f, 0.f, 0.f);

    const size_t prow = (size_t)bh * SEQ + m0;
    const size_t vtb = (size_t)bh * DEPTH * SEQ;

    for (int k0 = 0; k0 < Mb; k0 += 64) {
        // P tiles: 128 rows x 64 cols x {hi,lo} = 2048 uint4 / 256 thr
#pragma unroll
        for (int t = 0; t < 8; t++) {
            int id = tid + 256 * t;
            int arr = id >> 10, rem = id & 1023;
            int r = rem >> 3, q = rem & 7;
            const __half* src = arr ? Plo : Phi;
            __half (*dst)[LP] = arr ? Al : Ah;
            uint4 v = *(const uint4*)(src + (prow + r) * SEQ + k0 + q * 8);
            *(uint2*)&dst[r][q * 8]     = make_uint2(v.x, v.y);
            *(uint2*)&dst[r][q * 8 + 4] = make_uint2(v.z, v.w);
        }
        // V tiles: 64 d-rows x 64 cols x {hi,lo} = 1024 uint4 / 256 thr
#pragma unroll
        for (int t = 0; t < 4; t++) {
            int id = tid + 256 * t;            // 0..1023
            int arr = id >> 9, rem = id & 511; // arr 0/1, rem 0..511
            int r = rem >> 3, q = rem & 7;     // r 0..63, q 0..7
            const __half* src = arr ? Vtlo : Vthi;
            __half (*dst)[LP] = arr ? Vl : Vh;
            uint4 v = *(const uint4*)(src + vtb + (size_t)r * SEQ + k0 + q * 8);
            *(uint2*)&dst[r][q * 8]     = make_uint2(v.x, v.y);
            *(uint2*)&dst[r][q * 8 + 4] = make_uint2(v.z, v.w);
        }
        __syncthreads();

#pragma unroll
        for (int ks = 0; ks < 4; ks++) {
            const int kb0 = ks * 16;
            uint32_t ah[4][4], al[4][4];
#pragma unroll
            for (int mt = 0; mt < 4; mt++) {
                lda_x4(ah[mt], ah_b, 144, wm * 64 + mt * 16, kb0, lane);
                lda_x4(al[mt], al_b, 144, wm * 64 + mt * 16, kb0, lane);
            }
            uint32_t bhf[2][2], blf[2][2];
            ldb_x4(bhf[0], bhf[1], vh_b, 144, wn * 16, kb0, lane);
            ldb_x4(blf[0], blf[1], vl_b, 144, wn * 16, kb0, lane);
#pragma unroll
            for (int mt = 0; mt < 4; mt++)
#pragma unroll
                for (int nt = 0; nt < 2; nt++) {
                    mma16816(acc[mt][nt], ah[mt][0], ah[mt][1], ah[mt][2], ah[mt][3],
                             bhf[nt][0], bhf[nt][1]);
                    mma16816(acc[mt][nt], ah[mt][0], ah[mt][1], ah[mt][2], ah[mt][3],
                             blf[nt][0], blf[nt][1]);
                    mma16816(acc[mt][nt], al[mt][0], al[mt][1], al[mt][2], al[mt][3],
                             bhf[nt][0], bhf[nt][1]);
                }
        }
        __syncthreads();
    }

#pragma unroll
    for (int mt = 0; mt < 4; mt++) {
        int rl = wm * 64 + mt * 16 + grp;
        int r = m0 + rl;
        float iv0 = sinv[rl], iv1 = sinv[rl + 8];
#pragma unroll
        for (int nt = 0; nt < 2; nt++) {
            int d = wn * 16 + nt * 8 + tig * 2;
            size_t o = ((size_t)(b * SEQ + r)) * DM + h * 64 + d;
            float x0 = acc[mt][nt].x * iv0, x1 = acc[mt][nt].y * iv0;
            float x2 = acc[mt][nt].z * iv1, x3 = acc[mt][nt].w * iv1;
            *(__half2*)&Chi[o]          = __floats2half2_rn(x0, x1);
            *(__half2*)&Chi[o + 8 * DM] = __floats2half2_rn(x2, x3);
            *(__half2*)&Clo[o]          = __floats2half2_rn(residf(x0), residf(x1));
            *(__half2*)&Clo[o + 8 * DM] = __floats2half2_rn(residf(x2), residf(x3));
        }
    }
}

// ---------------------------------------------------------------------------
// Expand: write final full-width attn = mask ? 0 : (hi+lo)/rowsum. 1 block/row.
// ---------------------------------------------------------------------------
__global__ __launch_bounds__(256) void expand_kernel(
    const __half* __restrict__ Phi, const __half* __restrict__ Plo,
    const float* __restrict__ rowsum, const int* __restrict__ fwd,
    float* __restrict__ attn)
{
    const int row = blockIdx.x;            // 0 .. BH*SEQ-1
    const int b = row >> 15;               // NH*SEQ = 32768
    const float inv = 1.0f / rowsum[row];
    const __half* ph = Phi + (size_t)row * SEQ;
    const __half* pl = Plo + (size_t)row * SEQ;
    const int* fw = fwd + b * SEQ;
    float* o = attn + (size_t)row * SEQ;

    const int j0 = threadIdx.x * 8;
    float vals[8];
#pragma unroll
    for (int t = 0; t < 8; t++) {
        int f = fw[j0 + t];
        vals[t] = (f >= 0)
            ? (__half2float(ph[f]) + __half2float(pl[f])) * inv : 0.f;
    }
    *(float4*)(o + j0)     = make_float4(vals[0], vals[1], vals[2], vals[3]);
    *(float4*)(o + j0 + 4) = make_float4(vals[4], vals[5], vals[6], vals[7]);
}

// ---------------------------------------------------------------------------
// Launcher
// ---------------------------------------------------------------------------
extern "C" void kernel_launch(void* const* d_in, const int* in_sizes, int n_in,
                              void* d_out, int out_size)
{
    const float* v    = (const float*)d_in[0];
    const float* k    = (const float*)d_in[1];
    const float* q    = (const float*)d_in[2];
    const int*   mask = (const int*)  d_in[3];
    const float* Wq = (const float*)d_in[4];
    const float* bq = (const float*)d_in[5];
    const float* Wk = (const float*)d_in[6];
    const float* bk = (const float*)d_in[7];
    const float* Wv = (const float*)d_in[8];
    const float* bv = (const float*)d_in[9];
    const float* Wo = (const float*)d_in[10];
    const float* bo = (const float*)d_in[11];
    float* out = (float*)d_out;

    __half *Xhi, *Xlo, *QKVhi, *QKVlo, *Vthi, *Vtlo, *Cxhi, *Cxlo, *WThi, *WTlo;
    __half *Phi, *Plo;
    float *attnScratch, *partialp, *rowsump;
    int *fwdp, *cidxp, *cntp;
    cudaGetSymbolAddress((void**)&Xhi, g_Xhi);
    cudaGetSymbolAddress((void**)&Xlo, g_Xlo);
    cudaGetSymbolAddress((void**)&QKVhi, g_QKVhi);
    cudaGetSymbolAddress((void**)&QKVlo, g_QKVlo);
    cudaGetSymbolAddress((void**)&Vthi, g_Vthi);
    cudaGetSymbolAddress((void**)&Vtlo, g_Vtlo);
    cudaGetSymbolAddress((void**)&Cxhi, g_Cxhi);
    cudaGetSymbolAddress((void**)&Cxlo, g_Cxlo);
    cudaGetSymbolAddress((void**)&WThi, g_WThi);
    cudaGetSymbolAddress((void**)&WTlo, g_WTlo);
    cudaGetSymbolAddress((void**)&Phi, g_Phi);
    cudaGetSymbolAddress((void**)&Plo, g_Plo);
    cudaGetSymbolAddress((void**)&attnScratch, g_attn);
    cudaGetSymbolAddress((void**)&partialp, g_partial);
    cudaGetSymbolAddress((void**)&rowsump, g_rowsum);
    cudaGetSymbolAddress((void**)&fwdp, g_fwd);
    cudaGetSymbolAddress((void**)&cidxp, g_cidx);
    cudaGetSymbolAddress((void**)&cntp, g_cnt);

    cudaFuncSetAttribute(qkv_gemm_kernel,
                         cudaFuncAttributeMaxDynamicSharedMemorySize, GEMM_SMEM);
    cudaFuncSetAttribute(out_gemm_kernel,
                         cudaFuncAttributeMaxDynamicSharedMemorySize, GEMM_SMEM);
    cudaFuncSetAttribute(logits_kernel,
                         cudaFuncAttributeMaxDynamicSharedMemorySize, LOGITS_SMEM);
    cudaFuncSetAttribute(av_kernel,
                         cudaFuncAttributeMaxDynamicSharedMemorySize, AV_SMEM);

    const size_t FINAL_ELEMS = (size_t)BS_ROWS * DM;
    const size_t ATTN_ELEMS  = (size_t)BH * SEQ * SEQ;
    const size_t asz = (size_t)BS_ROWS * DM;
    float* attnp = ((size_t)out_size >= FINAL_ELEMS + ATTN_ELEMS)
                       ? (out + FINAL_ELEMS) : attnScratch;

    mask_scan_kernel<<<BATCH, 1024>>>(mask, fwdp, cidxp, cntp);
    split_inputs_kernel<<<dim3(4096, 3), 256>>>(q, k, v, Xhi, Xlo);
    transpose_split_kernel<<<dim3(32, 32, 4), 256>>>(Wq, Wk, Wv, Wo, WThi, WTlo);

    qkv_gemm_kernel<<<dim3(8, 32, 3), 256, GEMM_SMEM>>>(
        Xhi, Xlo, WThi, WTlo, bq, bk, bv, QKVhi, QKVlo);

    transpose_v_kernel<<<dim3(32, 128), 256>>>(
        QKVhi + 2 * asz, QKVlo + 2 * asz, fwdp, Vthi, Vtlo);

    logits_kernel<<<dim3(16, 16, BH), 256, LOGITS_SMEM>>>(
        QKVhi, QKVlo, QKVhi + asz, QKVlo + asz, cidxp, cntp, Phi, Plo, partialp);

    reduce_sums_kernel<<<(BH * SEQ) / 256, 256>>>(partialp, rowsump);

    av_kernel<<<dim3(16, BH), 256, AV_SMEM>>>(
        Phi, Plo, Vthi, Vtlo, rowsump, cntp, Cxhi, Cxlo);

    expand_kernel<<<BH * SEQ, 256>>>(Phi, Plo, rowsump, fwdp, attnp);

    out_gemm_kernel<<<dim3(8, 32), 256, GEMM_SMEM>>>(
        Cxhi, Cxlo, WThi, WTlo, bo, out);
}

// round 11
// speedup vs baseline: 1.0302x; 1.0302x over previous
#include <cuda_runtime.h>
#include <cuda_fp16.h>
#include <math.h>
#include <stdint.h>
#include <stddef.h>

#define DM 1024
#define NH 16
#define DEPTH 64
#define BATCH 2
#define SEQ 2048
#define BS_ROWS 4096
#define BH 32

// ---------------------------------------------------------------------------
// Scratch (__device__ globals; allocation-free rule). Zero-initialized.
// ---------------------------------------------------------------------------
__device__ __half g_Xhi[3][(size_t)BS_ROWS * DM];
__device__ __half g_Xlo[3][(size_t)BS_ROWS * DM];
__device__ __half g_QKVhi[3][(size_t)BS_ROWS * DM];
__device__ __half g_QKVlo[3][(size_t)BS_ROWS * DM];
__device__ __half g_Vthi[(size_t)BH * DEPTH * SEQ];   // [bh][d][compact s]
__device__ __half g_Vtlo[(size_t)BH * DEPTH * SEQ];
__device__ __half g_Cxhi[(size_t)BS_ROWS * DM];
__device__ __half g_Cxlo[(size_t)BS_ROWS * DM];
__device__ __half g_WThi[4][(size_t)DM * DM];
__device__ __half g_WTlo[4][(size_t)DM * DM];
__device__ __half g_Phi[(size_t)BH * SEQ * SEQ];      // exp(p) hi, compact cols
__device__ __half g_Plo[(size_t)BH * SEQ * SEQ];      // exp(p) lo residual
__device__ float  g_attn[(size_t)BH * SEQ * SEQ];     // fallback full attn
__device__ float  g_partial[(size_t)BH * SEQ * 16];
__device__ float  g_rowsum[(size_t)BH * SEQ];
__device__ int    g_fwd[BATCH * SEQ];
__device__ int    g_cidx[BATCH * SEQ];
__device__ int    g_cnt[BATCH];

// ---------------------------------------------------------------------------
// Helpers
// ---------------------------------------------------------------------------
__device__ __forceinline__ float residf(float x) {
    return x - __half2float(__float2half_rn(x));
}
__device__ __forceinline__ uint32_t smem_u32(const void* p) {
    return (uint32_t)__cvta_generic_to_shared(p);
}
#define CP16(dst_u32, src_ptr) \
    asm volatile("cp.async.cg.shared.global [%0], [%1], 16;\n" :: "r"(dst_u32), "l"(src_ptr))
#define CP_COMMIT asm volatile("cp.async.commit_group;\n" ::: "memory")
#define CP_WAIT1  asm volatile("cp.async.wait_group 1;\n" ::: "memory")
#define CP_WAIT0  asm volatile("cp.async.wait_group 0;\n" ::: "memory")

__device__ __forceinline__ void mma16816(float4& d,
    uint32_t a0, uint32_t a1, uint32_t a2, uint32_t a3,
    uint32_t b0, uint32_t b1)
{
    asm volatile(
        "mma.sync.aligned.m16n8k16.row.col.f32.f16.f16.f32 "
        "{%0,%1,%2,%3},{%4,%5,%6,%7},{%8,%9},{%0,%1,%2,%3};\n"
        : "+f"(d.x), "+f"(d.y), "+f"(d.z), "+f"(d.w)
        : "r"(a0), "r"(a1), "r"(a2), "r"(a3), "r"(b0), "r"(b1));
}

__device__ __forceinline__ void ldsm4(uint32_t& r0, uint32_t& r1,
                                      uint32_t& r2, uint32_t& r3, uint32_t addr)
{
    asm volatile("ldmatrix.sync.aligned.m8n8.x4.shared.b16 {%0,%1,%2,%3}, [%4];\n"
                 : "=r"(r0), "=r"(r1), "=r"(r2), "=r"(r3) : "r"(addr));
}

__device__ __forceinline__ void lda_x4(uint32_t* f, uint32_t sbase, int lp_bytes,
                                       int rbase, int kb0, int lane)
{
    int seg = lane >> 3, rw = lane & 7;
    int row = rbase + rw + ((seg & 1) << 3);
    int col = kb0 + ((seg >> 1) << 3);
    ldsm4(f[0], f[1], f[2], f[3], sbase + row * lp_bytes + col * 2);
}
__device__ __forceinline__ void ldb_x4(uint32_t* f0, uint32_t* f1, uint32_t sbase,
                                       int lp_bytes, int cbase, int kb0, int lane)
{
    int seg = lane >> 3, rw = lane & 7;
    int row = cbase + rw + ((seg >> 1) << 3);
    int col = kb0 + ((seg & 1) << 3);
    ldsm4(f0[0], f0[1], f1[0], f1[1], sbase + row * lp_bytes + col * 2);
}

// ---------------------------------------------------------------------------
// Mask scan: per batch, prefix-compact unmasked columns. 1 block/batch.
// ---------------------------------------------------------------------------
__global__ __launch_bounds__(1024) void mask_scan_kernel(
    const int* __restrict__ mask, int* __restrict__ fwd,
    int* __restrict__ cidx, int* __restrict__ cnt)
{
    __shared__ int sa[1024], sb[1024];
    const int b = blockIdx.x, t = threadIdx.x;
    const int j0 = 2 * t, j1 = 2 * t + 1;
    const int m0 = (mask[b * SEQ + j0] == 0);
    const int m1 = (mask[b * SEQ + j1] == 0);
    sa[t] = m0 + m1;
    __syncthreads();
    int* src = sa; int* dst = sb;
    for (int off = 1; off < 1024; off <<= 1) {
        int v = src[t] + ((t >= off) ? src[t - off] : 0);
        dst[t] = v;
        __syncthreads();
        int* tmp = src; src = dst; dst = tmp;
    }
    const int incl = src[t];
    const int excl = incl - (m0 + m1);
    fwd[b * SEQ + j0] = m0 ? excl : -1;
    fwd[b * SEQ + j1] = m1 ? (excl + m0) : -1;
    if (m0) cidx[b * SEQ + excl] = j0;
    if (m1) cidx[b * SEQ + excl + m0] = j1;
    const int total = src[1023];
    if (t == 0) cnt[b] = total;
    __syncthreads();
    for (int s = t; s < SEQ; s += 1024)
        if (s >= total) cidx[b * SEQ + s] = 0;
}

// ---------------------------------------------------------------------------
// Elementwise split of q/k/v inputs
// ---------------------------------------------------------------------------
__global__ __launch_bounds__(256) void split_inputs_kernel(
    const float* __restrict__ q, const float* __restrict__ k,
    const float* __restrict__ v, __half* __restrict__ Xhi, __half* __restrict__ Xlo)
{
    const int z = blockIdx.y;
    const float* src = (z == 0) ? q : (z == 1) ? k : v;
    const size_t i = ((size_t)blockIdx.x * 256 + threadIdx.x) * 4;
    const size_t o = (size_t)z * BS_ROWS * DM + i;
    float4 x = *(const float4*)(src + i);
    *(__half2*)(Xhi + o)     = __floats2half2_rn(x.x, x.y);
    *(__half2*)(Xhi + o + 2) = __floats2half2_rn(x.z, x.w);
    *(__half2*)(Xlo + o)     = __floats2half2_rn(residf(x.x), residf(x.y));
    *(__half2*)(Xlo + o + 2) = __floats2half2_rn(residf(x.z), residf(x.w));
}

// ---------------------------------------------------------------------------
// Weight transpose+split
// ---------------------------------------------------------------------------
__global__ __launch_bounds__(256) void transpose_split_kernel(
    const float* __restrict__ Wq, const float* __restrict__ Wk,
    const float* __restrict__ Wv, const float* __restrict__ Wo,
    __half* __restrict__ ThiB, __half* __restrict__ TloB)
{
    const int z = blockIdx.z;
    const float* W = (z == 0) ? Wq : (z == 1) ? Wk : (z == 2) ? Wv : Wo;
    __half* Thi = ThiB + (size_t)z * DM * DM;
    __half* Tlo = TloB + (size_t)z * DM * DM;

    __shared__ float tile[32][33];
    const int k0 = blockIdx.y * 32, n0 = blockIdx.x * 32;
    const int tx = threadIdx.x & 31, ty = threadIdx.x >> 5;
#pragma unroll
    for (int i = 0; i < 4; i++) {
        int kk = ty + i * 8;
        tile[kk][tx] = W[(size_t)(k0 + kk) * DM + n0 + tx];
    }
    __syncthreads();
#pragma unroll
    for (int i = 0; i < 4; i++) {
        int nn = ty + i * 8;
        float x = tile[tx][nn];
        __half hi = __float2half_rn(x);
        Thi[(size_t)(n0 + nn) * DM + k0 + tx] = hi;
        Tlo[(size_t)(n0 + nn) * DM + k0 + tx] = __float2half_rn(x - __half2float(hi));
    }
}

// ---------------------------------------------------------------------------
// V transpose with compaction: V [4096][1024] -> Vt [bh][64][compact s]
// ---------------------------------------------------------------------------
__global__ __launch_bounds__(256) void transpose_v_kernel(
    const __half* __restrict__ Vhi, const __half* __restrict__ Vlo,
    const int* __restrict__ fwd,
    __half* __restrict__ Thi, __half* __restrict__ Tlo)
{
    __shared__ __half thi[32][33], tlo[32][33];
    const int n0 = blockIdx.x * 32;
    const int s0 = blockIdx.y * 32;
    const int tx = threadIdx.x & 31, ty = threadIdx.x >> 5;
#pragma unroll
    for (int i = 0; i < 4; i++) {
        int r = ty + i * 8;
        thi[r][tx] = Vhi[(size_t)(s0 + r) * DM + n0 + tx];
        tlo[r][tx] = Vlo[(size_t)(s0 + r) * DM + n0 + tx];
    }
    __syncthreads();
    const int b = s0 >> 11;
    const int slot = fwd[b * SEQ + (s0 & 2047) + tx];
    if (slot >= 0) {
#pragma unroll
        for (int i = 0; i < 4; i++) {
            int nn = ty + i * 8;
            int gn = n0 + nn;
            int h = gn >> 6, d = gn & 63;
            size_t orow = ((size_t)(b * NH + h) * DEPTH + d) * SEQ + slot;
            Thi[orow] = thi[tx][nn];
            Tlo[orow] = tlo[tx][nn];
        }
    }
}

// ---------------------------------------------------------------------------
// Double-buffered split-fp16 GEMM (projections). BM=BN=128, BK=32.
// ---------------------------------------------------------------------------
#define GSTAGE 40960
#define GEMM_SMEM (2 * GSTAGE)

__device__ __forceinline__ void gemm_load_stage(uint32_t smbase, int s,
    const __half* AhiG, const __half* AloG,
    const __half* BhiG, const __half* BloG,
    int m0, int n0, int k0, int tid)
{
    uint32_t sb = smbase + s * GSTAGE;
#pragma unroll
    for (int t = 0; t < 2; t++) {
        int id = tid * 2 + t;
        int r = id >> 2, q = id & 3;
        uint32_t off = r * 80 + q * 16;
        const size_t ga = (size_t)(m0 + r) * DM + k0 + q * 8;
        const size_t gb = (size_t)(n0 + r) * DM + k0 + q * 8;
        CP16(sb + off,         AhiG + ga);
        CP16(sb + 10240 + off, AloG + ga);
        CP16(sb + 20480 + off, BhiG + gb);
        CP16(sb + 30720 + off, BloG + gb);
    }
}

template<bool OUT_F32>
__device__ __forceinline__ void gemm_core(
    const __half* __restrict__ AhiG, const __half* __restrict__ AloG,
    const __half* __restrict__ BhiG, const __half* __restrict__ BloG,
    const float* __restrict__ bias,
    float* __restrict__ Cf, __half* __restrict__ Chi, __half* __restrict__ Clo)
{
    extern __shared__ char dsm[];
    const uint32_t smbase = smem_u32(dsm);

    const int tid = threadIdx.x;
    const int m0 = blockIdx.y * 128, n0 = blockIdx.x * 128;
    const int lane = tid & 31, wid = tid >> 5;
    const int wm = wid >> 2, wn = wid & 3;
    const int grp = lane >> 2, tig = lane & 3;

    float4 acc[4][4];
#pragma unroll
    for (int i = 0; i < 4; i++)
#pragma unroll
        for (int j = 0; j < 4; j++) acc[i][j] = make_float4(0.f, 0.f, 0.f, 0.f);

    gemm_load_stage(smbase, 0, AhiG, AloG, BhiG, BloG, m0, n0, 0, tid);
    CP_COMMIT;

    for (int kt = 0; kt < 32; kt++) {
        if (kt + 1 < 32) {
            gemm_load_stage(smbase, (kt + 1) & 1, AhiG, AloG, BhiG, BloG,
                            m0, n0, (kt + 1) * 32, tid);
            CP_COMMIT;
            CP_WAIT1;
        } else {
            CP_WAIT0;
        }
        __syncthreads();

        const uint32_t sb = smbase + (kt & 1) * GSTAGE;
        const uint32_t ah_b = sb, al_b = sb + 10240, bh_b = sb + 20480, bl_b = sb + 30720;
#pragma unroll
        for (int ks = 0; ks < 2; ks++) {
            const int kb0 = ks * 16;
            uint32_t ah[4][4], al[4][4];
#pragma unroll
            for (int mt = 0; mt < 4; mt++) {
                lda_x4(ah[mt], ah_b, 80, wm * 64 + mt * 16, kb0, lane);
                lda_x4(al[mt], al_b, 80, wm * 64 + mt * 16, kb0, lane);
            }
            uint32_t bhf[4][2], blf[4][2];
#pragma unroll
            for (int p = 0; p < 2; p++) {
                ldb_x4(bhf[2 * p], bhf[2 * p + 1], bh_b, 80, wn * 32 + p * 16, kb0, lane);
                ldb_x4(blf[2 * p], blf[2 * p + 1], bl_b, 80, wn * 32 + p * 16, kb0, lane);
            }
#pragma unroll
            for (int mt = 0; mt < 4; mt++)
#pragma unroll
                for (int nt = 0; nt < 4; nt++) {
                    mma16816(acc[mt][nt], ah[mt][0], ah[mt][1], ah[mt][2], ah[mt][3],
                             bhf[nt][0], bhf[nt][1]);
                    mma16816(acc[mt][nt], ah[mt][0], ah[mt][1], ah[mt][2], ah[mt][3],
                             blf[nt][0], blf[nt][1]);
                    mma16816(acc[mt][nt], al[mt][0], al[mt][1], al[mt][2], al[mt][3],
                             bhf[nt][0], bhf[nt][1]);
                }
        }
        __syncthreads();
    }

#pragma unroll
    for (int mt = 0; mt < 4; mt++) {
        int r = m0 + wm * 64 + mt * 16 + grp;
#pragma unroll
        for (int nt = 0; nt < 4; nt++) {
            int c = n0 + wn * 32 + nt * 8 + tig * 2;
            float bx = bias[c], by = bias[c + 1];
            float x0 = acc[mt][nt].x + bx, x1 = acc[mt][nt].y + by;
            float x2 = acc[mt][nt].z + bx, x3 = acc[mt][nt].w + by;
            if (OUT_F32) {
                *(float2*)&Cf[(size_t)r * DM + c]       = make_float2(x0, x1);
                *(float2*)&Cf[(size_t)(r + 8) * DM + c] = make_float2(x2, x3);
            } else {
                *(__half2*)&Chi[(size_t)r * DM + c]       = __floats2half2_rn(x0, x1);
                *(__half2*)&Chi[(size_t)(r + 8) * DM + c] = __floats2half2_rn(x2, x3);
                *(__half2*)&Clo[(size_t)r * DM + c]       = __floats2half2_rn(residf(x0), residf(x1));
                *(__half2*)&Clo[(size_t)(r + 8) * DM + c] = __floats2half2_rn(residf(x2), residf(x3));
            }
        }
    }
}

__global__ __launch_bounds__(256) void qkv_gemm_kernel(
    const __half* __restrict__ Xhi, const __half* __restrict__ Xlo,
    const __half* __restrict__ WThi, const __half* __restrict__ WTlo,
    const float* __restrict__ bq, const float* __restrict__ bk,
    const float* __restrict__ bv,
    __half* __restrict__ QKVhi, __half* __restrict__ QKVlo)
{
    const int z = blockIdx.z;
    const size_t asz = (size_t)BS_ROWS * DM, wsz = (size_t)DM * DM;
    const float* bias = (z == 0) ? bq : (z == 1) ? bk : bv;
    gemm_core<false>(Xhi + z * asz, Xlo + z * asz, WThi + z * wsz, WTlo + z * wsz,
                     bias, nullptr, QKVhi + z * asz, QKVlo + z * asz);
}

__global__ __launch_bounds__(256) void out_gemm_kernel(
    const __half* __restrict__ Cxhi, const __half* __restrict__ Cxlo,
    const __half* __restrict__ WThi, const __half* __restrict__ WTlo,
    const float* __restrict__ bo, float* __restrict__ out)
{
    const size_t wsz = (size_t)DM * DM;
    gemm_core<true>(Cxhi, Cxlo, WThi + 3 * wsz, WTlo + 3 * wsz, bo,
                    out, nullptr, nullptr);
}

// ---------------------------------------------------------------------------
// Logits over COMPACT columns: p = exp(0.125*QK) for unmasked cols only.
// ---------------------------------------------------------------------------
#define LP 72
#define LOGITS_SMEM (4 * 128 * LP * 2 + 128 * 4 * 4)

__global__ __launch_bounds__(256) void logits_kernel(
    const __half* __restrict__ Qhi, const __half* __restrict__ Qlo,
    const __half* __restrict__ Khi, const __half* __restrict__ Klo,
    const int* __restrict__ cidx, const int* __restrict__ cnt,
    __half* __restrict__ Phi, __half* __restrict__ Plo,
    float* __restrict__ partial)
{
    extern __shared__ __half sm[];
    __half (*Qh)[LP] = (__half(*)[LP])sm;
    __half (*Ql)[LP] = (__half(*)[LP])(sm + 128 * LP);
    __half (*Kh)[LP] = (__half(*)[LP])(sm + 2 * 128 * LP);
    __half (*Kl)[LP] = (__half(*)[LP])(sm + 3 * 128 * LP);
    float* sums = (float*)(sm + 4 * 128 * LP);

    const int tid = threadIdx.x;
    const int n0 = blockIdx.x * 128, m0 = blockIdx.y * 128;
    const int bh = blockIdx.z, b = bh >> 4, h = bh & 15;
    const int Mb = cnt[b];

    if (n0 >= Mb) {
        if (tid < 128)
            partial[((size_t)bh * SEQ + m0 + tid) * 16 + blockIdx.x] = 0.f;
        return;
    }

    const size_t hbase = (size_t)b * SEQ * DM + h * 64;
    const int* cb = cidx + b * SEQ;

#pragma unroll
    for (int t = 0; t < 16; t++) {
        int id = tid + 256 * t;
        int arr = id >> 10, rem = id & 1023;
        int r = rem >> 3, q = rem & 7;
        const __half* src = (arr == 0) ? Qhi : (arr == 1) ? Qlo : (arr == 2) ? Khi : Klo;
        __half (*dst)[LP] = (arr == 0) ? Qh : (arr == 1) ? Ql : (arr == 2) ? Kh : Kl;
        int rphys;
        if (arr < 2) rphys = m0 + r;
        else {
            int jr = n0 + r;
            rphys = (jr < Mb) ? cb[jr] : 0;
        }
        uint4 v = *(const uint4*)(src + hbase + (size_t)rphys * DM + q * 8);
        *(uint2*)&dst[r][q * 8]     = make_uint2(v.x, v.y);
        *(uint2*)&dst[r][q * 8 + 4] = make_uint2(v.z, v.w);
    }
    __syncthreads();

    const int lane = tid & 31, wid = tid >> 5;
    const int wm = wid >> 2, wn = wid & 3;
    const int grp = lane >> 2, tig = lane & 3;
    const uint32_t qh_b = smem_u32(Qh), ql_b = smem_u32(Ql);
    const uint32_t kh_b = smem_u32(Kh), kl_b = smem_u32(Kl);

    float4 acc[4][4];
#pragma unroll
    for (int i = 0; i < 4; i++)
#pragma unroll
        for (int j = 0; j < 4; j++) acc[i][j] = make_float4(0.f, 0.f, 0.f, 0.f);

#pragma unroll
    for (int ks = 0; ks < 4; ks++) {
        const int kb0 = ks * 16;
        uint32_t ah[4][4], al[4][4];
#pragma unroll
        for (int mt = 0; mt < 4; mt++) {
            lda_x4(ah[mt], qh_b, 144, wm * 64 + mt * 16, kb0, lane);
            lda_x4(al[mt], ql_b, 144, wm * 64 + mt * 16, kb0, lane);
        }
        uint32_t bhf[4][2], blf[4][2];
#pragma unroll
        for (int p = 0; p < 2; p++) {
            ldb_x4(bhf[2 * p], bhf[2 * p + 1], kh_b, 144, wn * 32 + p * 16, kb0, lane);
            ldb_x4(blf[2 * p], blf[2 * p + 1], kl_b, 144, wn * 32 + p * 16, kb0, lane);
        }
#pragma unroll
        for (int mt = 0; mt < 4; mt++)
#pragma unroll
            for (int nt = 0; nt < 4; nt++) {
                mma16816(acc[mt][nt], ah[mt][0], ah[mt][1], ah[mt][2], ah[mt][3],
                         bhf[nt][0], bhf[nt][1]);
                mma16816(acc[mt][nt], ah[mt][0], ah[mt][1], ah[mt][2], ah[mt][3],
                         blf[nt][0], blf[nt][1]);
                mma16816(acc[mt][nt], al[mt][0], al[mt][1], al[mt][2], al[mt][3],
                         bhf[nt][0], bhf[nt][1]);
            }
    }

    float rs0[4], rs1[4];
#pragma unroll
    for (int mt = 0; mt < 4; mt++) { rs0[mt] = 0.f; rs1[mt] = 0.f; }

#pragma unroll
    for (int mt = 0; mt < 4; mt++) {
        int r = m0 + wm * 64 + mt * 16 + grp;
        __half* oh0 = Phi + ((size_t)bh * SEQ + r) * SEQ;
        __half* ol0 = Plo + ((size_t)bh * SEQ + r) * SEQ;
        __half* oh1 = oh0 + (size_t)8 * SEQ;
        __half* ol1 = ol0 + (size_t)8 * SEQ;
#pragma unroll
        for (int nt = 0; nt < 4; nt++) {
            int j = n0 + wn * 32 + nt * 8 + tig * 2;
            bool v0 = (j < Mb), v1 = (j + 1 < Mb);
            float4 a = acc[mt][nt];
            float p0 = v0 ? __expf(a.x * 0.125f) : 0.f;
            float p1 = v1 ? __expf(a.y * 0.125f) : 0.f;
            float p2 = v0 ? __expf(a.z * 0.125f) : 0.f;
            float p3 = v1 ? __expf(a.w * 0.125f) : 0.f;
            *(__half2*)(oh0 + j) = __floats2half2_rn(p0, p1);
            *(__half2*)(ol0 + j) = __floats2half2_rn(residf(p0), residf(p1));
            *(__half2*)(oh1 + j) = __floats2half2_rn(p2, p3);
            *(__half2*)(ol1 + j) = __floats2half2_rn(residf(p2), residf(p3));
            rs0[mt] += p0 + p1;
            rs1[mt] += p2 + p3;
        }
    }
#pragma unroll
    for (int mt = 0; mt < 4; mt++) {
        float s0 = rs0[mt], s1 = rs1[mt];
        s0 += __shfl_xor_sync(0xffffffffu, s0, 1);
        s0 += __shfl_xor_sync(0xffffffffu, s0, 2);
        s1 += __shfl_xor_sync(0xffffffffu, s1, 1);
        s1 += __shfl_xor_sync(0xffffffffu, s1, 2);
        if (tig == 0) {
            int rl = wm * 64 + mt * 16 + grp;
            sums[(size_t)rl * 4 + wn] = s0;
            sums[(size_t)(rl + 8) * 4 + wn] = s1;
        }
    }
    __syncthreads();
    if (tid < 128) {
        float tot = (sums[tid * 4 + 0] + sums[tid * 4 + 1]) +
                    (sums[tid * 4 + 2] + sums[tid * 4 + 3]);
        partial[((size_t)bh * SEQ + m0 + tid) * 16 + blockIdx.x] = tot;
    }
}

__global__ __launch_bounds__(256) void reduce_sums_kernel(
    const float* __restrict__ partial, float* __restrict__ rowsum)
{
    int i = blockIdx.x * 256 + threadIdx.x;
    const float4* p = (const float4*)(partial + (size_t)i * 16);
    float4 a = p[0], b = p[1], c = p[2], d = p[3];
    rowsum[i] = ((a.x + a.y) + (a.z + a.w)) + ((b.x + b.y) + (b.z + b.w)) +
                ((c.x + c.y) + (c.z + c.w)) + ((d.x + d.y) + (d.z + d.w));
}

// ---------------------------------------------------------------------------
// AV over compact K-dim: ctx = (P @ Vc) / rowsum. BM=128, BN=64, BK=64.
// ---------------------------------------------------------------------------
#define AV_SMEM (2 * 128 * LP * 2 + 2 * 64 * LP * 2 + 128 * 4)

__global__ __launch_bounds__(256) void av_kernel(
    const __half* __restrict__ Phi, const __half* __restrict__ Plo,
    const __half* __restrict__ Vthi, const __half* __restrict__ Vtlo,
    const float* __restrict__ rowsum, const int* __restrict__ cnt,
    __half* __restrict__ Chi, __half* __restrict__ Clo)
{
    extern __shared__ char smraw[];
    __half (*Ah)[LP] = (__half(*)[LP])smraw;
    __half (*Al)[LP] = (__half(*)[LP])(smraw + 128 * LP * 2);
    __half (*Vh)[LP] = (__half(*)[LP])(smraw + 2 * 128 * LP * 2);
    __half (*Vl)[LP] = (__half(*)[LP])(smraw + 2 * 128 * LP * 2 + 64 * LP * 2);
    float* sinv = (float*)(smraw + 2 * 128 * LP * 2 + 2 * 64 * LP * 2);

    const int tid = threadIdx.x;
    const int m0 = blockIdx.x * 128;
    const int bh = blockIdx.y, b = bh >> 4, h = bh & 15;
    const int Mb = cnt[b];

    if (tid < 128) sinv[tid] = 1.0f / rowsum[(size_t)bh * SEQ + m0 + tid];
    __syncthreads();

    const int lane = tid & 31, wid = tid >> 5;
    const int wm = wid >> 2, wn = wid & 3;
    const int grp = lane >> 2, tig = lane & 3;
    const uint32_t ah_b = smem_u32(Ah), al_b = smem_u32(Al);
    const uint32_t vh_b = smem_u32(Vh), vl_b = smem_u32(Vl);

    float4 acc[4][2];
#pragma unroll
    for (int i = 0; i < 4; i++)
#pragma unroll
        for (int j = 0; j < 2; j++) acc[i][j] = make_float4(0.f, 0.f, 0.f, 0.f);

    const size_t prow = (size_t)bh * SEQ + m0;
    const size_t vtb = (size_t)bh * DEPTH * SEQ;

    for (int k0 = 0; k0 < Mb; k0 += 64) {
#pragma unroll
        for (int t = 0; t < 8; t++) {
            int id = tid + 256 * t;
            int arr = id >> 10, rem = id & 1023;
            int r = rem >> 3, q = rem & 7;
            const __half* src = arr ? Plo : Phi;
            __half (*dst)[LP] = arr ? Al : Ah;
            uint4 v = *(const uint4*)(src + (prow + r) * SEQ + k0 + q * 8);
            *(uint2*)&dst[r][q * 8]     = make_uint2(v.x, v.y);
            *(uint2*)&dst[r][q * 8 + 4] = make_uint2(v.z, v.w);
        }
#pragma unroll
        for (int t = 0; t < 4; t++) {
            int id = tid + 256 * t;
            int arr = id >> 9, rem = id & 511;
            int r = rem >> 3, q = rem & 7;
            const __half* src = arr ? Vtlo : Vthi;
            __half (*dst)[LP] = arr ? Vl : Vh;
            uint4 v = *(const uint4*)(src + vtb + (size_t)r * SEQ + k0 + q * 8);
            *(uint2*)&dst[r][q * 8]     = make_uint2(v.x, v.y);
            *(uint2*)&dst[r][q * 8 + 4] = make_uint2(v.z, v.w);
        }
        __syncthreads();

#pragma unroll
        for (int ks = 0; ks < 4; ks++) {
            const int kb0 = ks * 16;
            uint32_t ah[4][4], al[4][4];
#pragma unroll
            for (int mt = 0; mt < 4; mt++) {
                lda_x4(ah[mt], ah_b, 144, wm * 64 + mt * 16, kb0, lane);
                lda_x4(al[mt], al_b, 144, wm * 64 + mt * 16, kb0, lane);
            }
            uint32_t bhf[2][2], blf[2][2];
            ldb_x4(bhf[0], bhf[1], vh_b, 144, wn * 16, kb0, lane);
            ldb_x4(blf[0], blf[1], vl_b, 144, wn * 16, kb0, lane);
#pragma unroll
            for (int mt = 0; mt < 4; mt++)
#pragma unroll
                for (int nt = 0; nt < 2; nt++) {
                    mma16816(acc[mt][nt], ah[mt][0], ah[mt][1], ah[mt][2], ah[mt][3],
                             bhf[nt][0], bhf[nt][1]);
                    mma16816(acc[mt][nt], ah[mt][0], ah[mt][1], ah[mt][2], ah[mt][3],
                             blf[nt][0], blf[nt][1]);
                    mma16816(acc[mt][nt], al[mt][0], al[mt][1], al[mt][2], al[mt][3],
                             bhf[nt][0], bhf[nt][1]);
                }
        }
        __syncthreads();
    }

#pragma unroll
    for (int mt = 0; mt < 4; mt++) {
        int rl = wm * 64 + mt * 16 + grp;
        int r = m0 + rl;
        float iv0 = sinv[rl], iv1 = sinv[rl + 8];
#pragma unroll
        for (int nt = 0; nt < 2; nt++) {
            int d = wn * 16 + nt * 8 + tig * 2;
            size_t o = ((size_t)(b * SEQ + r)) * DM + h * 64 + d;
            float x0 = acc[mt][nt].x * iv0, x1 = acc[mt][nt].y * iv0;
            float x2 = acc[mt][nt].z * iv1, x3 = acc[mt][nt].w * iv1;
            *(__half2*)&Chi[o]          = __floats2half2_rn(x0, x1);
            *(__half2*)&Chi[o + 8 * DM] = __floats2half2_rn(x2, x3);
            *(__half2*)&Clo[o]          = __floats2half2_rn(residf(x0), residf(x1));
            *(__half2*)&Clo[o + 8 * DM] = __floats2half2_rn(residf(x2), residf(x3));
        }
    }
}

// ---------------------------------------------------------------------------
// Expand: write final full-width attn = mask ? 0 : (hi+lo)/rowsum. 1 block/row.
// ---------------------------------------------------------------------------
__global__ __launch_bounds__(256) void expand_kernel(
    const __half* __restrict__ Phi, const __half* __restrict__ Plo,
    const float* __restrict__ rowsum, const int* __restrict__ fwd,
    float* __restrict__ attn)
{
    const int row = blockIdx.x;
    const int b = row >> 15;               // NH*SEQ = 32768
    const float inv = 1.0f / rowsum[row];
    const __half* ph = Phi + (size_t)row * SEQ;
    const __half* pl = Plo + (size_t)row * SEQ;
    const int* fw = fwd + b * SEQ;
    float* o = attn + (size_t)row * SEQ;

    const int j0 = threadIdx.x * 8;
    float vals[8];
#pragma unroll
    for (int t = 0; t < 8; t++) {
        int f = fw[j0 + t];
        vals[t] = (f >= 0)
            ? (__half2float(ph[f]) + __half2float(pl[f])) * inv : 0.f;
    }
    *(float4*)(o + j0)     = make_float4(vals[0], vals[1], vals[2], vals[3]);
    *(float4*)(o + j0 + 4) = make_float4(vals[4], vals[5], vals[6], vals[7]);
}

// ---------------------------------------------------------------------------
// Launcher — forked-stream graph: transpose_v ∥ logits, expand ∥ (av, out_gemm)
// ---------------------------------------------------------------------------
extern "C" void kernel_launch(void* const* d_in, const int* in_sizes, int n_in,
                              void* d_out, int out_size)
{
    const float* v    = (const float*)d_in[0];
    const float* k    = (const float*)d_in[1];
    const float* q    = (const float*)d_in[2];
    const int*   mask = (const int*)  d_in[3];
    const float* Wq = (const float*)d_in[4];
    const float* bq = (const float*)d_in[5];
    const float* Wk = (const float*)d_in[6];
    const float* bk = (const float*)d_in[7];
    const float* Wv = (const float*)d_in[8];
    const float* bv = (const float*)d_in[9];
    const float* Wo = (const float*)d_in[10];
    const float* bo = (const float*)d_in[11];
    float* out = (float*)d_out;

    __half *Xhi, *Xlo, *QKVhi, *QKVlo, *Vthi, *Vtlo, *Cxhi, *Cxlo, *WThi, *WTlo;
    __half *Phi, *Plo;
    float *attnScratch, *partialp, *rowsump;
    int *fwdp, *cidxp, *cntp;
    cudaGetSymbolAddress((void**)&Xhi, g_Xhi);
    cudaGetSymbolAddress((void**)&Xlo, g_Xlo);
    cudaGetSymbolAddress((void**)&QKVhi, g_QKVhi);
    cudaGetSymbolAddress((void**)&QKVlo, g_QKVlo);
    cudaGetSymbolAddress((void**)&Vthi, g_Vthi);
    cudaGetSymbolAddress((void**)&Vtlo, g_Vtlo);
    cudaGetSymbolAddress((void**)&Cxhi, g_Cxhi);
    cudaGetSymbolAddress((void**)&Cxlo, g_Cxlo);
    cudaGetSymbolAddress((void**)&WThi, g_WThi);
    cudaGetSymbolAddress((void**)&WTlo, g_WTlo);
    cudaGetSymbolAddress((void**)&Phi, g_Phi);
    cudaGetSymbolAddress((void**)&Plo, g_Plo);
    cudaGetSymbolAddress((void**)&attnScratch, g_attn);
    cudaGetSymbolAddress((void**)&partialp, g_partial);
    cudaGetSymbolAddress((void**)&rowsump, g_rowsum);
    cudaGetSymbolAddress((void**)&fwdp, g_fwd);
    cudaGetSymbolAddress((void**)&cidxp, g_cidx);
    cudaGetSymbolAddress((void**)&cntp, g_cnt);

    cudaFuncSetAttribute(qkv_gemm_kernel,
                         cudaFuncAttributeMaxDynamicSharedMemorySize, GEMM_SMEM);
    cudaFuncSetAttribute(out_gemm_kernel,
                         cudaFuncAttributeMaxDynamicSharedMemorySize, GEMM_SMEM);
    cudaFuncSetAttribute(logits_kernel,
                         cudaFuncAttributeMaxDynamicSharedMemorySize, LOGITS_SMEM);
    cudaFuncSetAttribute(av_kernel,
                         cudaFuncAttributeMaxDynamicSharedMemorySize, AV_SMEM);

    const size_t FINAL_ELEMS = (size_t)BS_ROWS * DM;
    const size_t ATTN_ELEMS  = (size_t)BH * SEQ * SEQ;
    const size_t asz = (size_t)BS_ROWS * DM;
    float* attnp = ((size_t)out_size >= FINAL_ELEMS + ATTN_ELEMS)
                       ? (out + FINAL_ELEMS) : attnScratch;

    // Fork machinery (created per call, never destroyed; no device allocs).
    cudaStream_t s2 = 0;
    bool forked = (cudaStreamCreateWithFlags(&s2, cudaStreamNonBlocking) == cudaSuccess);
    cudaEvent_t eFork = 0, eW = 0, eQkv = 0, eVt = 0, eRs = 0, eJoin = 0;
    if (forked) {
        forked = (cudaEventCreateWithFlags(&eFork, cudaEventDisableTiming) == cudaSuccess) &&
                 (cudaEventCreateWithFlags(&eW,    cudaEventDisableTiming) == cudaSuccess) &&
                 (cudaEventCreateWithFlags(&eQkv,  cudaEventDisableTiming) == cudaSuccess) &&
                 (cudaEventCreateWithFlags(&eVt,   cudaEventDisableTiming) == cudaSuccess) &&
                 (cudaEventCreateWithFlags(&eRs,   cudaEventDisableTiming) == cudaSuccess) &&
                 (cudaEventCreateWithFlags(&eJoin, cudaEventDisableTiming) == cudaSuccess);
    }

    if (forked) {
        // Pull s2 into the capture graph.
        cudaEventRecord(eFork, 0);
        cudaStreamWaitEvent(s2, eFork, 0);

        // s2: mask scan + weight transpose ; 0: input split (independent).
        mask_scan_kernel<<<BATCH, 1024, 0, s2>>>(mask, fwdp, cidxp, cntp);
        transpose_split_kernel<<<dim3(32, 32, 4), 256, 0, s2>>>(Wq, Wk, Wv, Wo, WThi, WTlo);
        cudaEventRecord(eW, s2);
        split_inputs_kernel<<<dim3(4096, 3), 256>>>(q, k, v, Xhi, Xlo);

        // 0: qkv (needs X + WT + [logits later needs cidx] -> wait eW).
        cudaStreamWaitEvent(0, eW, 0);
        qkv_gemm_kernel<<<dim3(8, 32, 3), 256, GEMM_SMEM>>>(
            Xhi, Xlo, WThi, WTlo, bq, bk, bv, QKVhi, QKVlo);
        cudaEventRecord(eQkv, 0);

        // s2: V transpose (needs qkv z=2 + fwd), concurrent with logits on 0.
        cudaStreamWaitEvent(s2, eQkv, 0);
        transpose_v_kernel<<<dim3(32, 128), 256, 0, s2>>>(
            QKVhi + 2 * asz, QKVlo + 2 * asz, fwdp, Vthi, Vtlo);
        cudaEventRecord(eVt, s2);

        logits_kernel<<<dim3(16, 16, BH), 256, LOGITS_SMEM>>>(
            QKVhi, QKVlo, QKVhi + asz, QKVlo + asz, cidxp, cntp, Phi, Plo, partialp);
        reduce_sums_kernel<<<(BH * SEQ) / 256, 256>>>(partialp, rowsump);
        cudaEventRecord(eRs, 0);

        // s2: expand (needs Phi/Plo + rowsum + fwd), concurrent with av+out on 0.
        cudaStreamWaitEvent(s2, eRs, 0);
        expand_kernel<<<BH * SEQ, 256, 0, s2>>>(Phi, Plo, rowsump, fwdp, attnp);
        cudaEventRecord(eJoin, s2);

        cudaStreamWaitEvent(0, eVt, 0);
        av_kernel<<<dim3(16, BH), 256, AV_SMEM>>>(
            Phi, Plo, Vthi, Vtlo, rowsump, cntp, Cxhi, Cxlo);
        out_gemm_kernel<<<dim3(8, 32), 256, GEMM_SMEM>>>(
            Cxhi, Cxlo, WThi, WTlo, bo, out);

        // Join s2 back into 0 before returning.
        cudaStreamWaitEvent(0, eJoin, 0);
    } else {
        // Sequential fallback (identical work).
        mask_scan_kernel<<<BATCH, 1024>>>(mask, fwdp, cidxp, cntp);
        split_inputs_kernel<<<dim3(4096, 3), 256>>>(q, k, v, Xhi, Xlo);
        transpose_split_kernel<<<dim3(32, 32, 4), 256>>>(Wq, Wk, Wv, Wo, WThi, WTlo);
        qkv_gemm_kernel<<<dim3(8, 32, 3), 256, GEMM_SMEM>>>(
            Xhi, Xlo, WThi, WTlo, bq, bk, bv, QKVhi, QKVlo);
        transpose_v_kernel<<<dim3(32, 128), 256>>>(
            QKVhi + 2 * asz, QKVlo + 2 * asz, fwdp, Vthi, Vtlo);
        logits_kernel<<<dim3(16, 16, BH), 256, LOGITS_SMEM>>>(
            QKVhi, QKVlo, QKVhi + asz, QKVlo + asz, cidxp, cntp, Phi, Plo, partialp);
        reduce_sums_kernel<<<(BH * SEQ) / 256, 256>>>(partialp, rowsump);
        av_kernel<<<dim3(16, BH), 256, AV_SMEM>>>(
            Phi, Plo, Vthi, Vtlo, rowsump, cntp, Cxhi, Cxlo);
        expand_kernel<<<BH * SEQ, 256>>>(Phi, Plo, rowsump, fwdp, attnp);
        out_gemm_kernel<<<dim3(8, 32), 256, GEMM_SMEM>>>(
            Cxhi, Cxlo, WThi, WTlo, bo, out);
    }
}

// round 13
// speedup vs baseline: 1.0362x; 1.0059x over previous
#include <cuda_runtime.h>
#include <cuda_fp16.h>
#include <math.h>
#include <stdint.h>
#include <stddef.h>

#define DM 1024
#define NH 16
#define DEPTH 64
#define BATCH 2
#define SEQ 2048
#define BS_ROWS 4096
#define BH 32

// ---------------------------------------------------------------------------
// Scratch (__device__ globals; allocation-free rule). Zero-initialized.
// ---------------------------------------------------------------------------
__device__ __half g_Xhi[3][(size_t)BS_ROWS * DM];
__device__ __half g_Xlo[3][(size_t)BS_ROWS * DM];
__device__ __half g_QKVhi[3][(size_t)BS_ROWS * DM];
__device__ __half g_QKVlo[3][(size_t)BS_ROWS * DM];
__device__ __half g_Vthi[(size_t)BH * DEPTH * SEQ];   // [bh][d][compact s]
__device__ __half g_Vtlo[(size_t)BH * DEPTH * SEQ];
__device__ __half g_Cxhi[(size_t)BS_ROWS * DM];
__device__ __half g_Cxlo[(size_t)BS_ROWS * DM];
__device__ __half g_WThi[4][(size_t)DM * DM];
__device__ __half g_WTlo[4][(size_t)DM * DM];
__device__ __half g_Phi[(size_t)BH * SEQ * SEQ];      // exp(p) hi, compact cols
__device__ __half g_Plo[(size_t)BH * SEQ * SEQ];      // exp(p) lo residual
__device__ float  g_attn[(size_t)BH * SEQ * SEQ];     // fallback full attn
__device__ float  g_partial[(size_t)BH * SEQ * 16];
__device__ float  g_rowsum[(size_t)BH * SEQ];
__device__ int    g_fwd[BATCH * SEQ];
__device__ int    g_cidx[BATCH * SEQ];
__device__ int    g_cnt[BATCH];

// ---------------------------------------------------------------------------
// Helpers
// ---------------------------------------------------------------------------
__device__ __forceinline__ float residf(float x) {
    return x - __half2float(__float2half_rn(x));
}
__device__ __forceinline__ uint32_t smem_u32(const void* p) {
    return (uint32_t)__cvta_generic_to_shared(p);
}
#define CP16(dst_u32, src_ptr) \
    asm volatile("cp.async.cg.shared.global [%0], [%1], 16;\n" :: "r"(dst_u32), "l"(src_ptr))
#define CP_COMMIT asm volatile("cp.async.commit_group;\n" ::: "memory")
#define CP_WAIT0  asm volatile("cp.async.wait_group 0;\n" ::: "memory")

__device__ __forceinline__ void mma16816(float4& d,
    uint32_t a0, uint32_t a1, uint32_t a2, uint32_t a3,
    uint32_t b0, uint32_t b1)
{
    asm volatile(
        "mma.sync.aligned.m16n8k16.row.col.f32.f16.f16.f32 "
        "{%0,%1,%2,%3},{%4,%5,%6,%7},{%8,%9},{%0,%1,%2,%3};\n"
        : "+f"(d.x), "+f"(d.y), "+f"(d.z), "+f"(d.w)
        : "r"(a0), "r"(a1), "r"(a2), "r"(a3), "r"(b0), "r"(b1));
}

__device__ __forceinline__ void ldsm4(uint32_t& r0, uint32_t& r1,
                                      uint32_t& r2, uint32_t& r3, uint32_t addr)
{
    asm volatile("ldmatrix.sync.aligned.m8n8.x4.shared.b16 {%0,%1,%2,%3}, [%4];\n"
                 : "=r"(r0), "=r"(r1), "=r"(r2), "=r"(r3) : "r"(addr));
}

__device__ __forceinline__ void lda_x4(uint32_t* f, uint32_t sbase, int lp_bytes,
                                       int rbase, int kb0, int lane)
{
    int seg = lane >> 3, rw = lane & 7;
    int row = rbase + rw + ((seg & 1) << 3);
    int col = kb0 + ((seg >> 1) << 3);
    ldsm4(f[0], f[1], f[2], f[3], sbase + row * lp_bytes + col * 2);
}
__device__ __forceinline__ void ldb_x4(uint32_t* f0, uint32_t* f1, uint32_t sbase,
                                       int lp_bytes, int cbase, int kb0, int lane)
{
    int seg = lane >> 3, rw = lane & 7;
    int row = cbase + rw + ((seg >> 1) << 3);
    int col = kb0 + ((seg & 1) << 3);
    ldsm4(f0[0], f0[1], f1[0], f1[1], sbase + row * lp_bytes + col * 2);
}

// ---------------------------------------------------------------------------
// Mask scan: per batch, prefix-compact unmasked columns. 1 block/batch.
// ---------------------------------------------------------------------------
__global__ __launch_bounds__(1024) void mask_scan_kernel(
    const int* __restrict__ mask, int* __restrict__ fwd,
    int* __restrict__ cidx, int* __restrict__ cnt)
{
    __shared__ int sa[1024], sb[1024];
    const int b = blockIdx.x, t = threadIdx.x;
    const int j0 = 2 * t, j1 = 2 * t + 1;
    const int m0 = (mask[b * SEQ + j0] == 0);
    const int m1 = (mask[b * SEQ + j1] == 0);
    sa[t] = m0 + m1;
    __syncthreads();
    int* src = sa; int* dst = sb;
    for (int off = 1; off < 1024; off <<= 1) {
        int v = src[t] + ((t >= off) ? src[t - off] : 0);
        dst[t] = v;
        __syncthreads();
        int* tmp = src; src = dst; dst = tmp;
    }
    const int incl = src[t];
    const int excl = incl - (m0 + m1);
    fwd[b * SEQ + j0] = m0 ? excl : -1;
    fwd[b * SEQ + j1] = m1 ? (excl + m0) : -1;
    if (m0) cidx[b * SEQ + excl] = j0;
    if (m1) cidx[b * SEQ + excl + m0] = j1;
    const int total = src[1023];
    if (t == 0) cnt[b] = total;
    __syncthreads();
    for (int s = t; s < SEQ; s += 1024)
        if (s >= total) cidx[b * SEQ + s] = 0;
}

// ---------------------------------------------------------------------------
// Elementwise split of q/k/v inputs
// ---------------------------------------------------------------------------
__global__ __launch_bounds__(256) void split_inputs_kernel(
    const float* __restrict__ q, const float* __restrict__ k,
    const float* __restrict__ v, __half* __restrict__ Xhi, __half* __restrict__ Xlo)
{
    const int z = blockIdx.y;
    const float* src = (z == 0) ? q : (z == 1) ? k : v;
    const size_t i = ((size_t)blockIdx.x * 256 + threadIdx.x) * 4;
    const size_t o = (size_t)z * BS_ROWS * DM + i;
    float4 x = *(const float4*)(src + i);
    *(__half2*)(Xhi + o)     = __floats2half2_rn(x.x, x.y);
    *(__half2*)(Xhi + o + 2) = __floats2half2_rn(x.z, x.w);
    *(__half2*)(Xlo + o)     = __floats2half2_rn(residf(x.x), residf(x.y));
    *(__half2*)(Xlo + o + 2) = __floats2half2_rn(residf(x.z), residf(x.w));
}

// ---------------------------------------------------------------------------
// Weight transpose+split
// ---------------------------------------------------------------------------
__global__ __launch_bounds__(256) void transpose_split_kernel(
    const float* __restrict__ Wq, const float* __restrict__ Wk,
    const float* __restrict__ Wv, const float* __restrict__ Wo,
    __half* __restrict__ ThiB, __half* __restrict__ TloB)
{
    const int z = blockIdx.z;
    const float* W = (z == 0) ? Wq : (z == 1) ? Wk : (z == 2) ? Wv : Wo;
    __half* Thi = ThiB + (size_t)z * DM * DM;
    __half* Tlo = TloB + (size_t)z * DM * DM;

    __shared__ float tile[32][33];
    const int k0 = blockIdx.y * 32, n0 = blockIdx.x * 32;
    const int tx = threadIdx.x & 31, ty = threadIdx.x >> 5;
#pragma unroll
    for (int i = 0; i < 4; i++) {
        int kk = ty + i * 8;
        tile[kk][tx] = W[(size_t)(k0 + kk) * DM + n0 + tx];
    }
    __syncthreads();
#pragma unroll
    for (int i = 0; i < 4; i++) {
        int nn = ty + i * 8;
        float x = tile[tx][nn];
        __half hi = __float2half_rn(x);
        Thi[(size_t)(n0 + nn) * DM + k0 + tx] = hi;
        Tlo[(size_t)(n0 + nn) * DM + k0 + tx] = __float2half_rn(x - __half2float(hi));
    }
}

// ---------------------------------------------------------------------------
// V transpose with compaction: V [4096][1024] -> Vt [bh][64][compact s]
// ---------------------------------------------------------------------------
__global__ __launch_bounds__(256) void transpose_v_kernel(
    const __half* __restrict__ Vhi, const __half* __restrict__ Vlo,
    const int* __restrict__ fwd,
    __half* __restrict__ Thi, __half* __restrict__ Tlo)
{
    __shared__ __half thi[32][33], tlo[32][33];
    const int n0 = blockIdx.x * 32;
    const int s0 = blockIdx.y * 32;
    const int tx = threadIdx.x & 31, ty = threadIdx.x >> 5;
#pragma unroll
    for (int i = 0; i < 4; i++) {
        int r = ty + i * 8;
        thi[r][tx] = Vhi[(size_t)(s0 + r) * DM + n0 + tx];
        tlo[r][tx] = Vlo[(size_t)(s0 + r) * DM + n0 + tx];
    }
    __syncthreads();
    const int b = s0 >> 11;
    const int slot = fwd[b * SEQ + (s0 & 2047) + tx];
    if (slot >= 0) {
#pragma unroll
        for (int i = 0; i < 4; i++) {
            int nn = ty + i * 8;
            int gn = n0 + nn;
            int h = gn >> 6, d = gn & 63;
            size_t orow = ((size_t)(b * NH + h) * DEPTH + d) * SEQ + slot;
            Thi[orow] = thi[tx][nn];
            Tlo[orow] = tlo[tx][nn];
        }
    }
}

// ---------------------------------------------------------------------------
// Double-buffered split-fp16 GEMM (projections). BM=BN=128, BK=32.
// Single barrier per k-iteration: wait -> sync -> issue next loads -> compute.
// ---------------------------------------------------------------------------
#define GSTAGE 40960
#define GEMM_SMEM (2 * GSTAGE)

__device__ __forceinline__ void gemm_load_stage(uint32_t smbase, int s,
    const __half* AhiG, const __half* AloG,
    const __half* BhiG, const __half* BloG,
    int m0, int n0, int k0, int tid)
{
    uint32_t sb = smbase + s * GSTAGE;
#pragma unroll
    for (int t = 0; t < 2; t++) {
        int id = tid * 2 + t;
        int r = id >> 2, q = id & 3;
        uint32_t off = r * 80 + q * 16;
        const size_t ga = (size_t)(m0 + r) * DM + k0 + q * 8;
        const size_t gb = (size_t)(n0 + r) * DM + k0 + q * 8;
        CP16(sb + off,         AhiG + ga);
        CP16(sb + 10240 + off, AloG + ga);
        CP16(sb + 20480 + off, BhiG + gb);
        CP16(sb + 30720 + off, BloG + gb);
    }
}

template<bool OUT_F32>
__device__ __forceinline__ void gemm_core(
    const __half* __restrict__ AhiG, const __half* __restrict__ AloG,
    const __half* __restrict__ BhiG, const __half* __restrict__ BloG,
    const float* __restrict__ bias,
    float* __restrict__ Cf, __half* __restrict__ Chi, __half* __restrict__ Clo)
{
    extern __shared__ char dsm[];
    const uint32_t smbase = smem_u32(dsm);

    const int tid = threadIdx.x;
    const int m0 = blockIdx.y * 128, n0 = blockIdx.x * 128;
    const int lane = tid & 31, wid = tid >> 5;
    const int wm = wid >> 2, wn = wid & 3;
    const int grp = lane >> 2, tig = lane & 3;

    float4 acc[4][4];
#pragma unroll
    for (int i = 0; i < 4; i++)
#pragma unroll
        for (int j = 0; j < 4; j++) acc[i][j] = make_float4(0.f, 0.f, 0.f, 0.f);

    gemm_load_stage(smbase, 0, AhiG, AloG, BhiG, BloG, m0, n0, 0, tid);
    CP_COMMIT;

    for (int kt = 0; kt < 32; kt++) {
        // S_kt loads complete for this thread; barrier makes them visible to
        // all warps AND guarantees everyone finished computing iteration kt-1
        // (so the other buffer is free to overwrite below).
        CP_WAIT0;
        __syncthreads();
        if (kt + 1 < 32) {
            gemm_load_stage(smbase, (kt + 1) & 1, AhiG, AloG, BhiG, BloG,
                            m0, n0, (kt + 1) * 32, tid);
            CP_COMMIT;
        }

        const uint32_t sb = smbase + (kt & 1) * GSTAGE;
        const uint32_t ah_b = sb, al_b = sb + 10240, bh_b = sb + 20480, bl_b = sb + 30720;
#pragma unroll
        for (int ks = 0; ks < 2; ks++) {
            const int kb0 = ks * 16;
            uint32_t ah[4][4], al[4][4];
#pragma unroll
            for (int mt = 0; mt < 4; mt++) {
                lda_x4(ah[mt], ah_b, 80, wm * 64 + mt * 16, kb0, lane);
                lda_x4(al[mt], al_b, 80, wm * 64 + mt * 16, kb0, lane);
            }
            uint32_t bhf[4][2], blf[4][2];
#pragma unroll
            for (int p = 0; p < 2; p++) {
                ldb_x4(bhf[2 * p], bhf[2 * p + 1], bh_b, 80, wn * 32 + p * 16, kb0, lane);
                ldb_x4(blf[2 * p], blf[2 * p + 1], bl_b, 80, wn * 32 + p * 16, kb0, lane);
            }
#pragma unroll
            for (int mt = 0; mt < 4; mt++)
#pragma unroll
                for (int nt = 0; nt < 4; nt++) {
                    mma16816(acc[mt][nt], ah[mt][0], ah[mt][1], ah[mt][2], ah[mt][3],
                             bhf[nt][0], bhf[nt][1]);
                    mma16816(acc[mt][nt], ah[mt][0], ah[mt][1], ah[mt][2], ah[mt][3],
                             blf[nt][0], blf[nt][1]);
                    mma16816(acc[mt][nt], al[mt][0], al[mt][1], al[mt][2], al[mt][3],
                             bhf[nt][0], bhf[nt][1]);
                }
        }
        // no trailing barrier: next iteration's leading barrier protects reuse
    }

#pragma unroll
    for (int mt = 0; mt < 4; mt++) {
        int r = m0 + wm * 64 + mt * 16 + grp;
#pragma unroll
        for (int nt = 0; nt < 4; nt++) {
            int c = n0 + wn * 32 + nt * 8 + tig * 2;
            float bx = bias[c], by = bias[c + 1];
            float x0 = acc[mt][nt].x + bx, x1 = acc[mt][nt].y + by;
            float x2 = acc[mt][nt].z + bx, x3 = acc[mt][nt].w + by;
            if (OUT_F32) {
                *(float2*)&Cf[(size_t)r * DM + c]       = make_float2(x0, x1);
                *(float2*)&Cf[(size_t)(r + 8) * DM + c] = make_float2(x2, x3);
            } else {
                *(__half2*)&Chi[(size_t)r * DM + c]       = __floats2half2_rn(x0, x1);
                *(__half2*)&Chi[(size_t)(r + 8) * DM + c] = __floats2half2_rn(x2, x3);
                *(__half2*)&Clo[(size_t)r * DM + c]       = __floats2half2_rn(residf(x0), residf(x1));
                *(__half2*)&Clo[(size_t)(r + 8) * DM + c] = __floats2half2_rn(residf(x2), residf(x3));
            }
        }
    }
}

__global__ __launch_bounds__(256) void qkv_gemm_kernel(
    const __half* __restrict__ Xhi, const __half* __restrict__ Xlo,
    const __half* __restrict__ WThi, const __half* __restrict__ WTlo,
    const float* __restrict__ bq, const float* __restrict__ bk,
    const float* __restrict__ bv,
    __half* __restrict__ QKVhi, __half* __restrict__ QKVlo)
{
    const int z = blockIdx.z;
    const size_t asz = (size_t)BS_ROWS * DM, wsz = (size_t)DM * DM;
    const float* bias = (z == 0) ? bq : (z == 1) ? bk : bv;
    gemm_core<false>(Xhi + z * asz, Xlo + z * asz, WThi + z * wsz, WTlo + z * wsz,
                     bias, nullptr, QKVhi + z * asz, QKVlo + z * asz);
}

__global__ __launch_bounds__(256) void out_gemm_kernel(
    const __half* __restrict__ Cxhi, const __half* __restrict__ Cxlo,
    const __half* __restrict__ WThi, const __half* __restrict__ WTlo,
    const float* __restrict__ bo, float* __restrict__ out)
{
    const size_t wsz = (size_t)DM * DM;
    gemm_core<true>(Cxhi, Cxlo, WThi + 3 * wsz, WTlo + 3 * wsz, bo,
                    out, nullptr, nullptr);
}

// ---------------------------------------------------------------------------
// Logits over COMPACT columns: p = exp(0.125*QK) for unmasked cols only.
// ---------------------------------------------------------------------------
#define LP 72
#define LOGITS_SMEM (4 * 128 * LP * 2 + 128 * 4 * 4)

__global__ __launch_bounds__(256) void logits_kernel(
    const __half* __restrict__ Qhi, const __half* __restrict__ Qlo,
    const __half* __restrict__ Khi, const __half* __restrict__ Klo,
    const int* __restrict__ cidx, const int* __restrict__ cnt,
    __half* __restrict__ Phi, __half* __restrict__ Plo,
    float* __restrict__ partial)
{
    extern __shared__ __half sm[];
    __half (*Qh)[LP] = (__half(*)[LP])sm;
    __half (*Ql)[LP] = (__half(*)[LP])(sm + 128 * LP);
    __half (*Kh)[LP] = (__half(*)[LP])(sm + 2 * 128 * LP);
    __half (*Kl)[LP] = (__half(*)[LP])(sm + 3 * 128 * LP);
    float* sums = (float*)(sm + 4 * 128 * LP);

    const int tid = threadIdx.x;
    const int n0 = blockIdx.x * 128, m0 = blockIdx.y * 128;
    const int bh = blockIdx.z, b = bh >> 4, h = bh & 15;
    const int Mb = cnt[b];

    if (n0 >= Mb) {
        if (tid < 128)
            partial[((size_t)bh * SEQ + m0 + tid) * 16 + blockIdx.x] = 0.f;
        return;
    }

    const size_t hbase = (size_t)b * SEQ * DM + h * 64;
    const int* cb = cidx + b * SEQ;

#pragma unroll
    for (int t = 0; t < 16; t++) {
        int id = tid + 256 * t;
        int arr = id >> 10, rem = id & 1023;
        int r = rem >> 3, q = rem & 7;
        const __half* src = (arr == 0) ? Qhi : (arr == 1) ? Qlo : (arr == 2) ? Khi : Klo;
        __half (*dst)[LP] = (arr == 0) ? Qh : (arr == 1) ? Ql : (arr == 2) ? Kh : Kl;
        int rphys;
        if (arr < 2) rphys = m0 + r;
        else {
            int jr = n0 + r;
            rphys = (jr < Mb) ? cb[jr] : 0;
        }
        uint4 v = *(const uint4*)(src + hbase + (size_t)rphys * DM + q * 8);
        *(uint2*)&dst[r][q * 8]     = make_uint2(v.x, v.y);
        *(uint2*)&dst[r][q * 8 + 4] = make_uint2(v.z, v.w);
    }
    __syncthreads();

    const int lane = tid & 31, wid = tid >> 5;
    const int wm = wid >> 2, wn = wid & 3;
    const int grp = lane >> 2, tig = lane & 3;
    const uint32_t qh_b = smem_u32(Qh), ql_b = smem_u32(Ql);
    const uint32_t kh_b = smem_u32(Kh), kl_b = smem_u32(Kl);

    float4 acc[4][4];
#pragma unroll
    for (int i = 0; i < 4; i++)
#pragma unroll
        for (int j = 0; j < 4; j++) acc[i][j] = make_float4(0.f, 0.f, 0.f, 0.f);

#pragma unroll
    for (int ks = 0; ks < 4; ks++) {
        const int kb0 = ks * 16;
        uint32_t ah[4][4], al[4][4];
#pragma unroll
        for (int mt = 0; mt < 4; mt++) {
            lda_x4(ah[mt], qh_b, 144, wm * 64 + mt * 16, kb0, lane);
            lda_x4(al[mt], ql_b, 144, wm * 64 + mt * 16, kb0, lane);
        }
        uint32_t bhf[4][2], blf[4][2];
#pragma unroll
        for (int p = 0; p < 2; p++) {
            ldb_x4(bhf[2 * p], bhf[2 * p + 1], kh_b, 144, wn * 32 + p * 16, kb0, lane);
            ldb_x4(blf[2 * p], blf[2 * p + 1], kl_b, 144, wn * 32 + p * 16, kb0, lane);
        }
#pragma unroll
        for (int mt = 0; mt < 4; mt++)
#pragma unroll
            for (int nt = 0; nt < 4; nt++) {
                mma16816(acc[mt][nt], ah[mt][0], ah[mt][1], ah[mt][2], ah[mt][3],
                         bhf[nt][0], bhf[nt][1]);
                mma16816(acc[mt][nt], ah[mt][0], ah[mt][1], ah[mt][2], ah[mt][3],
                         blf[nt][0], blf[nt][1]);
                mma16816(acc[mt][nt], al[mt][0], al[mt][1], al[mt][2], al[mt][3],
                         bhf[nt][0], bhf[nt][1]);
            }
    }

    float rs0[4], rs1[4];
#pragma unroll
    for (int mt = 0; mt < 4; mt++) { rs0[mt] = 0.f; rs1[mt] = 0.f; }

#pragma unroll
    for (int mt = 0; mt < 4; mt++) {
        int r = m0 + wm * 64 + mt * 16 + grp;
        __half* oh0 = Phi + ((size_t)bh * SEQ + r) * SEQ;
        __half* ol0 = Plo + ((size_t)bh * SEQ + r) * SEQ;
        __half* oh1 = oh0 + (size_t)8 * SEQ;
        __half* ol1 = ol0 + (size_t)8 * SEQ;
#pragma unroll
        for (int nt = 0; nt < 4; nt++) {
            int j = n0 + wn * 32 + nt * 8 + tig * 2;
            bool v0 = (j < Mb), v1 = (j + 1 < Mb);
            float4 a = acc[mt][nt];
            float p0 = v0 ? __expf(a.x * 0.125f) : 0.f;
            float p1 = v1 ? __expf(a.y * 0.125f) : 0.f;
            float p2 = v0 ? __expf(a.z * 0.125f) : 0.f;
            float p3 = v1 ? __expf(a.w * 0.125f) : 0.f;
            *(__half2*)(oh0 + j) = __floats2half2_rn(p0, p1);
            *(__half2*)(ol0 + j) = __floats2half2_rn(residf(p0), residf(p1));
            *(__half2*)(oh1 + j) = __floats2half2_rn(p2, p3);
            *(__half2*)(ol1 + j) = __floats2half2_rn(residf(p2), residf(p3));
            rs0[mt] += p0 + p1;
            rs1[mt] += p2 + p3;
        }
    }
#pragma unroll
    for (int mt = 0; mt < 4; mt++) {
        float s0 = rs0[mt], s1 = rs1[mt];
        s0 += __shfl_xor_sync(0xffffffffu, s0, 1);
        s0 += __shfl_xor_sync(0xffffffffu, s0, 2);
        s1 += __shfl_xor_sync(0xffffffffu, s1, 1);
        s1 += __shfl_xor_sync(0xffffffffu, s1, 2);
        if (tig == 0) {
            int rl = wm * 64 + mt * 16 + grp;
            sums[(size_t)rl * 4 + wn] = s0;
            sums[(size_t)(rl + 8) * 4 + wn] = s1;
        }
    }
    __syncthreads();
    if (tid < 128) {
        float tot = (sums[tid * 4 + 0] + sums[tid * 4 + 1]) +
                    (sums[tid * 4 + 2] + sums[tid * 4 + 3]);
        partial[((size_t)bh * SEQ + m0 + tid) * 16 + blockIdx.x] = tot;
    }
}

__global__ __launch_bounds__(256) void reduce_sums_kernel(
    const float* __restrict__ partial, float* __restrict__ rowsum)
{
    int i = blockIdx.x * 256 + threadIdx.x;
    const float4* p = (const float4*)(partial + (size_t)i * 16);
    float4 a = p[0], b = p[1], c = p[2], d = p[3];
    rowsum[i] = ((a.x + a.y) + (a.z + a.w)) + ((b.x + b.y) + (b.z + b.w)) +
                ((c.x + c.y) + (c.z + c.w)) + ((d.x + d.y) + (d.z + d.w));
}

// ---------------------------------------------------------------------------
// AV over compact K-dim: ctx = (P @ Vc) / rowsum. BM=128, BN=64, BK=64.
// ---------------------------------------------------------------------------
#define AV_SMEM (2 * 128 * LP * 2 + 2 * 64 * LP * 2 + 128 * 4)

__global__ __launch_bounds__(256) void av_kernel(
    const __half* __restrict__ Phi, const __half* __restrict__ Plo,
    const __half* __restrict__ Vthi, const __half* __restrict__ Vtlo,
    const float* __restrict__ rowsum, const int* __restrict__ cnt,
    __half* __restrict__ Chi, __half* __restrict__ Clo)
{
    extern __shared__ char smraw[];
    __half (*Ah)[LP] = (__half(*)[LP])smraw;
    __half (*Al)[LP] = (__half(*)[LP])(smraw + 128 * LP * 2);
    __half (*Vh)[LP] = (__half(*)[LP])(smraw + 2 * 128 * LP * 2);
    __half (*Vl)[LP] = (__half(*)[LP])(smraw + 2 * 128 * LP * 2 + 64 * LP * 2);
    float* sinv = (float*)(smraw + 2 * 128 * LP * 2 + 2 * 64 * LP * 2);

    const int tid = threadIdx.x;
    const int m0 = blockIdx.x * 128;
    const int bh = blockIdx.y, b = bh >> 4, h = bh & 15;
    const int Mb = cnt[b];

    if (tid < 128) sinv[tid] = 1.0f / rowsum[(size_t)bh * SEQ + m0 + tid];
    __syncthreads();

    const int lane = tid & 31, wid = tid >> 5;
    const int wm = wid >> 2, wn = wid & 3;
    const int grp = lane >> 2, tig = lane & 3;
    const uint32_t ah_b = smem_u32(Ah), al_b = smem_u32(Al);
    const uint32_t vh_b = smem_u32(Vh), vl_b = smem_u32(Vl);

    float4 acc[4][2];
#pragma unroll
    for (int i = 0; i < 4; i++)
#pragma unroll
        for (int j = 0; j < 2; j++) acc[i][j] = make_float4(0.f, 0.f, 0.f, 0.f);

    const size_t prow = (size_t)bh * SEQ + m0;
    const size_t vtb = (size_t)bh * DEPTH * SEQ;

    for (int k0 = 0; k0 < Mb; k0 += 64) {
#pragma unroll
        for (int t = 0; t < 8; t++) {
            int id = tid + 256 * t;
            int arr = id >> 10, rem = id & 1023;
            int r = rem >> 3, q = rem & 7;
            const __half* src = arr ? Plo : Phi;
            __half (*dst)[LP] = arr ? Al : Ah;
            uint4 v = *(const uint4*)(src + (prow + r) * SEQ + k0 + q * 8);
            *(uint2*)&dst[r][q * 8]     = make_uint2(v.x, v.y);
            *(uint2*)&dst[r][q * 8 + 4] = make_uint2(v.z, v.w);
        }
#pragma unroll
        for (int t = 0; t < 4; t++) {
            int id = tid + 256 * t;
            int arr = id >> 9, rem = id & 511;
            int r = rem >> 3, q = rem & 7;
            const __half* src = arr ? Vtlo : Vthi;
            __half (*dst)[LP] = arr ? Vl : Vh;
            uint4 v = *(const uint4*)(src + vtb + (size_t)r * SEQ + k0 + q * 8);
            *(uint2*)&dst[r][q * 8]     = make_uint2(v.x, v.y);
            *(uint2*)&dst[r][q * 8 + 4] = make_uint2(v.z, v.w);
        }
        __syncthreads();

#pragma unroll
        for (int ks = 0; ks < 4; ks++) {
            const int kb0 = ks * 16;
            uint32_t ah[4][4], al[4][4];
#pragma unroll
            for (int mt = 0; mt < 4; mt++) {
                lda_x4(ah[mt], ah_b, 144, wm * 64 + mt * 16, kb0, lane);
                lda_x4(al[mt], al_b, 144, wm * 64 + mt * 16, kb0, lane);
            }
            uint32_t bhf[2][2], blf[2][2];
            ldb_x4(bhf[0], bhf[1], vh_b, 144, wn * 16, kb0, lane);
            ldb_x4(blf[0], blf[1], vl_b, 144, wn * 16, kb0, lane);
#pragma unroll
            for (int mt = 0; mt < 4; mt++)
#pragma unroll
                for (int nt = 0; nt < 2; nt++) {
                    mma16816(acc[mt][nt], ah[mt][0], ah[mt][1], ah[mt][2], ah[mt][3],
                             bhf[nt][0], bhf[nt][1]);
                    mma16816(acc[mt][nt], ah[mt][0], ah[mt][1], ah[mt][2], ah[mt][3],
                             blf[nt][0], blf[nt][1]);
                    mma16816(acc[mt][nt], al[mt][0], al[mt][1], al[mt][2], al[mt][3],
                             bhf[nt][0], bhf[nt][1]);
                }
        }
        __syncthreads();
    }

#pragma unroll
    for (int mt = 0; mt < 4; mt++) {
        int rl = wm * 64 + mt * 16 + grp;
        int r = m0 + rl;
        float iv0 = sinv[rl], iv1 = sinv[rl + 8];
#pragma unroll
        for (int nt = 0; nt < 2; nt++) {
            int d = wn * 16 + nt * 8 + tig * 2;
            size_t o = ((size_t)(b * SEQ + r)) * DM + h * 64 + d;
            float x0 = acc[mt][nt].x * iv0, x1 = acc[mt][nt].y * iv0;
            float x2 = acc[mt][nt].z * iv1, x3 = acc[mt][nt].w * iv1;
            *(__half2*)&Chi[o]          = __floats2half2_rn(x0, x1);
            *(__half2*)&Chi[o + 8 * DM] = __floats2half2_rn(x2, x3);
            *(__half2*)&Clo[o]          = __floats2half2_rn(residf(x0), residf(x1));
            *(__half2*)&Clo[o + 8 * DM] = __floats2half2_rn(residf(x2), residf(x3));
        }
    }
}

// ---------------------------------------------------------------------------
// Expand: write final full-width attn = mask ? 0 : (hi+lo)/rowsum. 1 block/row.
// ---------------------------------------------------------------------------
__global__ __launch_bounds__(256) void expand_kernel(
    const __half* __restrict__ Phi, const __half* __restrict__ Plo,
    const float* __restrict__ rowsum, const int* __restrict__ fwd,
    float* __restrict__ attn)
{
    const int row = blockIdx.x;
    const int b = row >> 15;               // NH*SEQ = 32768
    const float inv = 1.0f / rowsum[row];
    const __half* ph = Phi + (size_t)row * SEQ;
    const __half* pl = Plo + (size_t)row * SEQ;
    const int* fw = fwd + b * SEQ;
    float* o = attn + (size_t)row * SEQ;

    const int j0 = threadIdx.x * 8;
    float vals[8];
#pragma unroll
    for (int t = 0; t < 8; t++) {
        int f = fw[j0 + t];
        vals[t] = (f >= 0)
            ? (__half2float(ph[f]) + __half2float(pl[f])) * inv : 0.f;
    }
    *(float4*)(o + j0)     = make_float4(vals[0], vals[1], vals[2], vals[3]);
    *(float4*)(o + j0 + 4) = make_float4(vals[4], vals[5], vals[6], vals[7]);
}

// ---------------------------------------------------------------------------
// Launcher — forked-stream graph: transpose_v ∥ logits, expand ∥ (av, out_gemm)
// ---------------------------------------------------------------------------
extern "C" void kernel_launch(void* const* d_in, const int* in_sizes, int n_in,
                              void* d_out, int out_size)
{
    const float* v    = (const float*)d_in[0];
    const float* k    = (const float*)d_in[1];
    const float* q    = (const float*)d_in[2];
    const int*   mask = (const int*)  d_in[3];
    const float* Wq = (const float*)d_in[4];
    const float* bq = (const float*)d_in[5];
    const float* Wk = (const float*)d_in[6];
    const float* bk = (const float*)d_in[7];
    const float* Wv = (const float*)d_in[8];
    const float* bv = (const float*)d_in[9];
    const float* Wo = (const float*)d_in[10];
    const float* bo = (const float*)d_in[11];
    float* out = (float*)d_out;

    __half *Xhi, *Xlo, *QKVhi, *QKVlo, *Vthi, *Vtlo, *Cxhi, *Cxlo, *WThi, *WTlo;
    __half *Phi, *Plo;
    float *attnScratch, *partialp, *rowsump;
    int *fwdp, *cidxp, *cntp;
    cudaGetSymbolAddress((void**)&Xhi, g_Xhi);
    cudaGetSymbolAddress((void**)&Xlo, g_Xlo);
    cudaGetSymbolAddress((void**)&QKVhi, g_QKVhi);
    cudaGetSymbolAddress((void**)&QKVlo, g_QKVlo);
    cudaGetSymbolAddress((void**)&Vthi, g_Vthi);
    cudaGetSymbolAddress((void**)&Vtlo, g_Vtlo);
    cudaGetSymbolAddress((void**)&Cxhi, g_Cxhi);
    cudaGetSymbolAddress((void**)&Cxlo, g_Cxlo);
    cudaGetSymbolAddress((void**)&WThi, g_WThi);
    cudaGetSymbolAddress((void**)&WTlo, g_WTlo);
    cudaGetSymbolAddress((void**)&Phi, g_Phi);
    cudaGetSymbolAddress((void**)&Plo, g_Plo);
    cudaGetSymbolAddress((void**)&attnScratch, g_attn);
    cudaGetSymbolAddress((void**)&partialp, g_partial);
    cudaGetSymbolAddress((void**)&rowsump, g_rowsum);
    cudaGetSymbolAddress((void**)&fwdp, g_fwd);
    cudaGetSymbolAddress((void**)&cidxp, g_cidx);
    cudaGetSymbolAddress((void**)&cntp, g_cnt);

    cudaFuncSetAttribute(qkv_gemm_kernel,
                         cudaFuncAttributeMaxDynamicSharedMemorySize, GEMM_SMEM);
    cudaFuncSetAttribute(out_gemm_kernel,
                         cudaFuncAttributeMaxDynamicSharedMemorySize, GEMM_SMEM);
    cudaFuncSetAttribute(logits_kernel,
                         cudaFuncAttributeMaxDynamicSharedMemorySize, LOGITS_SMEM);
    cudaFuncSetAttribute(av_kernel,
                         cudaFuncAttributeMaxDynamicSharedMemorySize, AV_SMEM);

    const size_t FINAL_ELEMS = (size_t)BS_ROWS * DM;
    const size_t ATTN_ELEMS  = (size_t)BH * SEQ * SEQ;
    const size_t asz = (size_t)BS_ROWS * DM;
    float* attnp = ((size_t)out_size >= FINAL_ELEMS + ATTN_ELEMS)
                       ? (out + FINAL_ELEMS) : attnScratch;

    // Fork machinery (created per call, never destroyed; no device allocs).
    cudaStream_t s2 = 0;
    bool forked = (cudaStreamCreateWithFlags(&s2, cudaStreamNonBlocking) == cudaSuccess);
    cudaEvent_t eFork = 0, eW = 0, eQkv = 0, eVt = 0, eRs = 0, eJoin = 0;
    if (forked) {
        forked = (cudaEventCreateWithFlags(&eFork, cudaEventDisableTiming) == cudaSuccess) &&
                 (cudaEventCreateWithFlags(&eW,    cudaEventDisableTiming) == cudaSuccess) &&
                 (cudaEventCreateWithFlags(&eQkv,  cudaEventDisableTiming) == cudaSuccess) &&
                 (cudaEventCreateWithFlags(&eVt,   cudaEventDisableTiming) == cudaSuccess) &&
                 (cudaEventCreateWithFlags(&eRs,   cudaEventDisableTiming) == cudaSuccess) &&
                 (cudaEventCreateWithFlags(&eJoin, cudaEventDisableTiming) == cudaSuccess);
    }

    if (forked) {
        cudaEventRecord(eFork, 0);
        cudaStreamWaitEvent(s2, eFork, 0);

        mask_scan_kernel<<<BATCH, 1024, 0, s2>>>(mask, fwdp, cidxp, cntp);
        transpose_split_kernel<<<dim3(32, 32, 4), 256, 0, s2>>>(Wq, Wk, Wv, Wo, WThi, WTlo);
        cudaEventRecord(eW, s2);
        split_inputs_kernel<<<dim3(4096, 3), 256>>>(q, k, v, Xhi, Xlo);

        cudaStreamWaitEvent(0, eW, 0);
        qkv_gemm_kernel<<<dim3(8, 32, 3), 256, GEMM_SMEM>>>(
            Xhi, Xlo, WThi, WTlo, bq, bk, bv, QKVhi, QKVlo);
        cudaEventRecord(eQkv, 0);

        cudaStreamWaitEvent(s2, eQkv, 0);
        transpose_v_kernel<<<dim3(32, 128), 256, 0, s2>>>(
            QKVhi + 2 * asz, QKVlo + 2 * asz, fwdp, Vthi, Vtlo);
        cudaEventRecord(eVt, s2);

        logits_kernel<<<dim3(16, 16, BH), 256, LOGITS_SMEM>>>(
            QKVhi, QKVlo, QKVhi + asz, QKVlo + asz, cidxp, cntp, Phi, Plo, partialp);
        reduce_sums_kernel<<<(BH * SEQ) / 256, 256>>>(partialp, rowsump);
        cudaEventRecord(eRs, 0);

        cudaStreamWaitEvent(s2, eRs, 0);
        expand_kernel<<<BH * SEQ, 256, 0, s2>>>(Phi, Plo, rowsump, fwdp, attnp);
        cudaEventRecord(eJoin, s2);

        cudaStreamWaitEvent(0, eVt, 0);
        av_kernel<<<dim3(16, BH), 256, AV_SMEM>>>(
            Phi, Plo, Vthi, Vtlo, rowsump, cntp, Cxhi, Cxlo);
        out_gemm_kernel<<<dim3(8, 32), 256, GEMM_SMEM>>>(
            Cxhi, Cxlo, WThi, WTlo, bo, out);

        cudaStreamWaitEvent(0, eJoin, 0);
    } else {
        mask_scan_kernel<<<BATCH, 1024>>>(mask, fwdp, cidxp, cntp);
        split_inputs_kernel<<<dim3(4096, 3), 256>>>(q, k, v, Xhi, Xlo);
        transpose_split_kernel<<<dim3(32, 32, 4), 256>>>(Wq, Wk, Wv, Wo, WThi, WTlo);
        qkv_gemm_kernel<<<dim3(8, 32, 3), 256, GEMM_SMEM>>>(
            Xhi, Xlo, WThi, WTlo, bq, bk, bv, QKVhi, QKVlo);
        transpose_v_kernel<<<dim3(32, 128), 256>>>(
            QKVhi + 2 * asz, QKVlo + 2 * asz, fwdp, Vthi, Vtlo);
        logits_kernel<<<dim3(16, 16, BH), 256, LOGITS_SMEM>>>(
            QKVhi, QKVlo, QKVhi + asz, QKVlo + asz, cidxp, cntp, Phi, Plo, partialp);
        reduce_sums_kernel<<<(BH * SEQ) / 256, 256>>>(partialp, rowsump);
        av_kernel<<<dim3(16, BH), 256, AV_SMEM>>>(
            Phi, Plo, Vthi, Vtlo, rowsump, cntp, Cxhi, Cxlo);
        expand_kernel<<<BH * SEQ, 256>>>(Phi, Plo, rowsump, fwdp, attnp);
        out_gemm_kernel<<<dim3(8, 32), 256, GEMM_SMEM>>>(
            Cxhi, Cxlo, WThi, WTlo, bo, out);
    }
}

// round 14
// speedup vs baseline: 1.1520x; 1.1118x over previous
#include <cuda_runtime.h>
#include <cuda_fp16.h>
#include <math.h>
#include <stdint.h>
#include <stddef.h>

#define DM 1024
#define NH 16
#define DEPTH 64
#define BATCH 2
#define SEQ 2048
#define BS_ROWS 4096
#define BH 32

// ---------------------------------------------------------------------------
// Scratch (__device__ globals; allocation-free rule). Zero-initialized.
// ---------------------------------------------------------------------------
__device__ __half g_Xhi[3][(size_t)BS_ROWS * DM];
__device__ __half g_Xlo[3][(size_t)BS_ROWS * DM];
__device__ __half g_QKVhi[3][(size_t)BS_ROWS * DM];
__device__ __half g_QKVlo[3][(size_t)BS_ROWS * DM];
__device__ __half g_Vthi[(size_t)BH * DEPTH * SEQ];   // [bh][d][compact s]
__device__ __half g_Vtlo[(size_t)BH * DEPTH * SEQ];
__device__ __half g_Cxhi[(size_t)BS_ROWS * DM];
__device__ __half g_Cxlo[(size_t)BS_ROWS * DM];
__device__ __half g_WThi[4][(size_t)DM * DM];
__device__ __half g_WTlo[4][(size_t)DM * DM];
__device__ __half g_Phi[(size_t)BH * SEQ * SEQ];      // exp(p) fp16, compact cols
__device__ float  g_attn[(size_t)BH * SEQ * SEQ];     // fallback full attn
__device__ float  g_partial[(size_t)BH * SEQ * 16];
__device__ float  g_rowsum[(size_t)BH * SEQ];
__device__ int    g_fwd[BATCH * SEQ];
__device__ int    g_cidx[BATCH * SEQ];
__device__ int    g_cnt[BATCH];

// ---------------------------------------------------------------------------
// Helpers
// ---------------------------------------------------------------------------
__device__ __forceinline__ float residf(float x) {
    return x - __half2float(__float2half_rn(x));
}
__device__ __forceinline__ uint32_t smem_u32(const void* p) {
    return (uint32_t)__cvta_generic_to_shared(p);
}
// FMA/ALU-pipe exp (fp32, rel err ~1e-7). Validated numerically in R9.
__device__ __forceinline__ float exp_fma(float x) {
    float t = x * 1.44269504088896341f;
    float r = t + 12582912.0f;                      // 1.5 * 2^23
    int   n = __float_as_int(r) - 0x4B400000;
    float f = t - (r - 12582912.0f);                // f in [-0.5, 0.5]
    float p = 1.5403530393e-4f;
    p = fmaf(p, f, 1.3333558146e-3f);
    p = fmaf(p, f, 9.6181291076e-3f);
    p = fmaf(p, f, 5.5504108665e-2f);
    p = fmaf(p, f, 2.4022650696e-1f);
    p = fmaf(p, f, 6.9314718056e-1f);
    p = fmaf(p, f, 1.0f);
    return __int_as_float(__float_as_int(p) + (n << 23));
}
#define CP16(dst_u32, src_ptr) \
    asm volatile("cp.async.cg.shared.global [%0], [%1], 16;\n" :: "r"(dst_u32), "l"(src_ptr))
#define CP_COMMIT asm volatile("cp.async.commit_group;\n" ::: "memory")
#define CP_WAIT0  asm volatile("cp.async.wait_group 0;\n" ::: "memory")

__device__ __forceinline__ void mma16816(float4& d,
    uint32_t a0, uint32_t a1, uint32_t a2, uint32_t a3,
    uint32_t b0, uint32_t b1)
{
    asm volatile(
        "mma.sync.aligned.m16n8k16.row.col.f32.f16.f16.f32 "
        "{%0,%1,%2,%3},{%4,%5,%6,%7},{%8,%9},{%0,%1,%2,%3};\n"
        : "+f"(d.x), "+f"(d.y), "+f"(d.z), "+f"(d.w)
        : "r"(a0), "r"(a1), "r"(a2), "r"(a3), "r"(b0), "r"(b1));
}

__device__ __forceinline__ void ldsm4(uint32_t& r0, uint32_t& r1,
                                      uint32_t& r2, uint32_t& r3, uint32_t addr)
{
    asm volatile("ldmatrix.sync.aligned.m8n8.x4.shared.b16 {%0,%1,%2,%3}, [%4];\n"
                 : "=r"(r0), "=r"(r1), "=r"(r2), "=r"(r3) : "r"(addr));
}

__device__ __forceinline__ void lda_x4(uint32_t* f, uint32_t sbase, int lp_bytes,
                                       int rbase, int kb0, int lane)
{
    int seg = lane >> 3, rw = lane & 7;
    int row = rbase + rw + ((seg & 1) << 3);
    int col = kb0 + ((seg >> 1) << 3);
    ldsm4(f[0], f[1], f[2], f[3], sbase + row * lp_bytes + col * 2);
}
__device__ __forceinline__ void ldb_x4(uint32_t* f0, uint32_t* f1, uint32_t sbase,
                                       int lp_bytes, int cbase, int kb0, int lane)
{
    int seg = lane >> 3, rw = lane & 7;
    int row = cbase + rw + ((seg >> 1) << 3);
    int col = kb0 + ((seg & 1) << 3);
    ldsm4(f0[0], f0[1], f1[0], f1[1], sbase + row * lp_bytes + col * 2);
}

// ---------------------------------------------------------------------------
// Mask scan: per batch, prefix-compact unmasked columns. 1 block/batch.
// ---------------------------------------------------------------------------
__global__ __launch_bounds__(1024) void mask_scan_kernel(
    const int* __restrict__ mask, int* __restrict__ fwd,
    int* __restrict__ cidx, int* __restrict__ cnt)
{
    __shared__ int sa[1024], sb[1024];
    const int b = blockIdx.x, t = threadIdx.x;
    const int j0 = 2 * t, j1 = 2 * t + 1;
    const int m0 = (mask[b * SEQ + j0] == 0);
    const int m1 = (mask[b * SEQ + j1] == 0);
    sa[t] = m0 + m1;
    __syncthreads();
    int* src = sa; int* dst = sb;
    for (int off = 1; off < 1024; off <<= 1) {
        int v = src[t] + ((t >= off) ? src[t - off] : 0);
        dst[t] = v;
        __syncthreads();
        int* tmp = src; src = dst; dst = tmp;
    }
    const int incl = src[t];
    const int excl = incl - (m0 + m1);
    fwd[b * SEQ + j0] = m0 ? excl : -1;
    fwd[b * SEQ + j1] = m1 ? (excl + m0) : -1;
    if (m0) cidx[b * SEQ + excl] = j0;
    if (m1) cidx[b * SEQ + excl + m0] = j1;
    const int total = src[1023];
    if (t == 0) cnt[b] = total;
    __syncthreads();
    for (int s = t; s < SEQ; s += 1024)
        if (s >= total) cidx[b * SEQ + s] = 0;
}

// ---------------------------------------------------------------------------
// Elementwise split of q/k/v inputs
// ---------------------------------------------------------------------------
__global__ __launch_bounds__(256) void split_inputs_kernel(
    const float* __restrict__ q, const float* __restrict__ k,
    const float* __restrict__ v, __half* __restrict__ Xhi, __half* __restrict__ Xlo)
{
    const int z = blockIdx.y;
    const float* src = (z == 0) ? q : (z == 1) ? k : v;
    const size_t i = ((size_t)blockIdx.x * 256 + threadIdx.x) * 4;
    const size_t o = (size_t)z * BS_ROWS * DM + i;
    float4 x = *(const float4*)(src + i);
    *(__half2*)(Xhi + o)     = __floats2half2_rn(x.x, x.y);
    *(__half2*)(Xhi + o + 2) = __floats2half2_rn(x.z, x.w);
    *(__half2*)(Xlo + o)     = __floats2half2_rn(residf(x.x), residf(x.y));
    *(__half2*)(Xlo + o + 2) = __floats2half2_rn(residf(x.z), residf(x.w));
}

// ---------------------------------------------------------------------------
// Weight transpose+split
// ---------------------------------------------------------------------------
__global__ __launch_bounds__(256) void transpose_split_kernel(
    const float* __restrict__ Wq, const float* __restrict__ Wk,
    const float* __restrict__ Wv, const float* __restrict__ Wo,
    __half* __restrict__ ThiB, __half* __restrict__ TloB)
{
    const int z = blockIdx.z;
    const float* W = (z == 0) ? Wq : (z == 1) ? Wk : (z == 2) ? Wv : Wo;
    __half* Thi = ThiB + (size_t)z * DM * DM;
    __half* Tlo = TloB + (size_t)z * DM * DM;

    __shared__ float tile[32][33];
    const int k0 = blockIdx.y * 32, n0 = blockIdx.x * 32;
    const int tx = threadIdx.x & 31, ty = threadIdx.x >> 5;
#pragma unroll
    for (int i = 0; i < 4; i++) {
        int kk = ty + i * 8;
        tile[kk][tx] = W[(size_t)(k0 + kk) * DM + n0 + tx];
    }
    __syncthreads();
#pragma unroll
    for (int i = 0; i < 4; i++) {
        int nn = ty + i * 8;
        float x = tile[tx][nn];
        __half hi = __float2half_rn(x);
        Thi[(size_t)(n0 + nn) * DM + k0 + tx] = hi;
        Tlo[(size_t)(n0 + nn) * DM + k0 + tx] = __float2half_rn(x - __half2float(hi));
    }
}

// ---------------------------------------------------------------------------
// V transpose with compaction: V [4096][1024] -> Vt [bh][64][compact s]
// ---------------------------------------------------------------------------
__global__ __launch_bounds__(256) void transpose_v_kernel(
    const __half* __restrict__ Vhi, const __half* __restrict__ Vlo,
    const int* __restrict__ fwd,
    __half* __restrict__ Thi, __half* __restrict__ Tlo)
{
    __shared__ __half thi[32][33], tlo[32][33];
    const int n0 = blockIdx.x * 32;
    const int s0 = blockIdx.y * 32;
    const int tx = threadIdx.x & 31, ty = threadIdx.x >> 5;
#pragma unroll
    for (int i = 0; i < 4; i++) {
        int r = ty + i * 8;
        thi[r][tx] = Vhi[(size_t)(s0 + r) * DM + n0 + tx];
        tlo[r][tx] = Vlo[(size_t)(s0 + r) * DM + n0 + tx];
    }
    __syncthreads();
    const int b = s0 >> 11;
    const int slot = fwd[b * SEQ + (s0 & 2047) + tx];
    if (slot >= 0) {
#pragma unroll
        for (int i = 0; i < 4; i++) {
            int nn = ty + i * 8;
            int gn = n0 + nn;
            int h = gn >> 6, d = gn & 63;
            size_t orow = ((size_t)(b * NH + h) * DEPTH + d) * SEQ + slot;
            Thi[orow] = thi[tx][nn];
            Tlo[orow] = tlo[tx][nn];
        }
    }
}

// ---------------------------------------------------------------------------
// Double-buffered split-fp16 GEMM (projections). BM=BN=128, BK=32.
// Single barrier per k-iteration: wait -> sync -> issue next loads -> compute.
// ---------------------------------------------------------------------------
#define GSTAGE 40960
#define GEMM_SMEM (2 * GSTAGE)

__device__ __forceinline__ void gemm_load_stage(uint32_t smbase, int s,
    const __half* AhiG, const __half* AloG,
    const __half* BhiG, const __half* BloG,
    int m0, int n0, int k0, int tid)
{
    uint32_t sb = smbase + s * GSTAGE;
#pragma unroll
    for (int t = 0; t < 2; t++) {
        int id = tid * 2 + t;
        int r = id >> 2, q = id & 3;
        uint32_t off = r * 80 + q * 16;
        const size_t ga = (size_t)(m0 + r) * DM + k0 + q * 8;
        const size_t gb = (size_t)(n0 + r) * DM + k0 + q * 8;
        CP16(sb + off,         AhiG + ga);
        CP16(sb + 10240 + off, AloG + ga);
        CP16(sb + 20480 + off, BhiG + gb);
        CP16(sb + 30720 + off, BloG + gb);
    }
}

template<bool OUT_F32>
__device__ __forceinline__ void gemm_core(
    const __half* __restrict__ AhiG, const __half* __restrict__ AloG,
    const __half* __restrict__ BhiG, const __half* __restrict__ BloG,
    const float* __restrict__ bias,
    float* __restrict__ Cf, __half* __restrict__ Chi, __half* __restrict__ Clo)
{
    extern __shared__ char dsm[];
    const uint32_t smbase = smem_u32(dsm);

    const int tid = threadIdx.x;
    const int m0 = blockIdx.y * 128, n0 = blockIdx.x * 128;
    const int lane = tid & 31, wid = tid >> 5;
    const int wm = wid >> 2, wn = wid & 3;
    const int grp = lane >> 2, tig = lane & 3;

    float4 acc[4][4];
#pragma unroll
    for (int i = 0; i < 4; i++)
#pragma unroll
        for (int j = 0; j < 4; j++) acc[i][j] = make_float4(0.f, 0.f, 0.f, 0.f);

    gemm_load_stage(smbase, 0, AhiG, AloG, BhiG, BloG, m0, n0, 0, tid);
    CP_COMMIT;

    for (int kt = 0; kt < 32; kt++) {
        CP_WAIT0;
        __syncthreads();
        if (kt + 1 < 32) {
            gemm_load_stage(smbase, (kt + 1) & 1, AhiG, AloG, BhiG, BloG,
                            m0, n0, (kt + 1) * 32, tid);
            CP_COMMIT;
        }

        const uint32_t sb = smbase + (kt & 1) * GSTAGE;
        const uint32_t ah_b = sb, al_b = sb + 10240, bh_b = sb + 20480, bl_b = sb + 30720;
#pragma unroll
        for (int ks = 0; ks < 2; ks++) {
            const int kb0 = ks * 16;
            uint32_t ah[4][4], al[4][4];
#pragma unroll
            for (int mt = 0; mt < 4; mt++) {
                lda_x4(ah[mt], ah_b, 80, wm * 64 + mt * 16, kb0, lane);
                lda_x4(al[mt], al_b, 80, wm * 64 + mt * 16, kb0, lane);
            }
            uint32_t bhf[4][2], blf[4][2];
#pragma unroll
            for (int p = 0; p < 2; p++) {
                ldb_x4(bhf[2 * p], bhf[2 * p + 1], bh_b, 80, wn * 32 + p * 16, kb0, lane);
                ldb_x4(blf[2 * p], blf[2 * p + 1], bl_b, 80, wn * 32 + p * 16, kb0, lane);
            }
#pragma unroll
            for (int mt = 0; mt < 4; mt++)
#pragma unroll
                for (int nt = 0; nt < 4; nt++) {
                    mma16816(acc[mt][nt], ah[mt][0], ah[mt][1], ah[mt][2], ah[mt][3],
                             bhf[nt][0], bhf[nt][1]);
                    mma16816(acc[mt][nt], ah[mt][0], ah[mt][1], ah[mt][2], ah[mt][3],
                             blf[nt][0], blf[nt][1]);
                    mma16816(acc[mt][nt], al[mt][0], al[mt][1], al[mt][2], al[mt][3],
                             bhf[nt][0], bhf[nt][1]);
                }
        }
    }

#pragma unroll
    for (int mt = 0; mt < 4; mt++) {
        int r = m0 + wm * 64 + mt * 16 + grp;
#pragma unroll
        for (int nt = 0; nt < 4; nt++) {
            int c = n0 + wn * 32 + nt * 8 + tig * 2;
            float bx = bias[c], by = bias[c + 1];
            float x0 = acc[mt][nt].x + bx, x1 = acc[mt][nt].y + by;
            float x2 = acc[mt][nt].z + bx, x3 = acc[mt][nt].w + by;
            if (OUT_F32) {
                *(float2*)&Cf[(size_t)r * DM + c]       = make_float2(x0, x1);
                *(float2*)&Cf[(size_t)(r + 8) * DM + c] = make_float2(x2, x3);
            } else {
                *(__half2*)&Chi[(size_t)r * DM + c]       = __floats2half2_rn(x0, x1);
                *(__half2*)&Chi[(size_t)(r + 8) * DM + c] = __floats2half2_rn(x2, x3);
                *(__half2*)&Clo[(size_t)r * DM + c]       = __floats2half2_rn(residf(x0), residf(x1));
                *(__half2*)&Clo[(size_t)(r + 8) * DM + c] = __floats2half2_rn(residf(x2), residf(x3));
            }
        }
    }
}

__global__ __launch_bounds__(256) void qkv_gemm_kernel(
    const __half* __restrict__ Xhi, const __half* __restrict__ Xlo,
    const __half* __restrict__ WThi, const __half* __restrict__ WTlo,
    const float* __restrict__ bq, const float* __restrict__ bk,
    const float* __restrict__ bv,
    __half* __restrict__ QKVhi, __half* __restrict__ QKVlo)
{
    const int z = blockIdx.z;
    const size_t asz = (size_t)BS_ROWS * DM, wsz = (size_t)DM * DM;
    const float* bias = (z == 0) ? bq : (z == 1) ? bk : bv;
    gemm_core<false>(Xhi + z * asz, Xlo + z * asz, WThi + z * wsz, WTlo + z * wsz,
                     bias, nullptr, QKVhi + z * asz, QKVlo + z * asz);
}

__global__ __launch_bounds__(256) void out_gemm_kernel(
    const __half* __restrict__ Cxhi, const __half* __restrict__ Cxlo,
    const __half* __restrict__ WThi, const __half* __restrict__ WTlo,
    const float* __restrict__ bo, float* __restrict__ out)
{
    const size_t wsz = (size_t)DM * DM;
    gemm_core<true>(Cxhi, Cxlo, WThi + 3 * wsz, WTlo + 3 * wsz, bo,
                    out, nullptr, nullptr);
}

// ---------------------------------------------------------------------------
// Logits over COMPACT columns: p = exp(0.125*QK), stored fp16 (no residual).
// Exp split 75% MUFU / 25% FMA-pipe poly (balance point per pipe model).
// ---------------------------------------------------------------------------
#define LP 72
#define LOGITS_SMEM (4 * 128 * LP * 2 + 128 * 4 * 4)

__global__ __launch_bounds__(256) void logits_kernel(
    const __half* __restrict__ Qhi, const __half* __restrict__ Qlo,
    const __half* __restrict__ Khi, const __half* __restrict__ Klo,
    const int* __restrict__ cidx, const int* __restrict__ cnt,
    __half* __restrict__ Phi, float* __restrict__ partial)
{
    extern __shared__ __half sm[];
    __half (*Qh)[LP] = (__half(*)[LP])sm;
    __half (*Ql)[LP] = (__half(*)[LP])(sm + 128 * LP);
    __half (*Kh)[LP] = (__half(*)[LP])(sm + 2 * 128 * LP);
    __half (*Kl)[LP] = (__half(*)[LP])(sm + 3 * 128 * LP);
    float* sums = (float*)(sm + 4 * 128 * LP);

    const int tid = threadIdx.x;
    const int n0 = blockIdx.x * 128, m0 = blockIdx.y * 128;
    const int bh = blockIdx.z, b = bh >> 4, h = bh & 15;
    const int Mb = cnt[b];

    if (n0 >= Mb) {
        if (tid < 128)
            partial[((size_t)bh * SEQ + m0 + tid) * 16 + blockIdx.x] = 0.f;
        return;
    }

    const size_t hbase = (size_t)b * SEQ * DM + h * 64;
    const int* cb = cidx + b * SEQ;

#pragma unroll
    for (int t = 0; t < 16; t++) {
        int id = tid + 256 * t;
        int arr = id >> 10, rem = id & 1023;
        int r = rem >> 3, q = rem & 7;
        const __half* src = (arr == 0) ? Qhi : (arr == 1) ? Qlo : (arr == 2) ? Khi : Klo;
        __half (*dst)[LP] = (arr == 0) ? Qh : (arr == 1) ? Ql : (arr == 2) ? Kh : Kl;
        int rphys;
        if (arr < 2) rphys = m0 + r;
        else {
            int jr = n0 + r;
            rphys = (jr < Mb) ? cb[jr] : 0;
        }
        uint4 v = *(const uint4*)(src + hbase + (size_t)rphys * DM + q * 8);
        *(uint2*)&dst[r][q * 8]     = make_uint2(v.x, v.y);
        *(uint2*)&dst[r][q * 8 + 4] = make_uint2(v.z, v.w);
    }
    __syncthreads();

    const int lane = tid & 31, wid = tid >> 5;
    const int wm = wid >> 2, wn = wid & 3;
    const int grp = lane >> 2, tig = lane & 3;
    const uint32_t qh_b = smem_u32(Qh), ql_b = smem_u32(Ql);
    const uint32_t kh_b = smem_u32(Kh), kl_b = smem_u32(Kl);

    float4 acc[4][4];
#pragma unroll
    for (int i = 0; i < 4; i++)
#pragma unroll
        for (int j = 0; j < 4; j++) acc[i][j] = make_float4(0.f, 0.f, 0.f, 0.f);

#pragma unroll
    for (int ks = 0; ks < 4; ks++) {
        const int kb0 = ks * 16;
        uint32_t ah[4][4], al[4][4];
#pragma unroll
        for (int mt = 0; mt < 4; mt++) {
            lda_x4(ah[mt], qh_b, 144, wm * 64 + mt * 16, kb0, lane);
            lda_x4(al[mt], ql_b, 144, wm * 64 + mt * 16, kb0, lane);
        }
        uint32_t bhf[4][2], blf[4][2];
#pragma unroll
        for (int p = 0; p < 2; p++) {
            ldb_x4(bhf[2 * p], bhf[2 * p + 1], kh_b, 144, wn * 32 + p * 16, kb0, lane);
            ldb_x4(blf[2 * p], blf[2 * p + 1], kl_b, 144, wn * 32 + p * 16, kb0, lane);
        }
#pragma unroll
        for (int mt = 0; mt < 4; mt++)
#pragma unroll
            for (int nt = 0; nt < 4; nt++) {
                mma16816(acc[mt][nt], ah[mt][0], ah[mt][1], ah[mt][2], ah[mt][3],
                         bhf[nt][0], bhf[nt][1]);
                mma16816(acc[mt][nt], ah[mt][0], ah[mt][1], ah[mt][2], ah[mt][3],
                         blf[nt][0], blf[nt][1]);
                mma16816(acc[mt][nt], al[mt][0], al[mt][1], al[mt][2], al[mt][3],
                         bhf[nt][0], bhf[nt][1]);
            }
    }

    float rs0[4], rs1[4];
#pragma unroll
    for (int mt = 0; mt < 4; mt++) { rs0[mt] = 0.f; rs1[mt] = 0.f; }

#pragma unroll
    for (int mt = 0; mt < 4; mt++) {
        int r = m0 + wm * 64 + mt * 16 + grp;
        __half* oh0 = Phi + ((size_t)bh * SEQ + r) * SEQ;
        __half* oh1 = oh0 + (size_t)8 * SEQ;
#pragma unroll
        for (int nt = 0; nt < 4; nt++) {
            int j = n0 + wn * 32 + nt * 8 + tig * 2;
            bool v0 = (j < Mb), v1 = (j + 1 < Mb);
            float4 a = acc[mt][nt];
            // 3 of 4 exps on MUFU, 1 of 4 on the FMA/ALU pipes (balance point).
            float p0 = v0 ? __expf(a.x * 0.125f)  : 0.f;
            float p1 = v1 ? __expf(a.y * 0.125f)  : 0.f;
            float p2 = v0 ? __expf(a.z * 0.125f)  : 0.f;
            float p3 = v1 ? exp_fma(a.w * 0.125f) : 0.f;
            *(__half2*)(oh0 + j) = __floats2half2_rn(p0, p1);
            *(__half2*)(oh1 + j) = __floats2half2_rn(p2, p3);
            rs0[mt] += p0 + p1;
            rs1[mt] += p2 + p3;
        }
    }
#pragma unroll
    for (int mt = 0; mt < 4; mt++) {
        float s0 = rs0[mt], s1 = rs1[mt];
        s0 += __shfl_xor_sync(0xffffffffu, s0, 1);
        s0 += __shfl_xor_sync(0xffffffffu, s0, 2);
        s1 += __shfl_xor_sync(0xffffffffu, s1, 1);
        s1 += __shfl_xor_sync(0xffffffffu, s1, 2);
        if (tig == 0) {
            int rl = wm * 64 + mt * 16 + grp;
            sums[(size_t)rl * 4 + wn] = s0;
            sums[(size_t)(rl + 8) * 4 + wn] = s1;
        }
    }
    __syncthreads();
    if (tid < 128) {
        float tot = (sums[tid * 4 + 0] + sums[tid * 4 + 1]) +
                    (sums[tid * 4 + 2] + sums[tid * 4 + 3]);
        partial[((size_t)bh * SEQ + m0 + tid) * 16 + blockIdx.x] = tot;
    }
}

__global__ __launch_bounds__(256) void reduce_sums_kernel(
    const float* __restrict__ partial, float* __restrict__ rowsum)
{
    int i = blockIdx.x * 256 + threadIdx.x;
    const float4* p = (const float4*)(partial + (size_t)i * 16);
    float4 a = p[0], b = p[1], c = p[2], d = p[3];
    rowsum[i] = ((a.x + a.y) + (a.z + a.w)) + ((b.x + b.y) + (b.z + b.w)) +
                ((c.x + c.y) + (c.z + c.w)) + ((d.x + d.y) + (d.z + d.w));
}

// ---------------------------------------------------------------------------
// AV over compact K-dim: ctx = (P @ Vc) / rowsum. P is fp16-only now.
// BM=128, BN=64, BK=64. 2 mma terms per tile (P·Vh + P·Vl).
// ---------------------------------------------------------------------------
#define AV_SMEM (128 * LP * 2 + 2 * 64 * LP * 2 + 128 * 4)

__global__ __launch_bounds__(256) void av_kernel(
    const __half* __restrict__ Phi,
    const __half* __restrict__ Vthi, const __half* __restrict__ Vtlo,
    const float* __restrict__ rowsum, const int* __restrict__ cnt,
    __half* __restrict__ Chi, __half* __restrict__ Clo)
{
    extern __shared__ char smraw[];
    __half (*Ah)[LP] = (__half(*)[LP])smraw;
    __half (*Vh)[LP] = (__half(*)[LP])(smraw + 128 * LP * 2);
    __half (*Vl)[LP] = (__half(*)[LP])(smraw + 128 * LP * 2 + 64 * LP * 2);
    float* sinv = (float*)(smraw + 128 * LP * 2 + 2 * 64 * LP * 2);

    const int tid = threadIdx.x;
    const int m0 = blockIdx.x * 128;
    const int bh = blockIdx.y, b = bh >> 4, h = bh & 15;
    const int Mb = cnt[b];

    if (tid < 128) sinv[tid] = 1.0f / rowsum[(size_t)bh * SEQ + m0 + tid];
    __syncthreads();

    const int lane = tid & 31, wid = tid >> 5;
    const int wm = wid >> 2, wn = wid & 3;
    const int grp = lane >> 2, tig = lane & 3;
    const uint32_t ah_b = smem_u32(Ah);
    const uint32_t vh_b = smem_u32(Vh), vl_b = smem_u32(Vl);

    float4 acc[4][2];
#pragma unroll
    for (int i = 0; i < 4; i++)
#pragma unroll
        for (int j = 0; j < 2; j++) acc[i][j] = make_float4(0.f, 0.f, 0.f, 0.f);

    const size_t prow = (size_t)bh * SEQ + m0;
    const size_t vtb = (size_t)bh * DEPTH * SEQ;

    for (int k0 = 0; k0 < Mb; k0 += 64) {
        // P tile: 128 rows x 64 cols fp16 = 1024 uint4 / 256 thr
#pragma unroll
        for (int t = 0; t < 4; t++) {
            int id = tid + 256 * t;            // 0..1023
            int r = id >> 3, q = id & 7;       // r 0..127, q 0..7
            uint4 v = *(const uint4*)(Phi + (prow + r) * SEQ + k0 + q * 8);
            *(uint2*)&Ah[r][q * 8]     = make_uint2(v.x, v.y);
            *(uint2*)&Ah[r][q * 8 + 4] = make_uint2(v.z, v.w);
        }
        // V tiles: 64 d-rows x 64 cols x {hi,lo} = 1024 uint4 / 256 thr
#pragma unroll
        for (int t = 0; t < 4; t++) {
            int id = tid + 256 * t;            // 0..1023
            int arr = id >> 9, rem = id & 511;
            int r = rem >> 3, q = rem & 7;
            const __half* src = arr ? Vtlo : Vthi;
            __half (*dst)[LP] = arr ? Vl : Vh;
            uint4 v = *(const uint4*)(src + vtb + (size_t)r * SEQ + k0 + q * 8);
            *(uint2*)&dst[r][q * 8]     = make_uint2(v.x, v.y);
            *(uint2*)&dst[r][q * 8 + 4] = make_uint2(v.z, v.w);
        }
        __syncthreads();

#pragma unroll
        for (int ks = 0; ks < 4; ks++) {
            const int kb0 = ks * 16;
            uint32_t ah[4][4];
#pragma unroll
            for (int mt = 0; mt < 4; mt++)
                lda_x4(ah[mt], ah_b, 144, wm * 64 + mt * 16, kb0, lane);
            uint32_t bhf[2][2], blf[2][2];
            ldb_x4(bhf[0], bhf[1], vh_b, 144, wn * 16, kb0, lane);
            ldb_x4(blf[0], blf[1], vl_b, 144, wn * 16, kb0, lane);
#pragma unroll
            for (int mt = 0; mt < 4; mt++)
#pragma unroll
                for (int nt = 0; nt < 2; nt++) {
                    mma16816(acc[mt][nt], ah[mt][0], ah[mt][1], ah[mt][2], ah[mt][3],
                             bhf[nt][0], bhf[nt][1]);
                    mma16816(acc[mt][nt], ah[mt][0], ah[mt][1], ah[mt][2], ah[mt][3],
                             blf[nt][0], blf[nt][1]);
                }
        }
        __syncthreads();
    }

#pragma unroll
    for (int mt = 0; mt < 4; mt++) {
        int rl = wm * 64 + mt * 16 + grp;
        int r = m0 + rl;
        float iv0 = sinv[rl], iv1 = sinv[rl + 8];
#pragma unroll
        for (int nt = 0; nt < 2; nt++) {
            int d = wn * 16 + nt * 8 + tig * 2;
            size_t o = ((size_t)(b * SEQ + r)) * DM + h * 64 + d;
            float x0 = acc[mt][nt].x * iv0, x1 = acc[mt][nt].y * iv0;
            float x2 = acc[mt][nt].z * iv1, x3 = acc[mt][nt].w * iv1;
            *(__half2*)&Chi[o]          = __floats2half2_rn(x0, x1);
            *(__half2*)&Chi[o + 8 * DM] = __floats2half2_rn(x2, x3);
            *(__half2*)&Clo[o]          = __floats2half2_rn(residf(x0), residf(x1));
            *(__half2*)&Clo[o + 8 * DM] = __floats2half2_rn(residf(x2), residf(x3));
        }
    }
}

// ---------------------------------------------------------------------------
// Expand: write final full-width attn = mask ? 0 : p/rowsum. 1 block/row.
// ---------------------------------------------------------------------------
__global__ __launch_bounds__(256) void expand_kernel(
    const __half* __restrict__ Phi,
    const float* __restrict__ rowsum, const int* __restrict__ fwd,
    float* __restrict__ attn)
{
    const int row = blockIdx.x;
    const int b = row >> 15;               // NH*SEQ = 32768
    const float inv = 1.0f / rowsum[row];
    const __half* ph = Phi + (size_t)row * SEQ;
    const int* fw = fwd + b * SEQ;
    float* o = attn + (size_t)row * SEQ;

    const int j0 = threadIdx.x * 8;
    float vals[8];
#pragma unroll
    for (int t = 0; t < 8; t++) {
        int f = fw[j0 + t];
        vals[t] = (f >= 0) ? __half2float(ph[f]) * inv : 0.f;
    }
    *(float4*)(o + j0)     = make_float4(vals[0], vals[1], vals[2], vals[3]);
    *(float4*)(o + j0 + 4) = make_float4(vals[4], vals[5], vals[6], vals[7]);
}

// ---------------------------------------------------------------------------
// Launcher — forked-stream graph: transpose_v ∥ logits, expand ∥ (av, out_gemm)
// ---------------------------------------------------------------------------
extern "C" void kernel_launch(void* const* d_in, const int* in_sizes, int n_in,
                              void* d_out, int out_size)
{
    const float* v    = (const float*)d_in[0];
    const float* k    = (const float*)d_in[1];
    const float* q    = (const float*)d_in[2];
    const int*   mask = (const int*)  d_in[3];
    const float* Wq = (const float*)d_in[4];
    const float* bq = (const float*)d_in[5];
    const float* Wk = (const float*)d_in[6];
    const float* bk = (const float*)d_in[7];
    const float* Wv = (const float*)d_in[8];
    const float* bv = (const float*)d_in[9];
    const float* Wo = (const float*)d_in[10];
    const float* bo = (const float*)d_in[11];
    float* out = (float*)d_out;

    __half *Xhi, *Xlo, *QKVhi, *QKVlo, *Vthi, *Vtlo, *Cxhi, *Cxlo, *WThi, *WTlo;
    __half *Phi;
    float *attnScratch, *partialp, *rowsump;
    int *fwdp, *cidxp, *cntp;
    cudaGetSymbolAddress((void**)&Xhi, g_Xhi);
    cudaGetSymbolAddress((void**)&Xlo, g_Xlo);
    cudaGetSymbolAddress((void**)&QKVhi, g_QKVhi);
    cudaGetSymbolAddress((void**)&QKVlo, g_QKVlo);
    cudaGetSymbolAddress((void**)&Vthi, g_Vthi);
    cudaGetSymbolAddress((void**)&Vtlo, g_Vtlo);
    cudaGetSymbolAddress((void**)&Cxhi, g_Cxhi);
    cudaGetSymbolAddress((void**)&Cxlo, g_Cxlo);
    cudaGetSymbolAddress((void**)&WThi, g_WThi);
    cudaGetSymbolAddress((void**)&WTlo, g_WTlo);
    cudaGetSymbolAddress((void**)&Phi, g_Phi);
    cudaGetSymbolAddress((void**)&attnScratch, g_attn);
    cudaGetSymbolAddress((void**)&partialp, g_partial);
    cudaGetSymbolAddress((void**)&rowsump, g_rowsum);
    cudaGetSymbolAddress((void**)&fwdp, g_fwd);
    cudaGetSymbolAddress((void**)&cidxp, g_cidx);
    cudaGetSymbolAddress((void**)&cntp, g_cnt);

    cudaFuncSetAttribute(qkv_gemm_kernel,
                         cudaFuncAttributeMaxDynamicSharedMemorySize, GEMM_SMEM);
    cudaFuncSetAttribute(out_gemm_kernel,
                         cudaFuncAttributeMaxDynamicSharedMemorySize, GEMM_SMEM);
    cudaFuncSetAttribute(logits_kernel,
                         cudaFuncAttributeMaxDynamicSharedMemorySize, LOGITS_SMEM);
    cudaFuncSetAttribute(av_kernel,
                         cudaFuncAttributeMaxDynamicSharedMemorySize, AV_SMEM);

    const size_t FINAL_ELEMS = (size_t)BS_ROWS * DM;
    const size_t ATTN_ELEMS  = (size_t)BH * SEQ * SEQ;
    const size_t asz = (size_t)BS_ROWS * DM;
    float* attnp = ((size_t)out_size >= FINAL_ELEMS + ATTN_ELEMS)
                       ? (out + FINAL_ELEMS) : attnScratch;

    // Fork machinery (created per call, never destroyed; no device allocs).
    cudaStream_t s2 = 0;
    bool forked = (cudaStreamCreateWithFlags(&s2, cudaStreamNonBlocking) == cudaSuccess);
    cudaEvent_t eFork = 0, eW = 0, eQkv = 0, eVt = 0, eRs = 0, eJoin = 0;
    if (forked) {
        forked = (cudaEventCreateWithFlags(&eFork, cudaEventDisableTiming) == cudaSuccess) &&
                 (cudaEventCreateWithFlags(&eW,    cudaEventDisableTiming) == cudaSuccess) &&
                 (cudaEventCreateWithFlags(&eQkv,  cudaEventDisableTiming) == cudaSuccess) &&
                 (cudaEventCreateWithFlags(&eVt,   cudaEventDisableTiming) == cudaSuccess) &&
                 (cudaEventCreateWithFlags(&eRs,   cudaEventDisableTiming) == cudaSuccess) &&
                 (cudaEventCreateWithFlags(&eJoin, cudaEventDisableTiming) == cudaSuccess);
    }

    if (forked) {
        cudaEventRecord(eFork, 0);
        cudaStreamWaitEvent(s2, eFork, 0);

        mask_scan_kernel<<<BATCH, 1024, 0, s2>>>(mask, fwdp, cidxp, cntp);
        transpose_split_kernel<<<dim3(32, 32, 4), 256, 0, s2>>>(Wq, Wk, Wv, Wo, WThi, WTlo);
        cudaEventRecord(eW, s2);
        split_inputs_kernel<<<dim3(4096, 3), 256>>>(q, k, v, Xhi, Xlo);

        cudaStreamWaitEvent(0, eW, 0);
        qkv_gemm_kernel<<<dim3(8, 32, 3), 256, GEMM_SMEM>>>(
            Xhi, Xlo, WThi, WTlo, bq, bk, bv, QKVhi, QKVlo);
        cudaEventRecord(eQkv, 0);

        cudaStreamWaitEvent(s2, eQkv, 0);
        transpose_v_kernel<<<dim3(32, 128), 256, 0, s2>>>(
            QKVhi + 2 * asz, QKVlo + 2 * asz, fwdp, Vthi, Vtlo);
        cudaEventRecord(eVt, s2);

        logits_kernel<<<dim3(16, 16, BH), 256, LOGITS_SMEM>>>(
            QKVhi, QKVlo, QKVhi + asz, QKVlo + asz, cidxp, cntp, Phi, partialp);
        reduce_sums_kernel<<<(BH * SEQ) / 256, 256>>>(partialp, rowsump);
        cudaEventRecord(eRs, 0);

        cudaStreamWaitEvent(s2, eRs, 0);
        expand_kernel<<<BH * SEQ, 256, 0, s2>>>(Phi, rowsump, fwdp, attnp);
        cudaEventRecord(eJoin, s2);

        cudaStreamWaitEvent(0, eVt, 0);
        av_kernel<<<dim3(16, BH), 256, AV_SMEM>>>(
            Phi, Vthi, Vtlo, rowsump, cntp, Cxhi, Cxlo);
        out_gemm_kernel<<<dim3(8, 32), 256, GEMM_SMEM>>>(
            Cxhi, Cxlo, WThi, WTlo, bo, out);

        cudaStreamWaitEvent(0, eJoin, 0);
    } else {
        mask_scan_kernel<<<BATCH, 1024>>>(mask, fwdp, cidxp, cntp);
        split_inputs_kernel<<<dim3(4096, 3), 256>>>(q, k, v, Xhi, Xlo);
        transpose_split_kernel<<<dim3(32, 32, 4), 256>>>(Wq, Wk, Wv, Wo, WThi, WTlo);
        qkv_gemm_kernel<<<dim3(8, 32, 3), 256, GEMM_SMEM>>>(
            Xhi, Xlo, WThi, WTlo, bq, bk, bv, QKVhi, QKVlo);
        transpose_v_kernel<<<dim3(32, 128), 256>>>(
            QKVhi + 2 * asz, QKVlo + 2 * asz, fwdp, Vthi, Vtlo);
        logits_kernel<<<dim3(16, 16, BH), 256, LOGITS_SMEM>>>(
            QKVhi, QKVlo, QKVhi + asz, QKVlo + asz, cidxp, cntp, Phi, partialp);
        reduce_sums_kernel<<<(BH * SEQ) / 256, 256>>>(partialp, rowsump);
        av_kernel<<<dim3(16, BH), 256, AV_SMEM>>>(
            Phi, Vthi, Vtlo, rowsump, cntp, Cxhi, Cxlo);
        expand_kernel<<<BH * SEQ, 256>>>(Phi, rowsump, fwdp, attnp);
        out_gemm_kernel<<<dim3(8, 32), 256, GEMM_SMEM>>>(
            Cxhi, Cxlo, WThi, WTlo, bo, out);
    }
}

// round 15
// speedup vs baseline: 1.1596x; 1.0066x over previous
#include <cuda_runtime.h>
#include <cuda_fp16.h>
#include <math.h>
#include <stdint.h>
#include <stddef.h>

#define DM 1024
#define NH 16
#define DEPTH 64
#define BATCH 2
#define SEQ 2048
#define BS_ROWS 4096
#define BH 32

// ---------------------------------------------------------------------------
// Scratch (__device__ globals; allocation-free rule). Zero-initialized.
// ---------------------------------------------------------------------------
__device__ __half g_Xhi[3][(size_t)BS_ROWS * DM];
__device__ __half g_Xlo[3][(size_t)BS_ROWS * DM];
__device__ __half g_QKVhi[3][(size_t)BS_ROWS * DM];
__device__ __half g_QKVlo[3][(size_t)BS_ROWS * DM];
__device__ __half g_Vthi[(size_t)BH * DEPTH * SEQ];   // [bh][d][compact s]
__device__ __half g_Vtlo[(size_t)BH * DEPTH * SEQ];
__device__ __half g_Cxhi[(size_t)BS_ROWS * DM];
__device__ __half g_Cxlo[(size_t)BS_ROWS * DM];
__device__ __half g_WThi[4][(size_t)DM * DM];
__device__ __half g_WTlo[4][(size_t)DM * DM];
__device__ __half g_Phi[(size_t)BH * SEQ * SEQ];      // exp(p) fp16, compact cols
__device__ float  g_attn[(size_t)BH * SEQ * SEQ];     // fallback full attn
__device__ float  g_partial[(size_t)BH * SEQ * 16];
__device__ float  g_rowsum[(size_t)BH * SEQ];
__device__ int    g_fwd[BATCH * SEQ];
__device__ int    g_cidx[BATCH * SEQ];
__device__ int    g_cnt[BATCH];

// ---------------------------------------------------------------------------
// Helpers
// ---------------------------------------------------------------------------
__device__ __forceinline__ float residf(float x) {
    return x - __half2float(__float2half_rn(x));
}
__device__ __forceinline__ uint32_t smem_u32(const void* p) {
    return (uint32_t)__cvta_generic_to_shared(p);
}
// FMA/ALU-pipe exp (fp32, rel err ~1e-7). Validated numerically in R9.
__device__ __forceinline__ float exp_fma(float x) {
    float t = x * 1.44269504088896341f;
    float r = t + 12582912.0f;                      // 1.5 * 2^23
    int   n = __float_as_int(r) - 0x4B400000;
    float f = t - (r - 12582912.0f);                // f in [-0.5, 0.5]
    float p = 1.5403530393e-4f;
    p = fmaf(p, f, 1.3333558146e-3f);
    p = fmaf(p, f, 9.6181291076e-3f);
    p = fmaf(p, f, 5.5504108665e-2f);
    p = fmaf(p, f, 2.4022650696e-1f);
    p = fmaf(p, f, 6.9314718056e-1f);
    p = fmaf(p, f, 1.0f);
    return __int_as_float(__float_as_int(p) + (n << 23));
}
#define CP16(dst_u32, src_ptr) \
    asm volatile("cp.async.cg.shared.global [%0], [%1], 16;\n" :: "r"(dst_u32), "l"(src_ptr))
#define CP_COMMIT asm volatile("cp.async.commit_group;\n" ::: "memory")
#define CP_WAIT0  asm volatile("cp.async.wait_group 0;\n" ::: "memory")

__device__ __forceinline__ void mma16816(float4& d,
    uint32_t a0, uint32_t a1, uint32_t a2, uint32_t a3,
    uint32_t b0, uint32_t b1)
{
    asm volatile(
        "mma.sync.aligned.m16n8k16.row.col.f32.f16.f16.f32 "
        "{%0,%1,%2,%3},{%4,%5,%6,%7},{%8,%9},{%0,%1,%2,%3};\n"
        : "+f"(d.x), "+f"(d.y), "+f"(d.z), "+f"(d.w)
        : "r"(a0), "r"(a1), "r"(a2), "r"(a3), "r"(b0), "r"(b1));
}

__device__ __forceinline__ void ldsm4(uint32_t& r0, uint32_t& r1,
                                      uint32_t& r2, uint32_t& r3, uint32_t addr)
{
    asm volatile("ldmatrix.sync.aligned.m8n8.x4.shared.b16 {%0,%1,%2,%3}, [%4];\n"
                 : "=r"(r0), "=r"(r1), "=r"(r2), "=r"(r3) : "r"(addr));
}

__device__ __forceinline__ void lda_x4(uint32_t* f, uint32_t sbase, int lp_bytes,
                                       int rbase, int kb0, int lane)
{
    int seg = lane >> 3, rw = lane & 7;
    int row = rbase + rw + ((seg & 1) << 3);
    int col = kb0 + ((seg >> 1) << 3);
    ldsm4(f[0], f[1], f[2], f[3], sbase + row * lp_bytes + col * 2);
}
__device__ __forceinline__ void ldb_x4(uint32_t* f0, uint32_t* f1, uint32_t sbase,
                                       int lp_bytes, int cbase, int kb0, int lane)
{
    int seg = lane >> 3, rw = lane & 7;
    int row = cbase + rw + ((seg >> 1) << 3);
    int col = kb0 + ((seg & 1) << 3);
    ldsm4(f0[0], f0[1], f1[0], f1[1], sbase + row * lp_bytes + col * 2);
}

// ---------------------------------------------------------------------------
// Mask scan: per batch, prefix-compact unmasked columns. 1 block/batch.
// ---------------------------------------------------------------------------
__global__ __launch_bounds__(1024) void mask_scan_kernel(
    const int* __restrict__ mask, int* __restrict__ fwd,
    int* __restrict__ cidx, int* __restrict__ cnt)
{
    __shared__ int sa[1024], sb[1024];
    const int b = blockIdx.x, t = threadIdx.x;
    const int j0 = 2 * t, j1 = 2 * t + 1;
    const int m0 = (mask[b * SEQ + j0] == 0);
    const int m1 = (mask[b * SEQ + j1] == 0);
    sa[t] = m0 + m1;
    __syncthreads();
    int* src = sa; int* dst = sb;
    for (int off = 1; off < 1024; off <<= 1) {
        int v = src[t] + ((t >= off) ? src[t - off] : 0);
        dst[t] = v;
        __syncthreads();
        int* tmp = src; src = dst; dst = tmp;
    }
    const int incl = src[t];
    const int excl = incl - (m0 + m1);
    fwd[b * SEQ + j0] = m0 ? excl : -1;
    fwd[b * SEQ + j1] = m1 ? (excl + m0) : -1;
    if (m0) cidx[b * SEQ + excl] = j0;
    if (m1) cidx[b * SEQ + excl + m0] = j1;
    const int total = src[1023];
    if (t == 0) cnt[b] = total;
    __syncthreads();
    for (int s = t; s < SEQ; s += 1024)
        if (s >= total) cidx[b * SEQ + s] = 0;
}

// ---------------------------------------------------------------------------
// Elementwise split of q/k/v inputs
// ---------------------------------------------------------------------------
__global__ __launch_bounds__(256) void split_inputs_kernel(
    const float* __restrict__ q, const float* __restrict__ k,
    const float* __restrict__ v, __half* __restrict__ Xhi, __half* __restrict__ Xlo)
{
    const int z = blockIdx.y;
    const float* src = (z == 0) ? q : (z == 1) ? k : v;
    const size_t i = ((size_t)blockIdx.x * 256 + threadIdx.x) * 4;
    const size_t o = (size_t)z * BS_ROWS * DM + i;
    float4 x = *(const float4*)(src + i);
    *(__half2*)(Xhi + o)     = __floats2half2_rn(x.x, x.y);
    *(__half2*)(Xhi + o + 2) = __floats2half2_rn(x.z, x.w);
    *(__half2*)(Xlo + o)     = __floats2half2_rn(residf(x.x), residf(x.y));
    *(__half2*)(Xlo + o + 2) = __floats2half2_rn(residf(x.z), residf(x.w));
}

// ---------------------------------------------------------------------------
// Weight transpose+split
// ---------------------------------------------------------------------------
__global__ __launch_bounds__(256) void transpose_split_kernel(
    const float* __restrict__ Wq, const float* __restrict__ Wk,
    const float* __restrict__ Wv, const float* __restrict__ Wo,
    __half* __restrict__ ThiB, __half* __restrict__ TloB)
{
    const int z = blockIdx.z;
    const float* W = (z == 0) ? Wq : (z == 1) ? Wk : (z == 2) ? Wv : Wo;
    __half* Thi = ThiB + (size_t)z * DM * DM;
    __half* Tlo = TloB + (size_t)z * DM * DM;

    __shared__ float tile[32][33];
    const int k0 = blockIdx.y * 32, n0 = blockIdx.x * 32;
    const int tx = threadIdx.x & 31, ty = threadIdx.x >> 5;
#pragma unroll
    for (int i = 0; i < 4; i++) {
        int kk = ty + i * 8;
        tile[kk][tx] = W[(size_t)(k0 + kk) * DM + n0 + tx];
    }
    __syncthreads();
#pragma unroll
    for (int i = 0; i < 4; i++) {
        int nn = ty + i * 8;
        float x = tile[tx][nn];
        __half hi = __float2half_rn(x);
        Thi[(size_t)(n0 + nn) * DM + k0 + tx] = hi;
        Tlo[(size_t)(n0 + nn) * DM + k0 + tx] = __float2half_rn(x - __half2float(hi));
    }
}

// ---------------------------------------------------------------------------
// V transpose with compaction: V [4096][1024] -> Vt [bh][64][compact s]
// ---------------------------------------------------------------------------
__global__ __launch_bounds__(256) void transpose_v_kernel(
    const __half* __restrict__ Vhi, const __half* __restrict__ Vlo,
    const int* __restrict__ fwd,
    __half* __restrict__ Thi, __half* __restrict__ Tlo)
{
    __shared__ __half thi[32][33], tlo[32][33];
    const int n0 = blockIdx.x * 32;
    const int s0 = blockIdx.y * 32;
    const int tx = threadIdx.x & 31, ty = threadIdx.x >> 5;
#pragma unroll
    for (int i = 0; i < 4; i++) {
        int r = ty + i * 8;
        thi[r][tx] = Vhi[(size_t)(s0 + r) * DM + n0 + tx];
        tlo[r][tx] = Vlo[(size_t)(s0 + r) * DM + n0 + tx];
    }
    __syncthreads();
    const int b = s0 >> 11;
    const int slot = fwd[b * SEQ + (s0 & 2047) + tx];
    if (slot >= 0) {
#pragma unroll
        for (int i = 0; i < 4; i++) {
            int nn = ty + i * 8;
            int gn = n0 + nn;
            int h = gn >> 6, d = gn & 63;
            size_t orow = ((size_t)(b * NH + h) * DEPTH + d) * SEQ + slot;
            Thi[orow] = thi[tx][nn];
            Tlo[orow] = tlo[tx][nn];
        }
    }
}

// ---------------------------------------------------------------------------
// Double-buffered split-fp16 GEMM (projections). BM=BN=128, BK=32.
// Single barrier per k-iteration: wait -> sync -> issue next loads -> compute.
// ---------------------------------------------------------------------------
#define GSTAGE 40960
#define GEMM_SMEM (2 * GSTAGE)

__device__ __forceinline__ void gemm_load_stage(uint32_t smbase, int s,
    const __half* AhiG, const __half* AloG,
    const __half* BhiG, const __half* BloG,
    int m0, int n0, int k0, int tid)
{
    uint32_t sb = smbase + s * GSTAGE;
#pragma unroll
    for (int t = 0; t < 2; t++) {
        int id = tid * 2 + t;
        int r = id >> 2, q = id & 3;
        uint32_t off = r * 80 + q * 16;
        const size_t ga = (size_t)(m0 + r) * DM + k0 + q * 8;
        const size_t gb = (size_t)(n0 + r) * DM + k0 + q * 8;
        CP16(sb + off,         AhiG + ga);
        CP16(sb + 10240 + off, AloG + ga);
        CP16(sb + 20480 + off, BhiG + gb);
        CP16(sb + 30720 + off, BloG + gb);
    }
}

template<bool OUT_F32>
__device__ __forceinline__ void gemm_core(
    const __half* __restrict__ AhiG, const __half* __restrict__ AloG,
    const __half* __restrict__ BhiG, const __half* __restrict__ BloG,
    const float* __restrict__ bias,
    float* __restrict__ Cf, __half* __restrict__ Chi, __half* __restrict__ Clo)
{
    extern __shared__ char dsm[];
    const uint32_t smbase = smem_u32(dsm);

    const int tid = threadIdx.x;
    const int m0 = blockIdx.y * 128, n0 = blockIdx.x * 128;
    const int lane = tid & 31, wid = tid >> 5;
    const int wm = wid >> 2, wn = wid & 3;
    const int grp = lane >> 2, tig = lane & 3;

    float4 acc[4][4];
#pragma unroll
    for (int i = 0; i < 4; i++)
#pragma unroll
        for (int j = 0; j < 4; j++) acc[i][j] = make_float4(0.f, 0.f, 0.f, 0.f);

    gemm_load_stage(smbase, 0, AhiG, AloG, BhiG, BloG, m0, n0, 0, tid);
    CP_COMMIT;

    for (int kt = 0; kt < 32; kt++) {
        CP_WAIT0;
        __syncthreads();
        if (kt + 1 < 32) {
            gemm_load_stage(smbase, (kt + 1) & 1, AhiG, AloG, BhiG, BloG,
                            m0, n0, (kt + 1) * 32, tid);
            CP_COMMIT;
        }

        const uint32_t sb = smbase + (kt & 1) * GSTAGE;
        const uint32_t ah_b = sb, al_b = sb + 10240, bh_b = sb + 20480, bl_b = sb + 30720;
#pragma unroll
        for (int ks = 0; ks < 2; ks++) {
            const int kb0 = ks * 16;
            uint32_t ah[4][4], al[4][4];
#pragma unroll
            for (int mt = 0; mt < 4; mt++) {
                lda_x4(ah[mt], ah_b, 80, wm * 64 + mt * 16, kb0, lane);
                lda_x4(al[mt], al_b, 80, wm * 64 + mt * 16, kb0, lane);
            }
            uint32_t bhf[4][2], blf[4][2];
#pragma unroll
            for (int p = 0; p < 2; p++) {
                ldb_x4(bhf[2 * p], bhf[2 * p + 1], bh_b, 80, wn * 32 + p * 16, kb0, lane);
                ldb_x4(blf[2 * p], blf[2 * p + 1], bl_b, 80, wn * 32 + p * 16, kb0, lane);
            }
#pragma unroll
            for (int mt = 0; mt < 4; mt++)
#pragma unroll
                for (int nt = 0; nt < 4; nt++) {
                    mma16816(acc[mt][nt], ah[mt][0], ah[mt][1], ah[mt][2], ah[mt][3],
                             bhf[nt][0], bhf[nt][1]);
                    mma16816(acc[mt][nt], ah[mt][0], ah[mt][1], ah[mt][2], ah[mt][3],
                             blf[nt][0], blf[nt][1]);
                    mma16816(acc[mt][nt], al[mt][0], al[mt][1], al[mt][2], al[mt][3],
                             bhf[nt][0], bhf[nt][1]);
                }
        }
    }

#pragma unroll
    for (int mt = 0; mt < 4; mt++) {
        int r = m0 + wm * 64 + mt * 16 + grp;
#pragma unroll
        for (int nt = 0; nt < 4; nt++) {
            int c = n0 + wn * 32 + nt * 8 + tig * 2;
            float bx = bias[c], by = bias[c + 1];
            float x0 = acc[mt][nt].x + bx, x1 = acc[mt][nt].y + by;
            float x2 = acc[mt][nt].z + bx, x3 = acc[mt][nt].w + by;
            if (OUT_F32) {
                *(float2*)&Cf[(size_t)r * DM + c]       = make_float2(x0, x1);
                *(float2*)&Cf[(size_t)(r + 8) * DM + c] = make_float2(x2, x3);
            } else {
                *(__half2*)&Chi[(size_t)r * DM + c]       = __floats2half2_rn(x0, x1);
                *(__half2*)&Chi[(size_t)(r + 8) * DM + c] = __floats2half2_rn(x2, x3);
                *(__half2*)&Clo[(size_t)r * DM + c]       = __floats2half2_rn(residf(x0), residf(x1));
                *(__half2*)&Clo[(size_t)(r + 8) * DM + c] = __floats2half2_rn(residf(x2), residf(x3));
            }
        }
    }
}

__global__ __launch_bounds__(256) void qkv_gemm_kernel(
    const __half* __restrict__ Xhi, const __half* __restrict__ Xlo,
    const __half* __restrict__ WThi, const __half* __restrict__ WTlo,
    const float* __restrict__ bq, const float* __restrict__ bk,
    const float* __restrict__ bv,
    __half* __restrict__ QKVhi, __half* __restrict__ QKVlo)
{
    const int z = blockIdx.z;
    const size_t asz = (size_t)BS_ROWS * DM, wsz = (size_t)DM * DM;
    const float* bias = (z == 0) ? bq : (z == 1) ? bk : bv;
    gemm_core<false>(Xhi + z * asz, Xlo + z * asz, WThi + z * wsz, WTlo + z * wsz,
                     bias, nullptr, QKVhi + z * asz, QKVlo + z * asz);
}

__global__ __launch_bounds__(256) void out_gemm_kernel(
    const __half* __restrict__ Cxhi, const __half* __restrict__ Cxlo,
    const __half* __restrict__ WThi, const __half* __restrict__ WTlo,
    const float* __restrict__ bo, float* __restrict__ out)
{
    const size_t wsz = (size_t)DM * DM;
    gemm_core<true>(Cxhi, Cxlo, WThi + 3 * wsz, WTlo + 3 * wsz, bo,
                    out, nullptr, nullptr);
}

// ---------------------------------------------------------------------------
// Logits over COMPACT columns: p = exp(0.125*QK), stored fp16 (no residual).
// Exp split 75% MUFU / 25% FMA-pipe poly (balance point per pipe model).
// ---------------------------------------------------------------------------
#define LP 72
#define LOGITS_SMEM (4 * 128 * LP * 2 + 128 * 4 * 4)

__global__ __launch_bounds__(256) void logits_kernel(
    const __half* __restrict__ Qhi, const __half* __restrict__ Qlo,
    const __half* __restrict__ Khi, const __half* __restrict__ Klo,
    const int* __restrict__ cidx, const int* __restrict__ cnt,
    __half* __restrict__ Phi, float* __restrict__ partial)
{
    extern __shared__ __half sm[];
    __half (*Qh)[LP] = (__half(*)[LP])sm;
    __half (*Ql)[LP] = (__half(*)[LP])(sm + 128 * LP);
    __half (*Kh)[LP] = (__half(*)[LP])(sm + 2 * 128 * LP);
    __half (*Kl)[LP] = (__half(*)[LP])(sm + 3 * 128 * LP);
    float* sums = (float*)(sm + 4 * 128 * LP);

    const int tid = threadIdx.x;
    const int n0 = blockIdx.x * 128, m0 = blockIdx.y * 128;
    const int bh = blockIdx.z, b = bh >> 4, h = bh & 15;
    const int Mb = cnt[b];

    if (n0 >= Mb) {
        if (tid < 128)
            partial[((size_t)bh * SEQ + m0 + tid) * 16 + blockIdx.x] = 0.f;
        return;
    }

    const size_t hbase = (size_t)b * SEQ * DM + h * 64;
    const int* cb = cidx + b * SEQ;

#pragma unroll
    for (int t = 0; t < 16; t++) {
        int id = tid + 256 * t;
        int arr = id >> 10, rem = id & 1023;
        int r = rem >> 3, q = rem & 7;
        const __half* src = (arr == 0) ? Qhi : (arr == 1) ? Qlo : (arr == 2) ? Khi : Klo;
        __half (*dst)[LP] = (arr == 0) ? Qh : (arr == 1) ? Ql : (arr == 2) ? Kh : Kl;
        int rphys;
        if (arr < 2) rphys = m0 + r;
        else {
            int jr = n0 + r;
            rphys = (jr < Mb) ? cb[jr] : 0;
        }
        uint4 v = *(const uint4*)(src + hbase + (size_t)rphys * DM + q * 8);
        *(uint2*)&dst[r][q * 8]     = make_uint2(v.x, v.y);
        *(uint2*)&dst[r][q * 8 + 4] = make_uint2(v.z, v.w);
    }
    __syncthreads();

    const int lane = tid & 31, wid = tid >> 5;
    const int wm = wid >> 2, wn = wid & 3;
    const int grp = lane >> 2, tig = lane & 3;
    const uint32_t qh_b = smem_u32(Qh), ql_b = smem_u32(Ql);
    const uint32_t kh_b = smem_u32(Kh), kl_b = smem_u32(Kl);

    float4 acc[4][4];
#pragma unroll
    for (int i = 0; i < 4; i++)
#pragma unroll
        for (int j = 0; j < 4; j++) acc[i][j] = make_float4(0.f, 0.f, 0.f, 0.f);

#pragma unroll
    for (int ks = 0; ks < 4; ks++) {
        const int kb0 = ks * 16;
        uint32_t ah[4][4], al[4][4];
#pragma unroll
        for (int mt = 0; mt < 4; mt++) {
            lda_x4(ah[mt], qh_b, 144, wm * 64 + mt * 16, kb0, lane);
            lda_x4(al[mt], ql_b, 144, wm * 64 + mt * 16, kb0, lane);
        }
        uint32_t bhf[4][2], blf[4][2];
#pragma unroll
        for (int p = 0; p < 2; p++) {
            ldb_x4(bhf[2 * p], bhf[2 * p + 1], kh_b, 144, wn * 32 + p * 16, kb0, lane);
            ldb_x4(blf[2 * p], blf[2 * p + 1], kl_b, 144, wn * 32 + p * 16, kb0, lane);
        }
#pragma unroll
        for (int mt = 0; mt < 4; mt++)
#pragma unroll
            for (int nt = 0; nt < 4; nt++) {
                mma16816(acc[mt][nt], ah[mt][0], ah[mt][1], ah[mt][2], ah[mt][3],
                         bhf[nt][0], bhf[nt][1]);
                mma16816(acc[mt][nt], ah[mt][0], ah[mt][1], ah[mt][2], ah[mt][3],
                         blf[nt][0], blf[nt][1]);
                mma16816(acc[mt][nt], al[mt][0], al[mt][1], al[mt][2], al[mt][3],
                         bhf[nt][0], bhf[nt][1]);
            }
    }

    float rs0[4], rs1[4];
#pragma unroll
    for (int mt = 0; mt < 4; mt++) { rs0[mt] = 0.f; rs1[mt] = 0.f; }

#pragma unroll
    for (int mt = 0; mt < 4; mt++) {
        int r = m0 + wm * 64 + mt * 16 + grp;
        __half* oh0 = Phi + ((size_t)bh * SEQ + r) * SEQ;
        __half* oh1 = oh0 + (size_t)8 * SEQ;
#pragma unroll
        for (int nt = 0; nt < 4; nt++) {
            int j = n0 + wn * 32 + nt * 8 + tig * 2;
            bool v0 = (j < Mb), v1 = (j + 1 < Mb);
            float4 a = acc[mt][nt];
            // 3 of 4 exps on MUFU, 1 of 4 on the FMA/ALU pipes (balance point).
            float p0 = v0 ? __expf(a.x * 0.125f)  : 0.f;
            float p1 = v1 ? __expf(a.y * 0.125f)  : 0.f;
            float p2 = v0 ? __expf(a.z * 0.125f)  : 0.f;
            float p3 = v1 ? exp_fma(a.w * 0.125f) : 0.f;
            *(__half2*)(oh0 + j) = __floats2half2_rn(p0, p1);
            *(__half2*)(oh1 + j) = __floats2half2_rn(p2, p3);
            rs0[mt] += p0 + p1;
            rs1[mt] += p2 + p3;
        }
    }
#pragma unroll
    for (int mt = 0; mt < 4; mt++) {
        float s0 = rs0[mt], s1 = rs1[mt];
        s0 += __shfl_xor_sync(0xffffffffu, s0, 1);
        s0 += __shfl_xor_sync(0xffffffffu, s0, 2);
        s1 += __shfl_xor_sync(0xffffffffu, s1, 1);
        s1 += __shfl_xor_sync(0xffffffffu, s1, 2);
        if (tig == 0) {
            int rl = wm * 64 + mt * 16 + grp;
            sums[(size_t)rl * 4 + wn] = s0;
            sums[(size_t)(rl + 8) * 4 + wn] = s1;
        }
    }
    __syncthreads();
    if (tid < 128) {
        float tot = (sums[tid * 4 + 0] + sums[tid * 4 + 1]) +
                    (sums[tid * 4 + 2] + sums[tid * 4 + 3]);
        partial[((size_t)bh * SEQ + m0 + tid) * 16 + blockIdx.x] = tot;
    }
}

__global__ __launch_bounds__(256) void reduce_sums_kernel(
    const float* __restrict__ partial, float* __restrict__ rowsum)
{
    int i = blockIdx.x * 256 + threadIdx.x;
    const float4* p = (const float4*)(partial + (size_t)i * 16);
    float4 a = p[0], b = p[1], c = p[2], d = p[3];
    rowsum[i] = ((a.x + a.y) + (a.z + a.w)) + ((b.x + b.y) + (b.z + b.w)) +
                ((c.x + c.y) + (c.z + c.w)) + ((d.x + d.y) + (d.z + d.w));
}

// ---------------------------------------------------------------------------
// AV over compact K-dim: ctx = (P @ Vc) / rowsum. P is fp16-only now.
// BM=128, BN=64, BK=64. 2 mma terms per tile (P·Vh + P·Vl).
// ---------------------------------------------------------------------------
#define AV_SMEM (128 * LP * 2 + 2 * 64 * LP * 2 + 128 * 4)

__global__ __launch_bounds__(256) void av_kernel(
    const __half* __restrict__ Phi,
    const __half* __restrict__ Vthi, const __half* __restrict__ Vtlo,
    const float* __restrict__ rowsum, const int* __restrict__ cnt,
    __half* __restrict__ Chi, __half* __restrict__ Clo)
{
    extern __shared__ char smraw[];
    __half (*Ah)[LP] = (__half(*)[LP])smraw;
    __half (*Vh)[LP] = (__half(*)[LP])(smraw + 128 * LP * 2);
    __half (*Vl)[LP] = (__half(*)[LP])(smraw + 128 * LP * 2 + 64 * LP * 2);
    float* sinv = (float*)(smraw + 128 * LP * 2 + 2 * 64 * LP * 2);

    const int tid = threadIdx.x;
    const int m0 = blockIdx.x * 128;
    const int bh = blockIdx.y, b = bh >> 4, h = bh & 15;
    const int Mb = cnt[b];

    if (tid < 128) sinv[tid] = 1.0f / rowsum[(size_t)bh * SEQ + m0 + tid];
    __syncthreads();

    const int lane = tid & 31, wid = tid >> 5;
    const int wm = wid >> 2, wn = wid & 3;
    const int grp = lane >> 2, tig = lane & 3;
    const uint32_t ah_b = smem_u32(Ah);
    const uint32_t vh_b = smem_u32(Vh), vl_b = smem_u32(Vl);

    float4 acc[4][2];
#pragma unroll
    for (int i = 0; i < 4; i++)
#pragma unroll
        for (int j = 0; j < 2; j++) acc[i][j] = make_float4(0.f, 0.f, 0.f, 0.f);

    const size_t prow = (size_t)bh * SEQ + m0;
    const size_t vtb = (size_t)bh * DEPTH * SEQ;

    for (int k0 = 0; k0 < Mb; k0 += 64) {
        // P tile: 128 rows x 64 cols fp16 = 1024 uint4 / 256 thr
#pragma unroll
        for (int t = 0; t < 4; t++) {
            int id = tid + 256 * t;            // 0..1023
            int r = id >> 3, q = id & 7;       // r 0..127, q 0..7
            uint4 v = *(const uint4*)(Phi + (prow + r) * SEQ + k0 + q * 8);
            *(uint2*)&Ah[r][q * 8]     = make_uint2(v.x, v.y);
            *(uint2*)&Ah[r][q * 8 + 4] = make_uint2(v.z, v.w);
        }
        // V tiles: 64 d-rows x 64 cols x {hi,lo} = 1024 uint4 / 256 thr
#pragma unroll
        for (int t = 0; t < 4; t++) {
            int id = tid + 256 * t;            // 0..1023
            int arr = id >> 9, rem = id & 511;
            int r = rem >> 3, q = rem & 7;
            const __half* src = arr ? Vtlo : Vthi;
            __half (*dst)[LP] = arr ? Vl : Vh;
            uint4 v = *(const uint4*)(src + vtb + (size_t)r * SEQ + k0 + q * 8);
            *(uint2*)&dst[r][q * 8]     = make_uint2(v.x, v.y);
            *(uint2*)&dst[r][q * 8 + 4] = make_uint2(v.z, v.w);
        }
        __syncthreads();

#pragma unroll
        for (int ks = 0; ks < 4; ks++) {
            const int kb0 = ks * 16;
            uint32_t ah[4][4];
#pragma unroll
            for (int mt = 0; mt < 4; mt++)
                lda_x4(ah[mt], ah_b, 144, wm * 64 + mt * 16, kb0, lane);
            uint32_t bhf[2][2], blf[2][2];
            ldb_x4(bhf[0], bhf[1], vh_b, 144, wn * 16, kb0, lane);
            ldb_x4(blf[0], blf[1], vl_b, 144, wn * 16, kb0, lane);
#pragma unroll
            for (int mt = 0; mt < 4; mt++)
#pragma unroll
                for (int nt = 0; nt < 2; nt++) {
                    mma16816(acc[mt][nt], ah[mt][0], ah[mt][1], ah[mt][2], ah[mt][3],
                             bhf[nt][0], bhf[nt][1]);
                    mma16816(acc[mt][nt], ah[mt][0], ah[mt][1], ah[mt][2], ah[mt][3],
                             blf[nt][0], blf[nt][1]);
                }
        }
        __syncthreads();
    }

#pragma unroll
    for (int mt = 0; mt < 4; mt++) {
        int rl = wm * 64 + mt * 16 + grp;
        int r = m0 + rl;
        float iv0 = sinv[rl], iv1 = sinv[rl + 8];
#pragma unroll
        for (int nt = 0; nt < 2; nt++) {
            int d = wn * 16 + nt * 8 + tig * 2;
            size_t o = ((size_t)(b * SEQ + r)) * DM + h * 64 + d;
            float x0 = acc[mt][nt].x * iv0, x1 = acc[mt][nt].y * iv0;
            float x2 = acc[mt][nt].z * iv1, x3 = acc[mt][nt].w * iv1;
            *(__half2*)&Chi[o]          = __floats2half2_rn(x0, x1);
            *(__half2*)&Chi[o + 8 * DM] = __floats2half2_rn(x2, x3);
            *(__half2*)&Clo[o]          = __floats2half2_rn(residf(x0), residf(x1));
            *(__half2*)&Clo[o + 8 * DM] = __floats2half2_rn(residf(x2), residf(x3));
        }
    }
}

// ---------------------------------------------------------------------------
// Expand: write final full-width attn = mask ? 0 : p/rowsum. 1 block/row.
// ---------------------------------------------------------------------------
__global__ __launch_bounds__(256) void expand_kernel(
    const __half* __restrict__ Phi,
    const float* __restrict__ rowsum, const int* __restrict__ fwd,
    float* __restrict__ attn)
{
    const int row = blockIdx.x;
    const int b = row >> 15;               // NH*SEQ = 32768
    const float inv = 1.0f / rowsum[row];
    const __half* ph = Phi + (size_t)row * SEQ;
    const int* fw = fwd + b * SEQ;
    float* o = attn + (size_t)row * SEQ;

    const int j0 = threadIdx.x * 8;
    float vals[8];
#pragma unroll
    for (int t = 0; t < 8; t++) {
        int f = fw[j0 + t];
        vals[t] = (f >= 0) ? __half2float(ph[f]) * inv : 0.f;
    }
    *(float4*)(o + j0)     = make_float4(vals[0], vals[1], vals[2], vals[3]);
    *(float4*)(o + j0 + 4) = make_float4(vals[4], vals[5], vals[6], vals[7]);
}

// ---------------------------------------------------------------------------
// Launcher — forked-stream graph: transpose_v ∥ logits, expand ∥ (av, out_gemm)
// ---------------------------------------------------------------------------
extern "C" void kernel_launch(void* const* d_in, const int* in_sizes, int n_in,
                              void* d_out, int out_size)
{
    const float* v    = (const float*)d_in[0];
    const float* k    = (const float*)d_in[1];
    const float* q    = (const float*)d_in[2];
    const int*   mask = (const int*)  d_in[3];
    const float* Wq = (const float*)d_in[4];
    const float* bq = (const float*)d_in[5];
    const float* Wk = (const float*)d_in[6];
    const float* bk = (const float*)d_in[7];
    const float* Wv = (const float*)d_in[8];
    const float* bv = (const float*)d_in[9];
    const float* Wo = (const float*)d_in[10];
    const float* bo = (const float*)d_in[11];
    float* out = (float*)d_out;

    __half *Xhi, *Xlo, *QKVhi, *QKVlo, *Vthi, *Vtlo, *Cxhi, *Cxlo, *WThi, *WTlo;
    __half *Phi;
    float *attnScratch, *partialp, *rowsump;
    int *fwdp, *cidxp, *cntp;
    cudaGetSymbolAddress((void**)&Xhi, g_Xhi);
    cudaGetSymbolAddress((void**)&Xlo, g_Xlo);
    cudaGetSymbolAddress((void**)&QKVhi, g_QKVhi);
    cudaGetSymbolAddress((void**)&QKVlo, g_QKVlo);
    cudaGetSymbolAddress((void**)&Vthi, g_Vthi);
    cudaGetSymbolAddress((void**)&Vtlo, g_Vtlo);
    cudaGetSymbolAddress((void**)&Cxhi, g_Cxhi);
    cudaGetSymbolAddress((void**)&Cxlo, g_Cxlo);
    cudaGetSymbolAddress((void**)&WThi, g_WThi);
    cudaGetSymbolAddress((void**)&WTlo, g_WTlo);
    cudaGetSymbolAddress((void**)&Phi, g_Phi);
    cudaGetSymbolAddress((void**)&attnScratch, g_attn);
    cudaGetSymbolAddress((void**)&partialp, g_partial);
    cudaGetSymbolAddress((void**)&rowsump, g_rowsum);
    cudaGetSymbolAddress((void**)&fwdp, g_fwd);
    cudaGetSymbolAddress((void**)&cidxp, g_cidx);
    cudaGetSymbolAddress((void**)&cntp, g_cnt);

    cudaFuncSetAttribute(qkv_gemm_kernel,
                         cudaFuncAttributeMaxDynamicSharedMemorySize, GEMM_SMEM);
    cudaFuncSetAttribute(out_gemm_kernel,
                         cudaFuncAttributeMaxDynamicSharedMemorySize, GEMM_SMEM);
    cudaFuncSetAttribute(logits_kernel,
                         cudaFuncAttributeMaxDynamicSharedMemorySize, LOGITS_SMEM);
    cudaFuncSetAttribute(av_kernel,
                         cudaFuncAttributeMaxDynamicSharedMemorySize, AV_SMEM);

    const size_t FINAL_ELEMS = (size_t)BS_ROWS * DM;
    const size_t ATTN_ELEMS  = (size_t)BH * SEQ * SEQ;
    const size_t asz = (size_t)BS_ROWS * DM;
    float* attnp = ((size_t)out_size >= FINAL_ELEMS + ATTN_ELEMS)
                       ? (out + FINAL_ELEMS) : attnScratch;

    // Fork machinery (created per call, never destroyed; no device allocs).
    cudaStream_t s2 = 0;
    bool forked = (cudaStreamCreateWithFlags(&s2, cudaStreamNonBlocking) == cudaSuccess);
    cudaEvent_t eFork = 0, eW = 0, eQkv = 0, eVt = 0, eRs = 0, eJoin = 0;
    if (forked) {
        forked = (cudaEventCreateWithFlags(&eFork, cudaEventDisableTiming) == cudaSuccess) &&
                 (cudaEventCreateWithFlags(&eW,    cudaEventDisableTiming) == cudaSuccess) &&
                 (cudaEventCreateWithFlags(&eQkv,  cudaEventDisableTiming) == cudaSuccess) &&
                 (cudaEventCreateWithFlags(&eVt,   cudaEventDisableTiming) == cudaSuccess) &&
                 (cudaEventCreateWithFlags(&eRs,   cudaEventDisableTiming) == cudaSuccess) &&
                 (cudaEventCreateWithFlags(&eJoin, cudaEventDisableTiming) == cudaSuccess);
    }

    if (forked) {
        cudaEventRecord(eFork, 0);
        cudaStreamWaitEvent(s2, eFork, 0);

        mask_scan_kernel<<<BATCH, 1024, 0, s2>>>(mask, fwdp, cidxp, cntp);
        transpose_split_kernel<<<dim3(32, 32, 4), 256, 0, s2>>>(Wq, Wk, Wv, Wo, WThi, WTlo);
        cudaEventRecord(eW, s2);
        split_inputs_kernel<<<dim3(4096, 3), 256>>>(q, k, v, Xhi, Xlo);

        cudaStreamWaitEvent(0, eW, 0);
        qkv_gemm_kernel<<<dim3(8, 32, 3), 256, GEMM_SMEM>>>(
            Xhi, Xlo, WThi, WTlo, bq, bk, bv, QKVhi, QKVlo);
        cudaEventRecord(eQkv, 0);

        cudaStreamWaitEvent(s2, eQkv, 0);
        transpose_v_kernel<<<dim3(32, 128), 256, 0, s2>>>(
            QKVhi + 2 * asz, QKVlo + 2 * asz, fwdp, Vthi, Vtlo);
        cudaEventRecord(eVt, s2);

        logits_kernel<<<dim3(16, 16, BH), 256, LOGITS_SMEM>>>(
            QKVhi, QKVlo, QKVhi + asz, QKVlo + asz, cidxp, cntp, Phi, partialp);
        reduce_sums_kernel<<<(BH * SEQ) / 256, 256>>>(partialp, rowsump);
        cudaEventRecord(eRs, 0);

        cudaStreamWaitEvent(s2, eRs, 0);
        expand_kernel<<<BH * SEQ, 256, 0, s2>>>(Phi, rowsump, fwdp, attnp);
        cudaEventRecord(eJoin, s2);

        cudaStreamWaitEvent(0, eVt, 0);
        av_kernel<<<dim3(16, BH), 256, AV_SMEM>>>(
            Phi, Vthi, Vtlo, rowsump, cntp, Cxhi, Cxlo);
        out_gemm_kernel<<<dim3(8, 32), 256, GEMM_SMEM>>>(
            Cxhi, Cxlo, WThi, WTlo, bo, out);

        cudaStreamWaitEvent(0, eJoin, 0);
    } else {
        mask_scan_kernel<<<BATCH, 1024>>>(mask, fwdp, cidxp, cntp);
        split_inputs_kernel<<<dim3(4096, 3), 256>>>(q, k, v, Xhi, Xlo);
        transpose_split_kernel<<<dim3(32, 32, 4), 256>>>(Wq, Wk, Wv, Wo, WThi, WTlo);
        qkv_gemm_kernel<<<dim3(8, 32, 3), 256, GEMM_SMEM>>>(
            Xhi, Xlo, WThi, WTlo, bq, bk, bv, QKVhi, QKVlo);
        transpose_v_kernel<<<dim3(32, 128), 256>>>(
            QKVhi + 2 * asz, QKVlo + 2 * asz, fwdp, Vthi, Vtlo);
        logits_kernel<<<dim3(16, 16, BH), 256, LOGITS_SMEM>>>(
            QKVhi, QKVlo, QKVhi + asz, QKVlo + asz, cidxp, cntp, Phi, partialp);
        reduce_sums_kernel<<<(BH * SEQ) / 256, 256>>>(partialp, rowsump);
        av_kernel<<<dim3(16, BH), 256, AV_SMEM>>>(
            Phi, Vthi, Vtlo, rowsump, cntp, Cxhi, Cxlo);
        expand_kernel<<<BH * SEQ, 256>>>(Phi, rowsump, fwdp, attnp);
        out_gemm_kernel<<<dim3(8, 32), 256, GEMM_SMEM>>>(
            Cxhi, Cxlo, WThi, WTlo, bo, out);
    }
}

// round 16
// speedup vs baseline: 1.1995x; 1.0344x over previous
#include <cuda_runtime.h>
#include <cuda_fp16.h>
#include <math.h>
#include <stdint.h>
#include <stddef.h>

#define DM 1024
#define NH 16
#define DEPTH 64
#define BATCH 2
#define SEQ 2048
#define BS_ROWS 4096
#define BH 32

// ---------------------------------------------------------------------------
// Scratch (__device__ globals; allocation-free rule). Zero-initialized.
// ---------------------------------------------------------------------------
__device__ __half g_Xhi[3][(size_t)BS_ROWS * DM];
__device__ __half g_Xlo[3][(size_t)BS_ROWS * DM];
__device__ __half g_QKVhi[3][(size_t)BS_ROWS * DM];
__device__ __half g_QKVlo[3][(size_t)BS_ROWS * DM];
__device__ __half g_Vt[(size_t)BH * DEPTH * SEQ];     // [bh][d][compact s], fp16
__device__ __half g_Cx[(size_t)BS_ROWS * DM];         // ctx, fp16
__device__ __half g_WThi[4][(size_t)DM * DM];
__device__ __half g_WTlo[4][(size_t)DM * DM];
__device__ __half g_Phi[(size_t)BH * SEQ * SEQ];      // exp(p) fp16, compact cols
__device__ float  g_attn[(size_t)BH * SEQ * SEQ];     // fallback full attn
__device__ float  g_partial[(size_t)BH * SEQ * 16];
__device__ float  g_rowsum[(size_t)BH * SEQ];
__device__ int    g_fwd[BATCH * SEQ];
__device__ int    g_cidx[BATCH * SEQ];
__device__ int    g_cnt[BATCH];

// ---------------------------------------------------------------------------
// Helpers
// ---------------------------------------------------------------------------
__device__ __forceinline__ float residf(float x) {
    return x - __half2float(__float2half_rn(x));
}
__device__ __forceinline__ uint32_t smem_u32(const void* p) {
    return (uint32_t)__cvta_generic_to_shared(p);
}
// FMA/ALU-pipe exp (fp32, rel err ~1e-7). Validated numerically in R9/R15.
__device__ __forceinline__ float exp_fma(float x) {
    float t = x * 1.44269504088896341f;
    float r = t + 12582912.0f;                      // 1.5 * 2^23
    int   n = __float_as_int(r) - 0x4B400000;
    float f = t - (r - 12582912.0f);                // f in [-0.5, 0.5]
    float p = 1.5403530393e-4f;
    p = fmaf(p, f, 1.3333558146e-3f);
    p = fmaf(p, f, 9.6181291076e-3f);
    p = fmaf(p, f, 5.5504108665e-2f);
    p = fmaf(p, f, 2.4022650696e-1f);
    p = fmaf(p, f, 6.9314718056e-1f);
    p = fmaf(p, f, 1.0f);
    return __int_as_float(__float_as_int(p) + (n << 23));
}
#define CP16(dst_u32, src_ptr) \
    asm volatile("cp.async.cg.shared.global [%0], [%1], 16;\n" :: "r"(dst_u32), "l"(src_ptr))
#define CP_COMMIT asm volatile("cp.async.commit_group;\n" ::: "memory")
#define CP_WAIT0  asm volatile("cp.async.wait_group 0;\n" ::: "memory")

__device__ __forceinline__ void mma16816(float4& d,
    uint32_t a0, uint32_t a1, uint32_t a2, uint32_t a3,
    uint32_t b0, uint32_t b1)
{
    asm volatile(
        "mma.sync.aligned.m16n8k16.row.col.f32.f16.f16.f32 "
        "{%0,%1,%2,%3},{%4,%5,%6,%7},{%8,%9},{%0,%1,%2,%3};\n"
        : "+f"(d.x), "+f"(d.y), "+f"(d.z), "+f"(d.w)
        : "r"(a0), "r"(a1), "r"(a2), "r"(a3), "r"(b0), "r"(b1));
}

__device__ __forceinline__ void ldsm4(uint32_t& r0, uint32_t& r1,
                                      uint32_t& r2, uint32_t& r3, uint32_t addr)
{
    asm volatile("ldmatrix.sync.aligned.m8n8.x4.shared.b16 {%0,%1,%2,%3}, [%4];\n"
                 : "=r"(r0), "=r"(r1), "=r"(r2), "=r"(r3) : "r"(addr));
}

__device__ __forceinline__ void lda_x4(uint32_t* f, uint32_t sbase, int lp_bytes,
                                       int rbase, int kb0, int lane)
{
    int seg = lane >> 3, rw = lane & 7;
    int row = rbase + rw + ((seg & 1) << 3);
    int col = kb0 + ((seg >> 1) << 3);
    ldsm4(f[0], f[1], f[2], f[3], sbase + row * lp_bytes + col * 2);
}
__device__ __forceinline__ void ldb_x4(uint32_t* f0, uint32_t* f1, uint32_t sbase,
                                       int lp_bytes, int cbase, int kb0, int lane)
{
    int seg = lane >> 3, rw = lane & 7;
    int row = cbase + rw + ((seg >> 1) << 3);
    int col = kb0 + ((seg & 1) << 3);
    ldsm4(f0[0], f0[1], f1[0], f1[1], sbase + row * lp_bytes + col * 2);
}

// ---------------------------------------------------------------------------
// Mask scan: per batch, prefix-compact unmasked columns. 1 block/batch.
// ---------------------------------------------------------------------------
__global__ __launch_bounds__(1024) void mask_scan_kernel(
    const int* __restrict__ mask, int* __restrict__ fwd,
    int* __restrict__ cidx, int* __restrict__ cnt)
{
    __shared__ int sa[1024], sb[1024];
    const int b = blockIdx.x, t = threadIdx.x;
    const int j0 = 2 * t, j1 = 2 * t + 1;
    const int m0 = (mask[b * SEQ + j0] == 0);
    const int m1 = (mask[b * SEQ + j1] == 0);
    sa[t] = m0 + m1;
    __syncthreads();
    int* src = sa; int* dst = sb;
    for (int off = 1; off < 1024; off <<= 1) {
        int v = src[t] + ((t >= off) ? src[t - off] : 0);
        dst[t] = v;
        __syncthreads();
        int* tmp = src; src = dst; dst = tmp;
    }
    const int incl = src[t];
    const int excl = incl - (m0 + m1);
    fwd[b * SEQ + j0] = m0 ? excl : -1;
    fwd[b * SEQ + j1] = m1 ? (excl + m0) : -1;
    if (m0) cidx[b * SEQ + excl] = j0;
    if (m1) cidx[b * SEQ + excl + m0] = j1;
    const int total = src[1023];
    if (t == 0) cnt[b] = total;
    __syncthreads();
    for (int s = t; s < SEQ; s += 1024)
        if (s >= total) cidx[b * SEQ + s] = 0;
}

// ---------------------------------------------------------------------------
// Elementwise split of q/k/v inputs
// ---------------------------------------------------------------------------
__global__ __launch_bounds__(256) void split_inputs_kernel(
    const float* __restrict__ q, const float* __restrict__ k,
    const float* __restrict__ v, __half* __restrict__ Xhi, __half* __restrict__ Xlo)
{
    const int z = blockIdx.y;
    const float* src = (z == 0) ? q : (z == 1) ? k : v;
    const size_t i = ((size_t)blockIdx.x * 256 + threadIdx.x) * 4;
    const size_t o = (size_t)z * BS_ROWS * DM + i;
    float4 x = *(const float4*)(src + i);
    *(__half2*)(Xhi + o)     = __floats2half2_rn(x.x, x.y);
    *(__half2*)(Xhi + o + 2) = __floats2half2_rn(x.z, x.w);
    *(__half2*)(Xlo + o)     = __floats2half2_rn(residf(x.x), residf(x.y));
    *(__half2*)(Xlo + o + 2) = __floats2half2_rn(residf(x.z), residf(x.w));
}

// ---------------------------------------------------------------------------
// Weight transpose+split
// ---------------------------------------------------------------------------
__global__ __launch_bounds__(256) void transpose_split_kernel(
    const float* __restrict__ Wq, const float* __restrict__ Wk,
    const float* __restrict__ Wv, const float* __restrict__ Wo,
    __half* __restrict__ ThiB, __half* __restrict__ TloB)
{
    const int z = blockIdx.z;
    const float* W = (z == 0) ? Wq : (z == 1) ? Wk : (z == 2) ? Wv : Wo;
    __half* Thi = ThiB + (size_t)z * DM * DM;
    __half* Tlo = TloB + (size_t)z * DM * DM;

    __shared__ float tile[32][33];
    const int k0 = blockIdx.y * 32, n0 = blockIdx.x * 32;
    const int tx = threadIdx.x & 31, ty = threadIdx.x >> 5;
#pragma unroll
    for (int i = 0; i < 4; i++) {
        int kk = ty + i * 8;
        tile[kk][tx] = W[(size_t)(k0 + kk) * DM + n0 + tx];
    }
    __syncthreads();
#pragma unroll
    for (int i = 0; i < 4; i++) {
        int nn = ty + i * 8;
        float x = tile[tx][nn];
        __half hi = __float2half_rn(x);
        Thi[(size_t)(n0 + nn) * DM + k0 + tx] = hi;
        Tlo[(size_t)(n0 + nn) * DM + k0 + tx] = __float2half_rn(x - __half2float(hi));
    }
}

// ---------------------------------------------------------------------------
// V transpose with compaction (hi only): V [4096][1024] -> Vt [bh][64][compact s]
// ---------------------------------------------------------------------------
__global__ __launch_bounds__(256) void transpose_v_kernel(
    const __half* __restrict__ Vhi, const int* __restrict__ fwd,
    __half* __restrict__ Thi)
{
    __shared__ __half thi[32][33];
    const int n0 = blockIdx.x * 32;
    const int s0 = blockIdx.y * 32;
    const int tx = threadIdx.x & 31, ty = threadIdx.x >> 5;
#pragma unroll
    for (int i = 0; i < 4; i++) {
        int r = ty + i * 8;
        thi[r][tx] = Vhi[(size_t)(s0 + r) * DM + n0 + tx];
    }
    __syncthreads();
    const int b = s0 >> 11;
    const int slot = fwd[b * SEQ + (s0 & 2047) + tx];
    if (slot >= 0) {
#pragma unroll
        for (int i = 0; i < 4; i++) {
            int nn = ty + i * 8;
            int gn = n0 + nn;
            int h = gn >> 6, d = gn & 63;
            size_t orow = ((size_t)(b * NH + h) * DEPTH + d) * SEQ + slot;
            Thi[orow] = thi[tx][nn];
        }
    }
}

// ---------------------------------------------------------------------------
// Double-buffered split-fp16 GEMM. BM=BN=128, BK=32, single barrier/iter.
// A_SPLIT: include the Alo·Bhi correction term (3-term); else Ahi-only (2-term).
// ---------------------------------------------------------------------------
#define GSTAGE 40960
#define GEMM_SMEM (2 * GSTAGE)

template<bool A_SPLIT>
__device__ __forceinline__ void gemm_load_stage(uint32_t smbase, int s,
    const __half* AhiG, const __half* AloG,
    const __half* BhiG, const __half* BloG,
    int m0, int n0, int k0, int tid)
{
    uint32_t sb = smbase + s * GSTAGE;
#pragma unroll
    for (int t = 0; t < 2; t++) {
        int id = tid * 2 + t;
        int r = id >> 2, q = id & 3;
        uint32_t off = r * 80 + q * 16;
        const size_t ga = (size_t)(m0 + r) * DM + k0 + q * 8;
        const size_t gb = (size_t)(n0 + r) * DM + k0 + q * 8;
        CP16(sb + off,         AhiG + ga);
        if (A_SPLIT) CP16(sb + 10240 + off, AloG + ga);
        CP16(sb + 20480 + off, BhiG + gb);
        CP16(sb + 30720 + off, BloG + gb);
    }
}

template<bool OUT_F32, bool A_SPLIT>
__device__ __forceinline__ void gemm_core(
    const __half* __restrict__ AhiG, const __half* __restrict__ AloG,
    const __half* __restrict__ BhiG, const __half* __restrict__ BloG,
    const float* __restrict__ bias,
    float* __restrict__ Cf, __half* __restrict__ Chi, __half* __restrict__ Clo)
{
    extern __shared__ char dsm[];
    const uint32_t smbase = smem_u32(dsm);

    const int tid = threadIdx.x;
    const int m0 = blockIdx.y * 128, n0 = blockIdx.x * 128;
    const int lane = tid & 31, wid = tid >> 5;
    const int wm = wid >> 2, wn = wid & 3;
    const int grp = lane >> 2, tig = lane & 3;

    float4 acc[4][4];
#pragma unroll
    for (int i = 0; i < 4; i++)
#pragma unroll
        for (int j = 0; j < 4; j++) acc[i][j] = make_float4(0.f, 0.f, 0.f, 0.f);

    gemm_load_stage<A_SPLIT>(smbase, 0, AhiG, AloG, BhiG, BloG, m0, n0, 0, tid);
    CP_COMMIT;

    for (int kt = 0; kt < 32; kt++) {
        CP_WAIT0;
        __syncthreads();
        if (kt + 1 < 32) {
            gemm_load_stage<A_SPLIT>(smbase, (kt + 1) & 1, AhiG, AloG, BhiG, BloG,
                                     m0, n0, (kt + 1) * 32, tid);
            CP_COMMIT;
        }

        const uint32_t sb = smbase + (kt & 1) * GSTAGE;
        const uint32_t ah_b = sb, al_b = sb + 10240, bh_b = sb + 20480, bl_b = sb + 30720;
#pragma unroll
        for (int ks = 0; ks < 2; ks++) {
            const int kb0 = ks * 16;
            uint32_t ah[4][4], al[4][4];
#pragma unroll
            for (int mt = 0; mt < 4; mt++) {
                lda_x4(ah[mt], ah_b, 80, wm * 64 + mt * 16, kb0, lane);
                if (A_SPLIT) lda_x4(al[mt], al_b, 80, wm * 64 + mt * 16, kb0, lane);
            }
            uint32_t bhf[4][2], blf[4][2];
#pragma unroll
            for (int p = 0; p < 2; p++) {
                ldb_x4(bhf[2 * p], bhf[2 * p + 1], bh_b, 80, wn * 32 + p * 16, kb0, lane);
                ldb_x4(blf[2 * p], blf[2 * p + 1], bl_b, 80, wn * 32 + p * 16, kb0, lane);
            }
#pragma unroll
            for (int mt = 0; mt < 4; mt++)
#pragma unroll
                for (int nt = 0; nt < 4; nt++) {
                    mma16816(acc[mt][nt], ah[mt][0], ah[mt][1], ah[mt][2], ah[mt][3],
                             bhf[nt][0], bhf[nt][1]);
                    mma16816(acc[mt][nt], ah[mt][0], ah[mt][1], ah[mt][2], ah[mt][3],
                             blf[nt][0], blf[nt][1]);
                    if (A_SPLIT)
                        mma16816(acc[mt][nt], al[mt][0], al[mt][1], al[mt][2], al[mt][3],
                                 bhf[nt][0], bhf[nt][1]);
                }
        }
    }

#pragma unroll
    for (int mt = 0; mt < 4; mt++) {
        int r = m0 + wm * 64 + mt * 16 + grp;
#pragma unroll
        for (int nt = 0; nt < 4; nt++) {
            int c = n0 + wn * 32 + nt * 8 + tig * 2;
            float bx = bias[c], by = bias[c + 1];
            float x0 = acc[mt][nt].x + bx, x1 = acc[mt][nt].y + by;
            float x2 = acc[mt][nt].z + bx, x3 = acc[mt][nt].w + by;
            if (OUT_F32) {
                *(float2*)&Cf[(size_t)r * DM + c]       = make_float2(x0, x1);
                *(float2*)&Cf[(size_t)(r + 8) * DM + c] = make_float2(x2, x3);
            } else {
                *(__half2*)&Chi[(size_t)r * DM + c]       = __floats2half2_rn(x0, x1);
                *(__half2*)&Chi[(size_t)(r + 8) * DM + c] = __floats2half2_rn(x2, x3);
                *(__half2*)&Clo[(size_t)r * DM + c]       = __floats2half2_rn(residf(x0), residf(x1));
                *(__half2*)&Clo[(size_t)(r + 8) * DM + c] = __floats2half2_rn(residf(x2), residf(x3));
            }
        }
    }
}

__global__ __launch_bounds__(256) void qkv_gemm_kernel(
    const __half* __restrict__ Xhi, const __half* __restrict__ Xlo,
    const __half* __restrict__ WThi, const __half* __restrict__ WTlo,
    const float* __restrict__ bq, const float* __restrict__ bk,
    const float* __restrict__ bv,
    __half* __restrict__ QKVhi, __half* __restrict__ QKVlo)
{
    const int z = blockIdx.z;
    const size_t asz = (size_t)BS_ROWS * DM, wsz = (size_t)DM * DM;
    const float* bias = (z == 0) ? bq : (z == 1) ? bk : bv;
    gemm_core<false, true>(Xhi + z * asz, Xlo + z * asz,
                           WThi + z * wsz, WTlo + z * wsz,
                           bias, nullptr, QKVhi + z * asz, QKVlo + z * asz);
}

__global__ __launch_bounds__(256) void out_gemm_kernel(
    const __half* __restrict__ Cx,
    const __half* __restrict__ WThi, const __half* __restrict__ WTlo,
    const float* __restrict__ bo, float* __restrict__ out)
{
    const size_t wsz = (size_t)DM * DM;
    gemm_core<true, false>(Cx, nullptr, WThi + 3 * wsz, WTlo + 3 * wsz, bo,
                           out, nullptr, nullptr);
}

// ---------------------------------------------------------------------------
// Logits over COMPACT columns: p = exp(0.125*QK), stored fp16.
// Exp split 75% MUFU / 25% FMA-pipe poly (measured balance point).
// ---------------------------------------------------------------------------
#define LP 72
#define LOGITS_SMEM (4 * 128 * LP * 2 + 128 * 4 * 4)

__global__ __launch_bounds__(256) void logits_kernel(
    const __half* __restrict__ Qhi, const __half* __restrict__ Qlo,
    const __half* __restrict__ Khi, const __half* __restrict__ Klo,
    const int* __restrict__ cidx, const int* __restrict__ cnt,
    __half* __restrict__ Phi, float* __restrict__ partial)
{
    extern __shared__ __half sm[];
    __half (*Qh)[LP] = (__half(*)[LP])sm;
    __half (*Ql)[LP] = (__half(*)[LP])(sm + 128 * LP);
    __half (*Kh)[LP] = (__half(*)[LP])(sm + 2 * 128 * LP);
    __half (*Kl)[LP] = (__half(*)[LP])(sm + 3 * 128 * LP);
    float* sums = (float*)(sm + 4 * 128 * LP);

    const int tid = threadIdx.x;
    const int n0 = blockIdx.x * 128, m0 = blockIdx.y * 128;
    const int bh = blockIdx.z, b = bh >> 4, h = bh & 15;
    const int Mb = cnt[b];

    if (n0 >= Mb) {
        if (tid < 128)
            partial[((size_t)bh * SEQ + m0 + tid) * 16 + blockIdx.x] = 0.f;
        return;
    }

    const size_t hbase = (size_t)b * SEQ * DM + h * 64;
    const int* cb = cidx + b * SEQ;

#pragma unroll
    for (int t = 0; t < 16; t++) {
        int id = tid + 256 * t;
        int arr = id >> 10, rem = id & 1023;
        int r = rem >> 3, q = rem & 7;
        const __half* src = (arr == 0) ? Qhi : (arr == 1) ? Qlo : (arr == 2) ? Khi : Klo;
        __half (*dst)[LP] = (arr == 0) ? Qh : (arr == 1) ? Ql : (arr == 2) ? Kh : Kl;
        int rphys;
        if (arr < 2) rphys = m0 + r;
        else {
            int jr = n0 + r;
            rphys = (jr < Mb) ? cb[jr] : 0;
        }
        uint4 v = *(const uint4*)(src + hbase + (size_t)rphys * DM + q * 8);
        *(uint2*)&dst[r][q * 8]     = make_uint2(v.x, v.y);
        *(uint2*)&dst[r][q * 8 + 4] = make_uint2(v.z, v.w);
    }
    __syncthreads();

    const int lane = tid & 31, wid = tid >> 5;
    const int wm = wid >> 2, wn = wid & 3;
    const int grp = lane >> 2, tig = lane & 3;
    const uint32_t qh_b = smem_u32(Qh), ql_b = smem_u32(Ql);
    const uint32_t kh_b = smem_u32(Kh), kl_b = smem_u32(Kl);

    float4 acc[4][4];
#pragma unroll
    for (int i = 0; i < 4; i++)
#pragma unroll
        for (int j = 0; j < 4; j++) acc[i][j] = make_float4(0.f, 0.f, 0.f, 0.f);

#pragma unroll
    for (int ks = 0; ks < 4; ks++) {
        const int kb0 = ks * 16;
        uint32_t ah[4][4], al[4][4];
#pragma unroll
        for (int mt = 0; mt < 4; mt++) {
            lda_x4(ah[mt], qh_b, 144, wm * 64 + mt * 16, kb0, lane);
            lda_x4(al[mt], ql_b, 144, wm * 64 + mt * 16, kb0, lane);
        }
        uint32_t bhf[4][2], blf[4][2];
#pragma unroll
        for (int p = 0; p < 2; p++) {
            ldb_x4(bhf[2 * p], bhf[2 * p + 1], kh_b, 144, wn * 32 + p * 16, kb0, lane);
            ldb_x4(blf[2 * p], blf[2 * p + 1], kl_b, 144, wn * 32 + p * 16, kb0, lane);
        }
#pragma unroll
        for (int mt = 0; mt < 4; mt++)
#pragma unroll
            for (int nt = 0; nt < 4; nt++) {
                mma16816(acc[mt][nt], ah[mt][0], ah[mt][1], ah[mt][2], ah[mt][3],
                         bhf[nt][0], bhf[nt][1]);
                mma16816(acc[mt][nt], ah[mt][0], ah[mt][1], ah[mt][2], ah[mt][3],
                         blf[nt][0], blf[nt][1]);
                mma16816(acc[mt][nt], al[mt][0], al[mt][1], al[mt][2], al[mt][3],
                         bhf[nt][0], bhf[nt][1]);
            }
    }

    float rs0[4], rs1[4];
#pragma unroll
    for (int mt = 0; mt < 4; mt++) { rs0[mt] = 0.f; rs1[mt] = 0.f; }

#pragma unroll
    for (int mt = 0; mt < 4; mt++) {
        int r = m0 + wm * 64 + mt * 16 + grp;
        __half* oh0 = Phi + ((size_t)bh * SEQ + r) * SEQ;
        __half* oh1 = oh0 + (size_t)8 * SEQ;
#pragma unroll
        for (int nt = 0; nt < 4; nt++) {
            int j = n0 + wn * 32 + nt * 8 + tig * 2;
            bool v0 = (j < Mb), v1 = (j + 1 < Mb);
            float4 a = acc[mt][nt];
            float p0 = v0 ? __expf(a.x * 0.125f)  : 0.f;
            float p1 = v1 ? __expf(a.y * 0.125f)  : 0.f;
            float p2 = v0 ? __expf(a.z * 0.125f)  : 0.f;
            float p3 = v1 ? exp_fma(a.w * 0.125f) : 0.f;
            *(__half2*)(oh0 + j) = __floats2half2_rn(p0, p1);
            *(__half2*)(oh1 + j) = __floats2half2_rn(p2, p3);
            rs0[mt] += p0 + p1;
            rs1[mt] += p2 + p3;
        }
    }
#pragma unroll
    for (int mt = 0; mt < 4; mt++) {
        float s0 = rs0[mt], s1 = rs1[mt];
        s0 += __shfl_xor_sync(0xffffffffu, s0, 1);
        s0 += __shfl_xor_sync(0xffffffffu, s0, 2);
        s1 += __shfl_xor_sync(0xffffffffu, s1, 1);
        s1 += __shfl_xor_sync(0xffffffffu, s1, 2);
        if (tig == 0) {
            int rl = wm * 64 + mt * 16 + grp;
            sums[(size_t)rl * 4 + wn] = s0;
            sums[(size_t)(rl + 8) * 4 + wn] = s1;
        }
    }
    __syncthreads();
    if (tid < 128) {
        float tot = (sums[tid * 4 + 0] + sums[tid * 4 + 1]) +
                    (sums[tid * 4 + 2] + sums[tid * 4 + 3]);
        partial[((size_t)bh * SEQ + m0 + tid) * 16 + blockIdx.x] = tot;
    }
}

__global__ __launch_bounds__(256) void reduce_sums_kernel(
    const float* __restrict__ partial, float* __restrict__ rowsum)
{
    int i = blockIdx.x * 256 + threadIdx.x;
    const float4* p = (const float4*)(partial + (size_t)i * 16);
    float4 a = p[0], b = p[1], c = p[2], d = p[3];
    rowsum[i] = ((a.x + a.y) + (a.z + a.w)) + ((b.x + b.y) + (b.z + b.w)) +
                ((c.x + c.y) + (c.z + c.w)) + ((d.x + d.y) + (d.z + d.w));
}

// ---------------------------------------------------------------------------
// AV over compact K-dim: ctx = (P @ V) / rowsum, all fp16 operands, 1 mma term.
// BM=128, BN=64, BK=64.
// ---------------------------------------------------------------------------
#define AV_SMEM (128 * LP * 2 + 64 * LP * 2 + 128 * 4)

__global__ __launch_bounds__(256) void av_kernel(
    const __half* __restrict__ Phi, const __half* __restrict__ Vt,
    const float* __restrict__ rowsum, const int* __restrict__ cnt,
    __half* __restrict__ Cx)
{
    extern __shared__ char smraw[];
    __half (*Ah)[LP] = (__half(*)[LP])smraw;
    __half (*Vh)[LP] = (__half(*)[LP])(smraw + 128 * LP * 2);
    float* sinv = (float*)(smraw + 128 * LP * 2 + 64 * LP * 2);

    const int tid = threadIdx.x;
    const int m0 = blockIdx.x * 128;
    const int bh = blockIdx.y, b = bh >> 4, h = bh & 15;
    const int Mb = cnt[b];

    if (tid < 128) sinv[tid] = 1.0f / rowsum[(size_t)bh * SEQ + m0 + tid];
    __syncthreads();

    const int lane = tid & 31, wid = tid >> 5;
    const int wm = wid >> 2, wn = wid & 3;
    const int grp = lane >> 2, tig = lane & 3;
    const uint32_t ah_b = smem_u32(Ah);
    const uint32_t vh_b = smem_u32(Vh);

    float4 acc[4][2];
#pragma unroll
    for (int i = 0; i < 4; i++)
#pragma unroll
        for (int j = 0; j < 2; j++) acc[i][j] = make_float4(0.f, 0.f, 0.f, 0.f);

    const size_t prow = (size_t)bh * SEQ + m0;
    const size_t vtb = (size_t)bh * DEPTH * SEQ;

    for (int k0 = 0; k0 < Mb; k0 += 64) {
        // P tile: 128 rows x 64 cols fp16 = 1024 uint4 / 256 thr
#pragma unroll
        for (int t = 0; t < 4; t++) {
            int id = tid + 256 * t;            // 0..1023
            int r = id >> 3, q = id & 7;
            uint4 v = *(const uint4*)(Phi + (prow + r) * SEQ + k0 + q * 8);
            *(uint2*)&Ah[r][q * 8]     = make_uint2(v.x, v.y);
            *(uint2*)&Ah[r][q * 8 + 4] = make_uint2(v.z, v.w);
        }
        // V tile: 64 d-rows x 64 cols fp16 = 512 uint4 / 256 thr
#pragma unroll
        for (int t = 0; t < 2; t++) {
            int id = tid + 256 * t;            // 0..511
            int r = id >> 3, q = id & 7;       // r 0..63
            uint4 v = *(const uint4*)(Vt + vtb + (size_t)r * SEQ + k0 + q * 8);
            *(uint2*)&Vh[r][q * 8]     = make_uint2(v.x, v.y);
            *(uint2*)&Vh[r][q * 8 + 4] = make_uint2(v.z, v.w);
        }
        __syncthreads();

#pragma unroll
        for (int ks = 0; ks < 4; ks++) {
            const int kb0 = ks * 16;
            uint32_t ah[4][4];
#pragma unroll
            for (int mt = 0; mt < 4; mt++)
                lda_x4(ah[mt], ah_b, 144, wm * 64 + mt * 16, kb0, lane);
            uint32_t bhf[2][2];
            ldb_x4(bhf[0], bhf[1], vh_b, 144, wn * 16, kb0, lane);
#pragma unroll
            for (int mt = 0; mt < 4; mt++)
#pragma unroll
                for (int nt = 0; nt < 2; nt++)
                    mma16816(acc[mt][nt], ah[mt][0], ah[mt][1], ah[mt][2], ah[mt][3],
                             bhf[nt][0], bhf[nt][1]);
        }
        __syncthreads();
    }

#pragma unroll
    for (int mt = 0; mt < 4; mt++) {
        int rl = wm * 64 + mt * 16 + grp;
        int r = m0 + rl;
        float iv0 = sinv[rl], iv1 = sinv[rl + 8];
#pragma unroll
        for (int nt = 0; nt < 2; nt++) {
            int d = wn * 16 + nt * 8 + tig * 2;
            size_t o = ((size_t)(b * SEQ + r)) * DM + h * 64 + d;
            *(__half2*)&Cx[o] =
                __floats2half2_rn(acc[mt][nt].x * iv0, acc[mt][nt].y * iv0);
            *(__half2*)&Cx[o + 8 * DM] =
                __floats2half2_rn(acc[mt][nt].z * iv1, acc[mt][nt].w * iv1);
        }
    }
}

// ---------------------------------------------------------------------------
// Expand: write final full-width attn = mask ? 0 : p/rowsum. 1 block/row.
// ---------------------------------------------------------------------------
__global__ __launch_bounds__(256) void expand_kernel(
    const __half* __restrict__ Phi,
    const float* __restrict__ rowsum, const int* __restrict__ fwd,
    float* __restrict__ attn)
{
    const int row = blockIdx.x;
    const int b = row >> 15;               // NH*SEQ = 32768
    const float inv = 1.0f / rowsum[row];
    const __half* ph = Phi + (size_t)row * SEQ;
    const int* fw = fwd + b * SEQ;
    float* o = attn + (size_t)row * SEQ;

    const int j0 = threadIdx.x * 8;
    float vals[8];
#pragma unroll
    for (int t = 0; t < 8; t++) {
        int f = fw[j0 + t];
        vals[t] = (f >= 0) ? __half2float(ph[f]) * inv : 0.f;
    }
    *(float4*)(o + j0)     = make_float4(vals[0], vals[1], vals[2], vals[3]);
    *(float4*)(o + j0 + 4) = make_float4(vals[4], vals[5], vals[6], vals[7]);
}

// ---------------------------------------------------------------------------
// Launcher — forked-stream graph: transpose_v ∥ logits, expand ∥ (av, out_gemm)
// ---------------------------------------------------------------------------
extern "C" void kernel_launch(void* const* d_in, const int* in_sizes, int n_in,
                              void* d_out, int out_size)
{
    const float* v    = (const float*)d_in[0];
    const float* k    = (const float*)d_in[1];
    const float* q    = (const float*)d_in[2];
    const int*   mask = (const int*)  d_in[3];
    const float* Wq = (const float*)d_in[4];
    const float* bq = (const float*)d_in[5];
    const float* Wk = (const float*)d_in[6];
    const float* bk = (const float*)d_in[7];
    const float* Wv = (const float*)d_in[8];
    const float* bv = (const float*)d_in[9];
    const float* Wo = (const float*)d_in[10];
    const float* bo = (const float*)d_in[11];
    float* out = (float*)d_out;

    __half *Xhi, *Xlo, *QKVhi, *QKVlo, *Vt, *Cx, *WThi, *WTlo, *Phi;
    float *attnScratch, *partialp, *rowsump;
    int *fwdp, *cidxp, *cntp;
    cudaGetSymbolAddress((void**)&Xhi, g_Xhi);
    cudaGetSymbolAddress((void**)&Xlo, g_Xlo);
    cudaGetSymbolAddress((void**)&QKVhi, g_QKVhi);
    cudaGetSymbolAddress((void**)&QKVlo, g_QKVlo);
    cudaGetSymbolAddress((void**)&Vt, g_Vt);
    cudaGetSymbolAddress((void**)&Cx, g_Cx);
    cudaGetSymbolAddress((void**)&WThi, g_WThi);
    cudaGetSymbolAddress((void**)&WTlo, g_WTlo);
    cudaGetSymbolAddress((void**)&Phi, g_Phi);
    cudaGetSymbolAddress((void**)&attnScratch, g_attn);
    cudaGetSymbolAddress((void**)&partialp, g_partial);
    cudaGetSymbolAddress((void**)&rowsump, g_rowsum);
    cudaGetSymbolAddress((void**)&fwdp, g_fwd);
    cudaGetSymbolAddress((void**)&cidxp, g_cidx);
    cudaGetSymbolAddress((void**)&cntp, g_cnt);

    cudaFuncSetAttribute(qkv_gemm_kernel,
                         cudaFuncAttributeMaxDynamicSharedMemorySize, GEMM_SMEM);
    cudaFuncSetAttribute(out_gemm_kernel,
                         cudaFuncAttributeMaxDynamicSharedMemorySize, GEMM_SMEM);
    cudaFuncSetAttribute(logits_kernel,
                         cudaFuncAttributeMaxDynamicSharedMemorySize, LOGITS_SMEM);
    cudaFuncSetAttribute(av_kernel,
                         cudaFuncAttributeMaxDynamicSharedMemorySize, AV_SMEM);

    const size_t FINAL_ELEMS = (size_t)BS_ROWS * DM;
    const size_t ATTN_ELEMS  = (size_t)BH * SEQ * SEQ;
    const size_t asz = (size_t)BS_ROWS * DM;
    float* attnp = ((size_t)out_size >= FINAL_ELEMS + ATTN_ELEMS)
                       ? (out + FINAL_ELEMS) : attnScratch;

    // Fork machinery (created per call, never destroyed; no device allocs).
    cudaStream_t s2 = 0;
    bool forked = (cudaStreamCreateWithFlags(&s2, cudaStreamNonBlocking) == cudaSuccess);
    cudaEvent_t eFork = 0, eW = 0, eQkv = 0, eVt = 0, eRs = 0, eJoin = 0;
    if (forked) {
        forked = (cudaEventCreateWithFlags(&eFork, cudaEventDisableTiming) == cudaSuccess) &&
                 (cudaEventCreateWithFlags(&eW,    cudaEventDisableTiming) == cudaSuccess) &&
                 (cudaEventCreateWithFlags(&eQkv,  cudaEventDisableTiming) == cudaSuccess) &&
                 (cudaEventCreateWithFlags(&eVt,   cudaEventDisableTiming) == cudaSuccess) &&
                 (cudaEventCreateWithFlags(&eRs,   cudaEventDisableTiming) == cudaSuccess) &&
                 (cudaEventCreateWithFlags(&eJoin, cudaEventDisableTiming) == cudaSuccess);
    }

    if (forked) {
        cudaEventRecord(eFork, 0);
        cudaStreamWaitEvent(s2, eFork, 0);

        mask_scan_kernel<<<BATCH, 1024, 0, s2>>>(mask, fwdp, cidxp, cntp);
        transpose_split_kernel<<<dim3(32, 32, 4), 256, 0, s2>>>(Wq, Wk, Wv, Wo, WThi, WTlo);
        cudaEventRecord(eW, s2);
        split_inputs_kernel<<<dim3(4096, 3), 256>>>(q, k, v, Xhi, Xlo);

        cudaStreamWaitEvent(0, eW, 0);
        qkv_gemm_kernel<<<dim3(8, 32, 3), 256, GEMM_SMEM>>>(
            Xhi, Xlo, WThi, WTlo, bq, bk, bv, QKVhi, QKVlo);
        cudaEventRecord(eQkv, 0);

        cudaStreamWaitEvent(s2, eQkv, 0);
        transpose_v_kernel<<<dim3(32, 128), 256, 0, s2>>>(
            QKVhi + 2 * asz, fwdp, Vt);
        cudaEventRecord(eVt, s2);

        logits_kernel<<<dim3(16, 16, BH), 256, LOGITS_SMEM>>>(
            QKVhi, QKVlo, QKVhi + asz, QKVlo + asz, cidxp, cntp, Phi, partialp);
        reduce_sums_kernel<<<(BH * SEQ) / 256, 256>>>(partialp, rowsump);
        cudaEventRecord(eRs, 0);

        cudaStreamWaitEvent(s2, eRs, 0);
        expand_kernel<<<BH * SEQ, 256, 0, s2>>>(Phi, rowsump, fwdp, attnp);
        cudaEventRecord(eJoin, s2);

        cudaStreamWaitEvent(0, eVt, 0);
        av_kernel<<<dim3(16, BH), 256, AV_SMEM>>>(
            Phi, Vt, rowsump, cntp, Cx);
        out_gemm_kernel<<<dim3(8, 32), 256, GEMM_SMEM>>>(
            Cx, WThi, WTlo, bo, out);

        cudaStreamWaitEvent(0, eJoin, 0);
    } else {
        mask_scan_kernel<<<BATCH, 1024>>>(mask, fwdp, cidxp, cntp);
        split_inputs_kernel<<<dim3(4096, 3), 256>>>(q, k, v, Xhi, Xlo);
        transpose_split_kernel<<<dim3(32, 32, 4), 256>>>(Wq, Wk, Wv, Wo, WThi, WTlo);
        qkv_gemm_kernel<<<dim3(8, 32, 3), 256, GEMM_SMEM>>>(
            Xhi, Xlo, WThi, WTlo, bq, bk, bv, QKVhi, QKVlo);
        transpose_v_kernel<<<dim3(32, 128), 256>>>(QKVhi + 2 * asz, fwdp, Vt);
        logits_kernel<<<dim3(16, 16, BH), 256, LOGITS_SMEM>>>(
            QKVhi, QKVlo, QKVhi + asz, QKVlo + asz, cidxp, cntp, Phi, partialp);
        reduce_sums_kernel<<<(BH * SEQ) / 256, 256>>>(partialp, rowsump);
        av_kernel<<<dim3(16, BH), 256, AV_SMEM>>>(Phi, Vt, rowsump, cntp, Cx);
        expand_kernel<<<BH * SEQ, 256>>>(Phi, rowsump, fwdp, attnp);
        out_gemm_kernel<<<dim3(8, 32), 256, GEMM_SMEM>>>(
            Cx, WThi, WTlo, bo, out);
    }
}

// round 17
// speedup vs baseline: 1.1999x; 1.0003x over previous
#include <cuda_runtime.h>
#include <cuda_fp16.h>
#include <math.h>
#include <stdint.h>
#include <stddef.h>

#define DM 1024
#define NH 16
#define DEPTH 64
#define BATCH 2
#define SEQ 2048
#define BS_ROWS 4096
#define BH 32

// ---------------------------------------------------------------------------
// Scratch (__device__ globals; allocation-free rule). Zero-initialized.
// ---------------------------------------------------------------------------
__device__ __half g_Xhi[3][(size_t)BS_ROWS * DM];
__device__ __half g_Xlo[3][(size_t)BS_ROWS * DM];
__device__ __half g_QKVhi[3][(size_t)BS_ROWS * DM];
__device__ __half g_QKVlo[3][(size_t)BS_ROWS * DM];
__device__ __half g_Vt[(size_t)BH * DEPTH * SEQ];     // [bh][d][compact s], fp16
__device__ __half g_Cx[(size_t)BS_ROWS * DM];         // ctx, fp16
__device__ __half g_WThi[4][(size_t)DM * DM];
__device__ __half g_WTlo[4][(size_t)DM * DM];
__device__ __half g_Phi[(size_t)BH * SEQ * SEQ];      // exp(p) fp16, compact cols
__device__ float  g_attn[(size_t)BH * SEQ * SEQ];     // fallback full attn
__device__ float  g_partial[(size_t)BH * SEQ * 16];
__device__ float  g_rowsum[(size_t)BH * SEQ];
__device__ int    g_fwd[BATCH * SEQ];
__device__ int    g_cidx[BATCH * SEQ];
__device__ int    g_cnt[BATCH];

// ---------------------------------------------------------------------------
// Helpers
// ---------------------------------------------------------------------------
__device__ __forceinline__ float residf(float x) {
    return x - __half2float(__float2half_rn(x));
}
__device__ __forceinline__ uint32_t smem_u32(const void* p) {
    return (uint32_t)__cvta_generic_to_shared(p);
}
// FMA/ALU-pipe exp (fp32, rel err ~1e-7). Validated numerically in R9/R15.
__device__ __forceinline__ float exp_fma(float x) {
    float t = x * 1.44269504088896341f;
    float r = t + 12582912.0f;                      // 1.5 * 2^23
    int   n = __float_as_int(r) - 0x4B400000;
    float f = t - (r - 12582912.0f);                // f in [-0.5, 0.5]
    float p = 1.5403530393e-4f;
    p = fmaf(p, f, 1.3333558146e-3f);
    p = fmaf(p, f, 9.6181291076e-3f);
    p = fmaf(p, f, 5.5504108665e-2f);
    p = fmaf(p, f, 2.4022650696e-1f);
    p = fmaf(p, f, 6.9314718056e-1f);
    p = fmaf(p, f, 1.0f);
    return __int_as_float(__float_as_int(p) + (n << 23));
}
#define CP16(dst_u32, src_ptr) \
    asm volatile("cp.async.cg.shared.global [%0], [%1], 16;\n" :: "r"(dst_u32), "l"(src_ptr))
#define CP_COMMIT asm volatile("cp.async.commit_group;\n" ::: "memory")
#define CP_WAIT0  asm volatile("cp.async.wait_group 0;\n" ::: "memory")

__device__ __forceinline__ void mma16816(float4& d,
    uint32_t a0, uint32_t a1, uint32_t a2, uint32_t a3,
    uint32_t b0, uint32_t b1)
{
    asm volatile(
        "mma.sync.aligned.m16n8k16.row.col.f32.f16.f16.f32 "
        "{%0,%1,%2,%3},{%4,%5,%6,%7},{%8,%9},{%0,%1,%2,%3};\n"
        : "+f"(d.x), "+f"(d.y), "+f"(d.z), "+f"(d.w)
        : "r"(a0), "r"(a1), "r"(a2), "r"(a3), "r"(b0), "r"(b1));
}

__device__ __forceinline__ void ldsm4(uint32_t& r0, uint32_t& r1,
                                      uint32_t& r2, uint32_t& r3, uint32_t addr)
{
    asm volatile("ldmatrix.sync.aligned.m8n8.x4.shared.b16 {%0,%1,%2,%3}, [%4];\n"
                 : "=r"(r0), "=r"(r1), "=r"(r2), "=r"(r3) : "r"(addr));
}

__device__ __forceinline__ void lda_x4(uint32_t* f, uint32_t sbase, int lp_bytes,
                                       int rbase, int kb0, int lane)
{
    int seg = lane >> 3, rw = lane & 7;
    int row = rbase + rw + ((seg & 1) << 3);
    int col = kb0 + ((seg >> 1) << 3);
    ldsm4(f[0], f[1], f[2], f[3], sbase + row * lp_bytes + col * 2);
}
__device__ __forceinline__ void ldb_x4(uint32_t* f0, uint32_t* f1, uint32_t sbase,
                                       int lp_bytes, int cbase, int kb0, int lane)
{
    int seg = lane >> 3, rw = lane & 7;
    int row = cbase + rw + ((seg >> 1) << 3);
    int col = kb0 + ((seg & 1) << 3);
    ldsm4(f0[0], f0[1], f1[0], f1[1], sbase + row * lp_bytes + col * 2);
}

// ---------------------------------------------------------------------------
// Mask scan: per batch, prefix-compact unmasked columns. 1 block/batch.
// ---------------------------------------------------------------------------
__global__ __launch_bounds__(1024) void mask_scan_kernel(
    const int* __restrict__ mask, int* __restrict__ fwd,
    int* __restrict__ cidx, int* __restrict__ cnt)
{
    __shared__ int sa[1024], sb[1024];
    const int b = blockIdx.x, t = threadIdx.x;
    const int j0 = 2 * t, j1 = 2 * t + 1;
    const int m0 = (mask[b * SEQ + j0] == 0);
    const int m1 = (mask[b * SEQ + j1] == 0);
    sa[t] = m0 + m1;
    __syncthreads();
    int* src = sa; int* dst = sb;
    for (int off = 1; off < 1024; off <<= 1) {
        int v = src[t] + ((t >= off) ? src[t - off] : 0);
        dst[t] = v;
        __syncthreads();
        int* tmp = src; src = dst; dst = tmp;
    }
    const int incl = src[t];
    const int excl = incl - (m0 + m1);
    fwd[b * SEQ + j0] = m0 ? excl : -1;
    fwd[b * SEQ + j1] = m1 ? (excl + m0) : -1;
    if (m0) cidx[b * SEQ + excl] = j0;
    if (m1) cidx[b * SEQ + excl + m0] = j1;
    const int total = src[1023];
    if (t == 0) cnt[b] = total;
    __syncthreads();
    for (int s = t; s < SEQ; s += 1024)
        if (s >= total) cidx[b * SEQ + s] = 0;
}

// ---------------------------------------------------------------------------
// Elementwise split of q/k/v inputs
// ---------------------------------------------------------------------------
__global__ __launch_bounds__(256) void split_inputs_kernel(
    const float* __restrict__ q, const float* __restrict__ k,
    const float* __restrict__ v, __half* __restrict__ Xhi, __half* __restrict__ Xlo)
{
    const int z = blockIdx.y;
    const float* src = (z == 0) ? q : (z == 1) ? k : v;
    const size_t i = ((size_t)blockIdx.x * 256 + threadIdx.x) * 4;
    const size_t o = (size_t)z * BS_ROWS * DM + i;
    float4 x = *(const float4*)(src + i);
    *(__half2*)(Xhi + o)     = __floats2half2_rn(x.x, x.y);
    *(__half2*)(Xhi + o + 2) = __floats2half2_rn(x.z, x.w);
    *(__half2*)(Xlo + o)     = __floats2half2_rn(residf(x.x), residf(x.y));
    *(__half2*)(Xlo + o + 2) = __floats2half2_rn(residf(x.z), residf(x.w));
}

// ---------------------------------------------------------------------------
// Weight transpose+split
// ---------------------------------------------------------------------------
__global__ __launch_bounds__(256) void transpose_split_kernel(
    const float* __restrict__ Wq, const float* __restrict__ Wk,
    const float* __restrict__ Wv, const float* __restrict__ Wo,
    __half* __restrict__ ThiB, __half* __restrict__ TloB)
{
    const int z = blockIdx.z;
    const float* W = (z == 0) ? Wq : (z == 1) ? Wk : (z == 2) ? Wv : Wo;
    __half* Thi = ThiB + (size_t)z * DM * DM;
    __half* Tlo = TloB + (size_t)z * DM * DM;

    __shared__ float tile[32][33];
    const int k0 = blockIdx.y * 32, n0 = blockIdx.x * 32;
    const int tx = threadIdx.x & 31, ty = threadIdx.x >> 5;
#pragma unroll
    for (int i = 0; i < 4; i++) {
        int kk = ty + i * 8;
        tile[kk][tx] = W[(size_t)(k0 + kk) * DM + n0 + tx];
    }
    __syncthreads();
#pragma unroll
    for (int i = 0; i < 4; i++) {
        int nn = ty + i * 8;
        float x = tile[tx][nn];
        __half hi = __float2half_rn(x);
        Thi[(size_t)(n0 + nn) * DM + k0 + tx] = hi;
        Tlo[(size_t)(n0 + nn) * DM + k0 + tx] = __float2half_rn(x - __half2float(hi));
    }
}

// ---------------------------------------------------------------------------
// V transpose with compaction (hi only): V [4096][1024] -> Vt [bh][64][compact s]
// ---------------------------------------------------------------------------
__global__ __launch_bounds__(256) void transpose_v_kernel(
    const __half* __restrict__ Vhi, const int* __restrict__ fwd,
    __half* __restrict__ Thi)
{
    __shared__ __half thi[32][33];
    const int n0 = blockIdx.x * 32;
    const int s0 = blockIdx.y * 32;
    const int tx = threadIdx.x & 31, ty = threadIdx.x >> 5;
#pragma unroll
    for (int i = 0; i < 4; i++) {
        int r = ty + i * 8;
        thi[r][tx] = Vhi[(size_t)(s0 + r) * DM + n0 + tx];
    }
    __syncthreads();
    const int b = s0 >> 11;
    const int slot = fwd[b * SEQ + (s0 & 2047) + tx];
    if (slot >= 0) {
#pragma unroll
        for (int i = 0; i < 4; i++) {
            int nn = ty + i * 8;
            int gn = n0 + nn;
            int h = gn >> 6, d = gn & 63;
            size_t orow = ((size_t)(b * NH + h) * DEPTH + d) * SEQ + slot;
            Thi[orow] = thi[tx][nn];
        }
    }
}

// ---------------------------------------------------------------------------
// Double-buffered split-fp16 GEMM. BM=BN=128, BK=32, single barrier/iter.
// A_SPLIT: include the Alo·Bhi correction term (3-term); else Ahi-only (2-term).
// ---------------------------------------------------------------------------
#define GSTAGE 40960
#define GEMM_SMEM (2 * GSTAGE)

template<bool A_SPLIT>
__device__ __forceinline__ void gemm_load_stage(uint32_t smbase, int s,
    const __half* AhiG, const __half* AloG,
    const __half* BhiG, const __half* BloG,
    int m0, int n0, int k0, int tid)
{
    uint32_t sb = smbase + s * GSTAGE;
#pragma unroll
    for (int t = 0; t < 2; t++) {
        int id = tid * 2 + t;
        int r = id >> 2, q = id & 3;
        uint32_t off = r * 80 + q * 16;
        const size_t ga = (size_t)(m0 + r) * DM + k0 + q * 8;
        const size_t gb = (size_t)(n0 + r) * DM + k0 + q * 8;
        CP16(sb + off,         AhiG + ga);
        if (A_SPLIT) CP16(sb + 10240 + off, AloG + ga);
        CP16(sb + 20480 + off, BhiG + gb);
        CP16(sb + 30720 + off, BloG + gb);
    }
}

template<bool OUT_F32, bool A_SPLIT>
__device__ __forceinline__ void gemm_core(
    const __half* __restrict__ AhiG, const __half* __restrict__ AloG,
    const __half* __restrict__ BhiG, const __half* __restrict__ BloG,
    const float* __restrict__ bias,
    float* __restrict__ Cf, __half* __restrict__ Chi, __half* __restrict__ Clo)
{
    extern __shared__ char dsm[];
    const uint32_t smbase = smem_u32(dsm);

    const int tid = threadIdx.x;
    const int m0 = blockIdx.y * 128, n0 = blockIdx.x * 128;
    const int lane = tid & 31, wid = tid >> 5;
    const int wm = wid >> 2, wn = wid & 3;
    const int grp = lane >> 2, tig = lane & 3;

    float4 acc[4][4];
#pragma unroll
    for (int i = 0; i < 4; i++)
#pragma unroll
        for (int j = 0; j < 4; j++) acc[i][j] = make_float4(0.f, 0.f, 0.f, 0.f);

    gemm_load_stage<A_SPLIT>(smbase, 0, AhiG, AloG, BhiG, BloG, m0, n0, 0, tid);
    CP_COMMIT;

    for (int kt = 0; kt < 32; kt++) {
        CP_WAIT0;
        __syncthreads();
        if (kt + 1 < 32) {
            gemm_load_stage<A_SPLIT>(smbase, (kt + 1) & 1, AhiG, AloG, BhiG, BloG,
                                     m0, n0, (kt + 1) * 32, tid);
            CP_COMMIT;
        }

        const uint32_t sb = smbase + (kt & 1) * GSTAGE;
        const uint32_t ah_b = sb, al_b = sb + 10240, bh_b = sb + 20480, bl_b = sb + 30720;
#pragma unroll
        for (int ks = 0; ks < 2; ks++) {
            const int kb0 = ks * 16;
            uint32_t ah[4][4], al[4][4];
#pragma unroll
            for (int mt = 0; mt < 4; mt++) {
                lda_x4(ah[mt], ah_b, 80, wm * 64 + mt * 16, kb0, lane);
                if (A_SPLIT) lda_x4(al[mt], al_b, 80, wm * 64 + mt * 16, kb0, lane);
            }
            uint32_t bhf[4][2], blf[4][2];
#pragma unroll
            for (int p = 0; p < 2; p++) {
                ldb_x4(bhf[2 * p], bhf[2 * p + 1], bh_b, 80, wn * 32 + p * 16, kb0, lane);
                ldb_x4(blf[2 * p], blf[2 * p + 1], bl_b, 80, wn * 32 + p * 16, kb0, lane);
            }
#pragma unroll
            for (int mt = 0; mt < 4; mt++)
#pragma unroll
                for (int nt = 0; nt < 4; nt++) {
                    mma16816(acc[mt][nt], ah[mt][0], ah[mt][1], ah[mt][2], ah[mt][3],
                             bhf[nt][0], bhf[nt][1]);
                    mma16816(acc[mt][nt], ah[mt][0], ah[mt][1], ah[mt][2], ah[mt][3],
                             blf[nt][0], blf[nt][1]);
                    if (A_SPLIT)
                        mma16816(acc[mt][nt], al[mt][0], al[mt][1], al[mt][2], al[mt][3],
                                 bhf[nt][0], bhf[nt][1]);
                }
        }
    }

#pragma unroll
    for (int mt = 0; mt < 4; mt++) {
        int r = m0 + wm * 64 + mt * 16 + grp;
#pragma unroll
        for (int nt = 0; nt < 4; nt++) {
            int c = n0 + wn * 32 + nt * 8 + tig * 2;
            float bx = bias[c], by = bias[c + 1];
            float x0 = acc[mt][nt].x + bx, x1 = acc[mt][nt].y + by;
            float x2 = acc[mt][nt].z + bx, x3 = acc[mt][nt].w + by;
            if (OUT_F32) {
                *(float2*)&Cf[(size_t)r * DM + c]       = make_float2(x0, x1);
                *(float2*)&Cf[(size_t)(r + 8) * DM + c] = make_float2(x2, x3);
            } else {
                *(__half2*)&Chi[(size_t)r * DM + c]       = __floats2half2_rn(x0, x1);
                *(__half2*)&Chi[(size_t)(r + 8) * DM + c] = __floats2half2_rn(x2, x3);
                *(__half2*)&Clo[(size_t)r * DM + c]       = __floats2half2_rn(residf(x0), residf(x1));
                *(__half2*)&Clo[(size_t)(r + 8) * DM + c] = __floats2half2_rn(residf(x2), residf(x3));
            }
        }
    }
}

__global__ __launch_bounds__(256) void qkv_gemm_kernel(
    const __half* __restrict__ Xhi, const __half* __restrict__ Xlo,
    const __half* __restrict__ WThi, const __half* __restrict__ WTlo,
    const float* __restrict__ bq, const float* __restrict__ bk,
    const float* __restrict__ bv,
    __half* __restrict__ QKVhi, __half* __restrict__ QKVlo)
{
    const int z = blockIdx.z;
    const size_t asz = (size_t)BS_ROWS * DM, wsz = (size_t)DM * DM;
    const float* bias = (z == 0) ? bq : (z == 1) ? bk : bv;
    gemm_core<false, true>(Xhi + z * asz, Xlo + z * asz,
                           WThi + z * wsz, WTlo + z * wsz,
                           bias, nullptr, QKVhi + z * asz, QKVlo + z * asz);
}

__global__ __launch_bounds__(256) void out_gemm_kernel(
    const __half* __restrict__ Cx,
    const __half* __restrict__ WThi, const __half* __restrict__ WTlo,
    const float* __restrict__ bo, float* __restrict__ out)
{
    const size_t wsz = (size_t)DM * DM;
    gemm_core<true, false>(Cx, nullptr, WThi + 3 * wsz, WTlo + 3 * wsz, bo,
                           out, nullptr, nullptr);
}

// ---------------------------------------------------------------------------
// Logits over COMPACT columns: p = exp(0.125*QK), stored fp16.
// Exp split 75% MUFU / 25% FMA-pipe poly (measured balance point).
// ---------------------------------------------------------------------------
#define LP 72
#define LOGITS_SMEM (4 * 128 * LP * 2 + 128 * 4 * 4)

__global__ __launch_bounds__(256) void logits_kernel(
    const __half* __restrict__ Qhi, const __half* __restrict__ Qlo,
    const __half* __restrict__ Khi, const __half* __restrict__ Klo,
    const int* __restrict__ cidx, const int* __restrict__ cnt,
    __half* __restrict__ Phi, float* __restrict__ partial)
{
    extern __shared__ __half sm[];
    __half (*Qh)[LP] = (__half(*)[LP])sm;
    __half (*Ql)[LP] = (__half(*)[LP])(sm + 128 * LP);
    __half (*Kh)[LP] = (__half(*)[LP])(sm + 2 * 128 * LP);
    __half (*Kl)[LP] = (__half(*)[LP])(sm + 3 * 128 * LP);
    float* sums = (float*)(sm + 4 * 128 * LP);

    const int tid = threadIdx.x;
    const int n0 = blockIdx.x * 128, m0 = blockIdx.y * 128;
    const int bh = blockIdx.z, b = bh >> 4, h = bh & 15;
    const int Mb = cnt[b];

    if (n0 >= Mb) {
        if (tid < 128)
            partial[((size_t)bh * SEQ + m0 + tid) * 16 + blockIdx.x] = 0.f;
        return;
    }

    const size_t hbase = (size_t)b * SEQ * DM + h * 64;
    const int* cb = cidx + b * SEQ;

#pragma unroll
    for (int t = 0; t < 16; t++) {
        int id = tid + 256 * t;
        int arr = id >> 10, rem = id & 1023;
        int r = rem >> 3, q = rem & 7;
        const __half* src = (arr == 0) ? Qhi : (arr == 1) ? Qlo : (arr == 2) ? Khi : Klo;
        __half (*dst)[LP] = (arr == 0) ? Qh : (arr == 1) ? Ql : (arr == 2) ? Kh : Kl;
        int rphys;
        if (arr < 2) rphys = m0 + r;
        else {
            int jr = n0 + r;
            rphys = (jr < Mb) ? cb[jr] : 0;
        }
        uint4 v = *(const uint4*)(src + hbase + (size_t)rphys * DM + q * 8);
        *(uint2*)&dst[r][q * 8]     = make_uint2(v.x, v.y);
        *(uint2*)&dst[r][q * 8 + 4] = make_uint2(v.z, v.w);
    }
    __syncthreads();

    const int lane = tid & 31, wid = tid >> 5;
    const int wm = wid >> 2, wn = wid & 3;
    const int grp = lane >> 2, tig = lane & 3;
    const uint32_t qh_b = smem_u32(Qh), ql_b = smem_u32(Ql);
    const uint32_t kh_b = smem_u32(Kh), kl_b = smem_u32(Kl);

    float4 acc[4][4];
#pragma unroll
    for (int i = 0; i < 4; i++)
#pragma unroll
        for (int j = 0; j < 4; j++) acc[i][j] = make_float4(0.f, 0.f, 0.f, 0.f);

#pragma unroll
    for (int ks = 0; ks < 4; ks++) {
        const int kb0 = ks * 16;
        uint32_t ah[4][4], al[4][4];
#pragma unroll
        for (int mt = 0; mt < 4; mt++) {
            lda_x4(ah[mt], qh_b, 144, wm * 64 + mt * 16, kb0, lane);
            lda_x4(al[mt], ql_b, 144, wm * 64 + mt * 16, kb0, lane);
        }
        uint32_t bhf[4][2], blf[4][2];
#pragma unroll
        for (int p = 0; p < 2; p++) {
            ldb_x4(bhf[2 * p], bhf[2 * p + 1], kh_b, 144, wn * 32 + p * 16, kb0, lane);
            ldb_x4(blf[2 * p], blf[2 * p + 1], kl_b, 144, wn * 32 + p * 16, kb0, lane);
        }
#pragma unroll
        for (int mt = 0; mt < 4; mt++)
#pragma unroll
            for (int nt = 0; nt < 4; nt++) {
                mma16816(acc[mt][nt], ah[mt][0], ah[mt][1], ah[mt][2], ah[mt][3],
                         bhf[nt][0], bhf[nt][1]);
                mma16816(acc[mt][nt], ah[mt][0], ah[mt][1], ah[mt][2], ah[mt][3],
                         blf[nt][0], blf[nt][1]);
                mma16816(acc[mt][nt], al[mt][0], al[mt][1], al[mt][2], al[mt][3],
                         bhf[nt][0], bhf[nt][1]);
            }
    }

    float rs0[4], rs1[4];
#pragma unroll
    for (int mt = 0; mt < 4; mt++) { rs0[mt] = 0.f; rs1[mt] = 0.f; }

#pragma unroll
    for (int mt = 0; mt < 4; mt++) {
        int r = m0 + wm * 64 + mt * 16 + grp;
        __half* oh0 = Phi + ((size_t)bh * SEQ + r) * SEQ;
        __half* oh1 = oh0 + (size_t)8 * SEQ;
#pragma unroll
        for (int nt = 0; nt < 4; nt++) {
            int j = n0 + wn * 32 + nt * 8 + tig * 2;
            bool v0 = (j < Mb), v1 = (j + 1 < Mb);
            float4 a = acc[mt][nt];
            float p0 = v0 ? __expf(a.x * 0.125f)  : 0.f;
            float p1 = v1 ? __expf(a.y * 0.125f)  : 0.f;
            float p2 = v0 ? __expf(a.z * 0.125f)  : 0.f;
            float p3 = v1 ? exp_fma(a.w * 0.125f) : 0.f;
            *(__half2*)(oh0 + j) = __floats2half2_rn(p0, p1);
            *(__half2*)(oh1 + j) = __floats2half2_rn(p2, p3);
            rs0[mt] += p0 + p1;
            rs1[mt] += p2 + p3;
        }
    }
#pragma unroll
    for (int mt = 0; mt < 4; mt++) {
        float s0 = rs0[mt], s1 = rs1[mt];
        s0 += __shfl_xor_sync(0xffffffffu, s0, 1);
        s0 += __shfl_xor_sync(0xffffffffu, s0, 2);
        s1 += __shfl_xor_sync(0xffffffffu, s1, 1);
        s1 += __shfl_xor_sync(0xffffffffu, s1, 2);
        if (tig == 0) {
            int rl = wm * 64 + mt * 16 + grp;
            sums[(size_t)rl * 4 + wn] = s0;
            sums[(size_t)(rl + 8) * 4 + wn] = s1;
        }
    }
    __syncthreads();
    if (tid < 128) {
        float tot = (sums[tid * 4 + 0] + sums[tid * 4 + 1]) +
                    (sums[tid * 4 + 2] + sums[tid * 4 + 3]);
        partial[((size_t)bh * SEQ + m0 + tid) * 16 + blockIdx.x] = tot;
    }
}

__global__ __launch_bounds__(256) void reduce_sums_kernel(
    const float* __restrict__ partial, float* __restrict__ rowsum)
{
    int i = blockIdx.x * 256 + threadIdx.x;
    const float4* p = (const float4*)(partial + (size_t)i * 16);
    float4 a = p[0], b = p[1], c = p[2], d = p[3];
    rowsum[i] = ((a.x + a.y) + (a.z + a.w)) + ((b.x + b.y) + (b.z + b.w)) +
                ((c.x + c.y) + (c.z + c.w)) + ((d.x + d.y) + (d.z + d.w));
}

// ---------------------------------------------------------------------------
// AV over compact K-dim: ctx = (P @ V) / rowsum, all fp16 operands, 1 mma term.
// BM=128, BN=64, BK=64.
// ---------------------------------------------------------------------------
#define AV_SMEM (128 * LP * 2 + 64 * LP * 2 + 128 * 4)

__global__ __launch_bounds__(256) void av_kernel(
    const __half* __restrict__ Phi, const __half* __restrict__ Vt,
    const float* __restrict__ rowsum, const int* __restrict__ cnt,
    __half* __restrict__ Cx)
{
    extern __shared__ char smraw[];
    __half (*Ah)[LP] = (__half(*)[LP])smraw;
    __half (*Vh)[LP] = (__half(*)[LP])(smraw + 128 * LP * 2);
    float* sinv = (float*)(smraw + 128 * LP * 2 + 64 * LP * 2);

    const int tid = threadIdx.x;
    const int m0 = blockIdx.x * 128;
    const int bh = blockIdx.y, b = bh >> 4, h = bh & 15;
    const int Mb = cnt[b];

    if (tid < 128) sinv[tid] = 1.0f / rowsum[(size_t)bh * SEQ + m0 + tid];
    __syncthreads();

    const int lane = tid & 31, wid = tid >> 5;
    const int wm = wid >> 2, wn = wid & 3;
    const int grp = lane >> 2, tig = lane & 3;
    const uint32_t ah_b = smem_u32(Ah);
    const uint32_t vh_b = smem_u32(Vh);

    float4 acc[4][2];
#pragma unroll
    for (int i = 0; i < 4; i++)
#pragma unroll
        for (int j = 0; j < 2; j++) acc[i][j] = make_float4(0.f, 0.f, 0.f, 0.f);

    const size_t prow = (size_t)bh * SEQ + m0;
    const size_t vtb = (size_t)bh * DEPTH * SEQ;

    for (int k0 = 0; k0 < Mb; k0 += 64) {
        // P tile: 128 rows x 64 cols fp16 = 1024 uint4 / 256 thr
#pragma unroll
        for (int t = 0; t < 4; t++) {
            int id = tid + 256 * t;            // 0..1023
            int r = id >> 3, q = id & 7;
            uint4 v = *(const uint4*)(Phi + (prow + r) * SEQ + k0 + q * 8);
            *(uint2*)&Ah[r][q * 8]     = make_uint2(v.x, v.y);
            *(uint2*)&Ah[r][q * 8 + 4] = make_uint2(v.z, v.w);
        }
        // V tile: 64 d-rows x 64 cols fp16 = 512 uint4 / 256 thr
#pragma unroll
        for (int t = 0; t < 2; t++) {
            int id = tid + 256 * t;            // 0..511
            int r = id >> 3, q = id & 7;       // r 0..63
            uint4 v = *(const uint4*)(Vt + vtb + (size_t)r * SEQ + k0 + q * 8);
            *(uint2*)&Vh[r][q * 8]     = make_uint2(v.x, v.y);
            *(uint2*)&Vh[r][q * 8 + 4] = make_uint2(v.z, v.w);
        }
        __syncthreads();

#pragma unroll
        for (int ks = 0; ks < 4; ks++) {
            const int kb0 = ks * 16;
            uint32_t ah[4][4];
#pragma unroll
            for (int mt = 0; mt < 4; mt++)
                lda_x4(ah[mt], ah_b, 144, wm * 64 + mt * 16, kb0, lane);
            uint32_t bhf[2][2];
            ldb_x4(bhf[0], bhf[1], vh_b, 144, wn * 16, kb0, lane);
#pragma unroll
            for (int mt = 0; mt < 4; mt++)
#pragma unroll
                for (int nt = 0; nt < 2; nt++)
                    mma16816(acc[mt][nt], ah[mt][0], ah[mt][1], ah[mt][2], ah[mt][3],
                             bhf[nt][0], bhf[nt][1]);
        }
        __syncthreads();
    }

#pragma unroll
    for (int mt = 0; mt < 4; mt++) {
        int rl = wm * 64 + mt * 16 + grp;
        int r = m0 + rl;
        float iv0 = sinv[rl], iv1 = sinv[rl + 8];
#pragma unroll
        for (int nt = 0; nt < 2; nt++) {
            int d = wn * 16 + nt * 8 + tig * 2;
            size_t o = ((size_t)(b * SEQ + r)) * DM + h * 64 + d;
            *(__half2*)&Cx[o] =
                __floats2half2_rn(acc[mt][nt].x * iv0, acc[mt][nt].y * iv0);
            *(__half2*)&Cx[o + 8 * DM] =
                __floats2half2_rn(acc[mt][nt].z * iv1, acc[mt][nt].w * iv1);
        }
    }
}

// ---------------------------------------------------------------------------
// Expand: write final full-width attn = mask ? 0 : p/rowsum. 1 block/row.
// ---------------------------------------------------------------------------
__global__ __launch_bounds__(256) void expand_kernel(
    const __half* __restrict__ Phi,
    const float* __restrict__ rowsum, const int* __restrict__ fwd,
    float* __restrict__ attn)
{
    const int row = blockIdx.x;
    const int b = row >> 15;               // NH*SEQ = 32768
    const float inv = 1.0f / rowsum[row];
    const __half* ph = Phi + (size_t)row * SEQ;
    const int* fw = fwd + b * SEQ;
    float* o = attn + (size_t)row * SEQ;

    const int j0 = threadIdx.x * 8;
    float vals[8];
#pragma unroll
    for (int t = 0; t < 8; t++) {
        int f = fw[j0 + t];
        vals[t] = (f >= 0) ? __half2float(ph[f]) * inv : 0.f;
    }
    *(float4*)(o + j0)     = make_float4(vals[0], vals[1], vals[2], vals[3]);
    *(float4*)(o + j0 + 4) = make_float4(vals[4], vals[5], vals[6], vals[7]);
}

// ---------------------------------------------------------------------------
// Launcher — forked-stream graph: transpose_v ∥ logits, expand ∥ (av, out_gemm)
// ---------------------------------------------------------------------------
extern "C" void kernel_launch(void* const* d_in, const int* in_sizes, int n_in,
                              void* d_out, int out_size)
{
    const float* v    = (const float*)d_in[0];
    const float* k    = (const float*)d_in[1];
    const float* q    = (const float*)d_in[2];
    const int*   mask = (const int*)  d_in[3];
    const float* Wq = (const float*)d_in[4];
    const float* bq = (const float*)d_in[5];
    const float* Wk = (const float*)d_in[6];
    const float* bk = (const float*)d_in[7];
    const float* Wv = (const float*)d_in[8];
    const float* bv = (const float*)d_in[9];
    const float* Wo = (const float*)d_in[10];
    const float* bo = (const float*)d_in[11];
    float* out = (float*)d_out;

    __half *Xhi, *Xlo, *QKVhi, *QKVlo, *Vt, *Cx, *WThi, *WTlo, *Phi;
    float *attnScratch, *partialp, *rowsump;
    int *fwdp, *cidxp, *cntp;
    cudaGetSymbolAddress((void**)&Xhi, g_Xhi);
    cudaGetSymbolAddress((void**)&Xlo, g_Xlo);
    cudaGetSymbolAddress((void**)&QKVhi, g_QKVhi);
    cudaGetSymbolAddress((void**)&QKVlo, g_QKVlo);
    cudaGetSymbolAddress((void**)&Vt, g_Vt);
    cudaGetSymbolAddress((void**)&Cx, g_Cx);
    cudaGetSymbolAddress((void**)&WThi, g_WThi);
    cudaGetSymbolAddress((void**)&WTlo, g_WTlo);
    cudaGetSymbolAddress((void**)&Phi, g_Phi);
    cudaGetSymbolAddress((void**)&attnScratch, g_attn);
    cudaGetSymbolAddress((void**)&partialp, g_partial);
    cudaGetSymbolAddress((void**)&rowsump, g_rowsum);
    cudaGetSymbolAddress((void**)&fwdp, g_fwd);
    cudaGetSymbolAddress((void**)&cidxp, g_cidx);
    cudaGetSymbolAddress((void**)&cntp, g_cnt);

    cudaFuncSetAttribute(qkv_gemm_kernel,
                         cudaFuncAttributeMaxDynamicSharedMemorySize, GEMM_SMEM);
    cudaFuncSetAttribute(out_gemm_kernel,
                         cudaFuncAttributeMaxDynamicSharedMemorySize, GEMM_SMEM);
    cudaFuncSetAttribute(logits_kernel,
                         cudaFuncAttributeMaxDynamicSharedMemorySize, LOGITS_SMEM);
    cudaFuncSetAttribute(av_kernel,
                         cudaFuncAttributeMaxDynamicSharedMemorySize, AV_SMEM);

    const size_t FINAL_ELEMS = (size_t)BS_ROWS * DM;
    const size_t ATTN_ELEMS  = (size_t)BH * SEQ * SEQ;
    const size_t asz = (size_t)BS_ROWS * DM;
    float* attnp = ((size_t)out_size >= FINAL_ELEMS + ATTN_ELEMS)
                       ? (out + FINAL_ELEMS) : attnScratch;

    // Fork machinery (created per call, never destroyed; no device allocs).
    cudaStream_t s2 = 0;
    bool forked = (cudaStreamCreateWithFlags(&s2, cudaStreamNonBlocking) == cudaSuccess);
    cudaEvent_t eFork = 0, eW = 0, eQkv = 0, eVt = 0, eRs = 0, eJoin = 0;
    if (forked) {
        forked = (cudaEventCreateWithFlags(&eFork, cudaEventDisableTiming) == cudaSuccess) &&
                 (cudaEventCreateWithFlags(&eW,    cudaEventDisableTiming) == cudaSuccess) &&
                 (cudaEventCreateWithFlags(&eQkv,  cudaEventDisableTiming) == cudaSuccess) &&
                 (cudaEventCreateWithFlags(&eVt,   cudaEventDisableTiming) == cudaSuccess) &&
                 (cudaEventCreateWithFlags(&eRs,   cudaEventDisableTiming) == cudaSuccess) &&
                 (cudaEventCreateWithFlags(&eJoin, cudaEventDisableTiming) == cudaSuccess);
    }

    if (forked) {
        cudaEventRecord(eFork, 0);
        cudaStreamWaitEvent(s2, eFork, 0);

        mask_scan_kernel<<<BATCH, 1024, 0, s2>>>(mask, fwdp, cidxp, cntp);
        transpose_split_kernel<<<dim3(32, 32, 4), 256, 0, s2>>>(Wq, Wk, Wv, Wo, WThi, WTlo);
        cudaEventRecord(eW, s2);
        split_inputs_kernel<<<dim3(4096, 3), 256>>>(q, k, v, Xhi, Xlo);

        cudaStreamWaitEvent(0, eW, 0);
        qkv_gemm_kernel<<<dim3(8, 32, 3), 256, GEMM_SMEM>>>(
            Xhi, Xlo, WThi, WTlo, bq, bk, bv, QKVhi, QKVlo);
        cudaEventRecord(eQkv, 0);

        cudaStreamWaitEvent(s2, eQkv, 0);
        transpose_v_kernel<<<dim3(32, 128), 256, 0, s2>>>(
            QKVhi + 2 * asz, fwdp, Vt);
        cudaEventRecord(eVt, s2);

        logits_kernel<<<dim3(16, 16, BH), 256, LOGITS_SMEM>>>(
            QKVhi, QKVlo, QKVhi + asz, QKVlo + asz, cidxp, cntp, Phi, partialp);
        reduce_sums_kernel<<<(BH * SEQ) / 256, 256>>>(partialp, rowsump);
        cudaEventRecord(eRs, 0);

        cudaStreamWaitEvent(s2, eRs, 0);
        expand_kernel<<<BH * SEQ, 256, 0, s2>>>(Phi, rowsump, fwdp, attnp);
        cudaEventRecord(eJoin, s2);

        cudaStreamWaitEvent(0, eVt, 0);
        av_kernel<<<dim3(16, BH), 256, AV_SMEM>>>(
            Phi, Vt, rowsump, cntp, Cx);
        out_gemm_kernel<<<dim3(8, 32), 256, GEMM_SMEM>>>(
            Cx, WThi, WTlo, bo, out);

        cudaStreamWaitEvent(0, eJoin, 0);
    } else {
        mask_scan_kernel<<<BATCH, 1024>>>(mask, fwdp, cidxp, cntp);
        split_inputs_kernel<<<dim3(4096, 3), 256>>>(q, k, v, Xhi, Xlo);
        transpose_split_kernel<<<dim3(32, 32, 4), 256>>>(Wq, Wk, Wv, Wo, WThi, WTlo);
        qkv_gemm_kernel<<<dim3(8, 32, 3), 256, GEMM_SMEM>>>(
            Xhi, Xlo, WThi, WTlo, bq, bk, bv, QKVhi, QKVlo);
        transpose_v_kernel<<<dim3(32, 128), 256>>>(QKVhi + 2 * asz, fwdp, Vt);
        logits_kernel<<<dim3(16, 16, BH), 256, LOGITS_SMEM>>>(
            QKVhi, QKVlo, QKVhi + asz, QKVlo + asz, cidxp, cntp, Phi, partialp);
        reduce_sums_kernel<<<(BH * SEQ) / 256, 256>>>(partialp, rowsump);
        av_kernel<<<dim3(16, BH), 256, AV_SMEM>>>(Phi, Vt, rowsump, cntp, Cx);
        expand_kernel<<<BH * SEQ, 256>>>(Phi, rowsump, fwdp, attnp);
        out_gemm_kernel<<<dim3(8, 32), 256, GEMM_SMEM>>>(
            Cx, WThi, WTlo, bo, out);
    }
}